// round 7
// baseline (speedup 1.0000x reference)
#include <cuda_runtime.h>
#include <cuda_bf16.h>
#include <cstdint>

#define S_LEN 4096
#define D_MODEL 1024
#define N_HEADS 16
#define HEAD_DIM 64
#define HALF_DIM 32

// ---------------- split-bf16 scratch (device globals) ----------------------
__device__ __align__(16) __nv_bfloat16 g_xhi[S_LEN * D_MODEL];
__device__ __align__(16) __nv_bfloat16 g_xlo[S_LEN * D_MODEL];
__device__ __align__(16) __nv_bfloat16 g_whi[4][D_MODEL * D_MODEL];
__device__ __align__(16) __nv_bfloat16 g_wlo[4][D_MODEL * D_MODEL];
__device__ __align__(16) __nv_bfloat16 g_qhi[N_HEADS * S_LEN * HEAD_DIM]; // [h][s][d] RoPE'd, /8
__device__ __align__(16) __nv_bfloat16 g_qlo[N_HEADS * S_LEN * HEAD_DIM];
__device__ __align__(16) __nv_bfloat16 g_khi[N_HEADS * S_LEN * HEAD_DIM]; // [h][s][d] RoPE'd
__device__ __align__(16) __nv_bfloat16 g_klo[N_HEADS * S_LEN * HEAD_DIM];
__device__ __align__(16) __nv_bfloat16 g_vhi[N_HEADS * HEAD_DIM * S_LEN]; // [h][d][s]
__device__ __align__(16) __nv_bfloat16 g_vlo[N_HEADS * HEAD_DIM * S_LEN];
__device__ __align__(16) __nv_bfloat16 g_ahi[S_LEN * D_MODEL];            // attn out
__device__ __align__(16) __nv_bfloat16 g_alo[S_LEN * D_MODEL];

// ---------------- helpers ---------------------------------------------------
__device__ __forceinline__ uint32_t smem_u32(const void* p) {
    uint32_t a;
    asm("{ .reg .u64 t; cvta.to.shared.u64 t, %1; cvt.u32.u64 %0, t; }"
        : "=r"(a) : "l"(p));
    return a;
}

__device__ __forceinline__ void cpa16(uint32_t dst, const void* src) {
    asm volatile("cp.async.cg.shared.global [%0], [%1], 16;"
                 :: "r"(dst), "l"(src));
}
__device__ __forceinline__ void cpa_commit() {
    asm volatile("cp.async.commit_group;");
}
template <int N>
__device__ __forceinline__ void cpa_wait() {
    asm volatile("cp.async.wait_group %0;" :: "n"(N));
}

__device__ __forceinline__ void ldsm_x4(uint32_t* r, uint32_t addr) {
    asm volatile("ldmatrix.sync.aligned.m8n8.x4.shared.b16 {%0,%1,%2,%3}, [%4];"
                 : "=r"(r[0]), "=r"(r[1]), "=r"(r[2]), "=r"(r[3]) : "r"(addr));
}

__device__ __forceinline__ void mma_bf16(float* c, const uint32_t* a,
                                         const uint32_t* b) {
    asm volatile(
        "mma.sync.aligned.m16n8k16.row.col.f32.bf16.bf16.f32 "
        "{%0,%1,%2,%3}, {%4,%5,%6,%7}, {%8,%9}, {%0,%1,%2,%3};"
        : "+f"(c[0]), "+f"(c[1]), "+f"(c[2]), "+f"(c[3])
        : "r"(a[0]), "r"(a[1]), "r"(a[2]), "r"(a[3]), "r"(b[0]), "r"(b[1]));
}

__device__ __forceinline__ uint32_t pk_bf2(__nv_bfloat16 a, __nv_bfloat16 b) {
    __nv_bfloat162 t = __halves2bfloat162(a, b);
    return *reinterpret_cast<uint32_t*>(&t);
}

__device__ __forceinline__ void split2(float a, float b,
                                       uint32_t& hi, uint32_t& lo) {
    __nv_bfloat16 ha = __float2bfloat16_rn(a);
    __nv_bfloat16 hb = __float2bfloat16_rn(b);
    __nv_bfloat16 la = __float2bfloat16_rn(a - __bfloat162float(ha));
    __nv_bfloat16 lb = __float2bfloat16_rn(b - __bfloat162float(hb));
    hi = pk_bf2(ha, hb);
    lo = pk_bf2(la, lb);
}

__device__ __forceinline__ void store_split1(__nv_bfloat16* hi, __nv_bfloat16* lo,
                                             size_t i, float v) {
    __nv_bfloat16 h = __float2bfloat16_rn(v);
    hi[i] = h;
    lo[i] = __float2bfloat16_rn(v - __bfloat162float(h));
}

// A-fragment address (m16k16 tile), B-fragment x4 address (two n8k16 tiles)
__device__ __forceinline__ uint32_t addrA(uint32_t base, int m0, int k0,
                                          int lane, int ld) {
    int r = m0 + (lane & 15);
    int c = k0 + ((lane >> 4) << 3);
    return base + (uint32_t)(r * ld + c) * 2u;
}
__device__ __forceinline__ uint32_t addrB4(uint32_t base, int n0, int k0,
                                           int lane, int ld) {
    int g = lane >> 3;                         // 0..3
    int r = n0 + ((g >> 1) << 3) + (lane & 7); // tiles n0, n0+8
    int c = k0 + ((g & 1) << 3);
    return base + (uint32_t)(r * ld + c) * 2u;
}

// ---------------- pre-pass: f32 -> split-bf16 (fused, one launch) ----------
#define NX (S_LEN * D_MODEL / 4)
#define NW (D_MODEL * D_MODEL / 4)

__global__ void __launch_bounds__(256) conv_all(
    const float* __restrict__ x, const float* __restrict__ wq,
    const float* __restrict__ wk, const float* __restrict__ wv,
    const float* __restrict__ wo)
{
    int idx = blockIdx.x * 256 + threadIdx.x;
    const float* src;
    __nv_bfloat16 *hi, *lo;
    int off;
    if (idx < NX) {
        src = x; hi = g_xhi; lo = g_xlo; off = idx;
    } else {
        int j = idx - NX;
        int t = j >> 18;           // NW = 2^18
        off = j & (NW - 1);
        src = (t == 0) ? wq : (t == 1) ? wk : (t == 2) ? wv : wo;
        hi = g_whi[t]; lo = g_wlo[t];
    }
    float4 f = ((const float4*)src)[off];
    uint32_t h0, h1, l0, l1;
    split2(f.x, f.y, h0, l0);
    split2(f.z, f.w, h1, l1);
    ((uint2*)hi)[off] = make_uint2(h0, h1);
    ((uint2*)lo)[off] = make_uint2(l0, l1);
}

// ------------------- tensor-core GEMM (cp.async, double-buffered) ----------
#define LDT 40
#define GEMM_BUF (128 * LDT * 2)            // 10240 B per tile buffer
#define GEMM_STAGE (4 * GEMM_BUF)           // Ahi|Alo|Bhi|Blo
#define GEMM_SMEM (2 * GEMM_STAGE)          // 81920 B

__device__ __forceinline__ void gemm_issue(
    uint32_t sb, uint32_t soff,
    const __nv_bfloat16* pAh, const __nv_bfloat16* pAl,
    const __nv_bfloat16* pBh, const __nv_bfloat16* pBl, int c)
{
    int go = c * 32;
    cpa16(sb + soff,                       pAh + go);
    cpa16(sb + soff + 16,                  pAh + go + 8);
    cpa16(sb + GEMM_BUF + soff,            pAl + go);
    cpa16(sb + GEMM_BUF + soff + 16,       pAl + go + 8);
    cpa16(sb + 2 * GEMM_BUF + soff,        pBh + go);
    cpa16(sb + 2 * GEMM_BUF + soff + 16,   pBh + go + 8);
    cpa16(sb + 3 * GEMM_BUF + soff,        pBl + go);
    cpa16(sb + 3 * GEMM_BUF + soff + 16,   pBl + go + 8);
    cpa_commit();
}

// GEMM core: fills acc[4][4][4] for warp tile (m0,n0). sb0 = dyn smem base.
__device__ __forceinline__ void gemm_core(
    uint32_t sb0, uint32_t soff,
    const __nv_bfloat16* pAh, const __nv_bfloat16* pAl,
    const __nv_bfloat16* pBh, const __nv_bfloat16* pBl,
    int m0, int n0, int lane, float acc[4][4][4])
{
    gemm_issue(sb0, soff, pAh, pAl, pBh, pBl, 0);
    gemm_issue(sb0 + GEMM_STAGE, soff, pAh, pAl, pBh, pBl, 1);

    for (int c = 0; c < 32; c++) {
        if (c < 31) cpa_wait<1>(); else cpa_wait<0>();
        __syncthreads();
        uint32_t sb = sb0 + (c & 1) * GEMM_STAGE;
        uint32_t aAhi = sb, aAlo = sb + GEMM_BUF;
        uint32_t aBhi = sb + 2 * GEMM_BUF, aBlo = sb + 3 * GEMM_BUF;
#pragma unroll
        for (int ks = 0; ks < 2; ks++) {
            int k0 = ks * 16;
            uint32_t bh[2][4], bl[2][4];
#pragma unroll
            for (int p = 0; p < 2; p++) {
                ldsm_x4(bh[p], addrB4(aBhi, n0 + p * 16, k0, lane, LDT));
                ldsm_x4(bl[p], addrB4(aBlo, n0 + p * 16, k0, lane, LDT));
            }
#pragma unroll
            for (int mt = 0; mt < 4; mt++) {
                uint32_t ah[4], al[4];
                ldsm_x4(ah, addrA(aAhi, m0 + mt * 16, k0, lane, LDT));
                ldsm_x4(al, addrA(aAlo, m0 + mt * 16, k0, lane, LDT));
#pragma unroll
                for (int nt = 0; nt < 4; nt++) {
                    const uint32_t* pbh = &bh[nt >> 1][(nt & 1) * 2];
                    const uint32_t* pbl = &bl[nt >> 1][(nt & 1) * 2];
                    mma_bf16(acc[mt][nt], ah, pbh);
                    mma_bf16(acc[mt][nt], ah, pbl);
                    mma_bf16(acc[mt][nt], al, pbh);
                }
            }
        }
        __syncthreads();
        if (c + 2 < 32)
            gemm_issue(sb0 + (c & 1) * GEMM_STAGE, soff, pAh, pAl, pBh, pBl, c + 2);
    }
}

// QKV fused: blockIdx.z = mode (0=Q,1=K,2=V)
__global__ void __launch_bounds__(256, 1) gemm_qkv(
    const float* __restrict__ bq, const float* __restrict__ bk,
    const float* __restrict__ bv, const float* __restrict__ fcos,
    const float* __restrict__ fsin)
{
    extern __shared__ __align__(16) char dsm[];
    uint32_t sb0 = smem_u32(dsm);

    int mode = blockIdx.z;
    const float* bias = (mode == 0) ? bq : (mode == 1) ? bk : bv;
    const __nv_bfloat16* Bhi = g_whi[mode];
    const __nv_bfloat16* Blo = g_wlo[mode];

    int tid = threadIdx.x, wid = tid >> 5, lane = tid & 31;
    int m0 = (wid >> 2) * 64, n0 = (wid & 3) * 32;
    int bm = blockIdx.y * 128, bn = blockIdx.x * 128;

    int lrow = tid >> 1, lks = (tid & 1) * 16;
    uint32_t soff = (uint32_t)(lrow * LDT + lks) * 2u;
    const __nv_bfloat16* pAh = g_xhi + (size_t)(bm + lrow) * D_MODEL + lks;
    const __nv_bfloat16* pAl = g_xlo + (size_t)(bm + lrow) * D_MODEL + lks;
    const __nv_bfloat16* pBh = Bhi + (size_t)(bn + lrow) * D_MODEL + lks;
    const __nv_bfloat16* pBl = Blo + (size_t)(bn + lrow) * D_MODEL + lks;

    float acc[4][4][4];
#pragma unroll
    for (int i = 0; i < 4; i++)
#pragma unroll
        for (int j = 0; j < 4; j++)
#pragma unroll
            for (int e = 0; e < 4; e++) acc[i][j][e] = 0.f;

    gemm_core(sb0, soff, pAh, pAl, pBh, pBl, m0, n0, lane, acc);

    int rq = lane >> 2, cq = (lane & 3) * 2;
    float scale = (mode == 0) ? 0.125f : 1.f;
#pragma unroll
    for (int mt = 0; mt < 4; mt++) {
#pragma unroll
        for (int nt = 0; nt < 4; nt++) {
            int r0 = bm + m0 + mt * 16 + rq;
            int cg = bn + n0 + nt * 8 + cq;
            float b0 = bias[cg], b1 = bias[cg + 1];
            float v00 = acc[mt][nt][0] + b0, v01 = acc[mt][nt][1] + b1;
            float v10 = acc[mt][nt][2] + b0, v11 = acc[mt][nt][3] + b1;
            int h = cg >> 6, d = cg & 63;
            if (mode == 2) {
                size_t o0 = ((size_t)h * HEAD_DIM + d) * S_LEN;
                store_split1(g_vhi, g_vlo, o0 + r0, v00);
                store_split1(g_vhi, g_vlo, o0 + r0 + 8, v10);
                store_split1(g_vhi, g_vlo, o0 + S_LEN + r0, v01);
                store_split1(g_vhi, g_vlo, o0 + S_LEN + r0 + 8, v11);
            } else {
                float c0 = fcos[(size_t)r0 * HALF_DIM + (d >> 1)];
                float s0 = fsin[(size_t)r0 * HALF_DIM + (d >> 1)];
                float c1 = fcos[(size_t)(r0 + 8) * HALF_DIM + (d >> 1)];
                float s1 = fsin[(size_t)(r0 + 8) * HALF_DIM + (d >> 1)];
                float q00 = (v00 * c0 - v01 * s0) * scale;
                float q01 = (v00 * s0 + v01 * c0) * scale;
                float q10 = (v10 * c1 - v11 * s1) * scale;
                float q11 = (v10 * s1 + v11 * c1) * scale;
                __nv_bfloat16* dh = (mode == 0) ? g_qhi : g_khi;
                __nv_bfloat16* dl = (mode == 0) ? g_qlo : g_klo;
                size_t o0 = ((size_t)h * S_LEN + r0) * HEAD_DIM + d;
                uint32_t hh, ll;
                split2(q00, q01, hh, ll);
                *(uint32_t*)(dh + o0) = hh;
                *(uint32_t*)(dl + o0) = ll;
                split2(q10, q11, hh, ll);
                *(uint32_t*)(dh + o0 + 8 * HEAD_DIM) = hh;
                *(uint32_t*)(dl + o0 + 8 * HEAD_DIM) = ll;
            }
        }
    }
}

// O projection: A = attention output (split), writes f32 result
__global__ void __launch_bounds__(256, 1) gemm_o(
    const float* __restrict__ bias, float* __restrict__ oout)
{
    extern __shared__ __align__(16) char dsm[];
    uint32_t sb0 = smem_u32(dsm);

    int tid = threadIdx.x, wid = tid >> 5, lane = tid & 31;
    int m0 = (wid >> 2) * 64, n0 = (wid & 3) * 32;
    int bm = blockIdx.y * 128, bn = blockIdx.x * 128;

    int lrow = tid >> 1, lks = (tid & 1) * 16;
    uint32_t soff = (uint32_t)(lrow * LDT + lks) * 2u;
    const __nv_bfloat16* pAh = g_ahi + (size_t)(bm + lrow) * D_MODEL + lks;
    const __nv_bfloat16* pAl = g_alo + (size_t)(bm + lrow) * D_MODEL + lks;
    const __nv_bfloat16* pBh = g_whi[3] + (size_t)(bn + lrow) * D_MODEL + lks;
    const __nv_bfloat16* pBl = g_wlo[3] + (size_t)(bn + lrow) * D_MODEL + lks;

    float acc[4][4][4];
#pragma unroll
    for (int i = 0; i < 4; i++)
#pragma unroll
        for (int j = 0; j < 4; j++)
#pragma unroll
            for (int e = 0; e < 4; e++) acc[i][j][e] = 0.f;

    gemm_core(sb0, soff, pAh, pAl, pBh, pBl, m0, n0, lane, acc);

    int rq = lane >> 2, cq = (lane & 3) * 2;
#pragma unroll
    for (int mt = 0; mt < 4; mt++) {
#pragma unroll
        for (int nt = 0; nt < 4; nt++) {
            int r0 = bm + m0 + mt * 16 + rq;
            int cg = bn + n0 + nt * 8 + cq;
            float b0 = bias[cg], b1 = bias[cg + 1];
            *(float2*)(oout + (size_t)r0 * D_MODEL + cg) =
                make_float2(acc[mt][nt][0] + b0, acc[mt][nt][1] + b1);
            *(float2*)(oout + (size_t)(r0 + 8) * D_MODEL + cg) =
                make_float2(acc[mt][nt][2] + b0, acc[mt][nt][3] + b1);
        }
    }
}

// ------------------- flash attention (cp.async double-buffered K/V) --------
#define LDQK 72
#define LDV 136
#define QBUF (128 * LDQK * 2)        // 18432
#define VBUF (64 * LDV * 2)          // 17408
#define KV_STAGE (2 * QBUF + 2 * VBUF)  // 71680
#define OFF_STAGE0 (2 * QBUF)           // after Q hi/lo
#define ATTN_SMEM (2 * QBUF + 2 * KV_STAGE)  // 180224

__device__ __forceinline__ void attn_issue_kv(
    uint32_t sbase, int h, int kb, int tid)
{
    const __nv_bfloat16* khg = g_khi + ((size_t)h * S_LEN + kb * 128) * HEAD_DIM;
    const __nv_bfloat16* klg = g_klo + ((size_t)h * S_LEN + kb * 128) * HEAD_DIM;
    const __nv_bfloat16* vhg = g_vhi + (size_t)h * HEAD_DIM * S_LEN + kb * 128;
    const __nv_bfloat16* vlg = g_vlo + (size_t)h * HEAD_DIM * S_LEN + kb * 128;
    uint32_t aKhi = sbase, aKlo = sbase + QBUF;
    uint32_t aVhi = sbase + 2 * QBUF, aVlo = sbase + 2 * QBUF + VBUF;
#pragma unroll
    for (int it = 0; it < 4; it++) {
        int idx4 = tid + it * 256;
        int row = idx4 >> 3, col = (idx4 & 7) << 3;
        uint32_t koff = (uint32_t)(row * LDQK + col) * 2u;
        cpa16(aKhi + koff, khg + (size_t)row * HEAD_DIM + col);
        cpa16(aKlo + koff, klg + (size_t)row * HEAD_DIM + col);
        int vrow = idx4 >> 4, vcol = (idx4 & 15) << 3;
        uint32_t voff = (uint32_t)(vrow * LDV + vcol) * 2u;
        cpa16(aVhi + voff, vhg + (size_t)vrow * S_LEN + vcol);
        cpa16(aVlo + voff, vlg + (size_t)vrow * S_LEN + vcol);
    }
    cpa_commit();
}

__global__ void __launch_bounds__(256, 1) attn_k()
{
    extern __shared__ __align__(16) char smraw[];
    uint32_t sb = smem_u32(smraw);
    uint32_t aQhi = sb, aQlo = sb + QBUF;

    int qb = gridDim.x - 1 - blockIdx.x;  // longest blocks first
    int h = blockIdx.y;
    int tid = threadIdx.x, wid = tid >> 5, lane = tid & 31;
    int m0 = wid * 16;
    int rq = lane >> 2, cq = (lane & 3) * 2;

    // prologue: start K/V stage 0
    attn_issue_kv(sb + OFF_STAGE0, h, 0, tid);

    // load Q tile (blocking; once)
    {
        const __nv_bfloat16* qhg = g_qhi + ((size_t)h * S_LEN + qb * 128) * HEAD_DIM;
        const __nv_bfloat16* qlg = g_qlo + ((size_t)h * S_LEN + qb * 128) * HEAD_DIM;
#pragma unroll
        for (int it = 0; it < 4; it++) {
            int idx4 = tid + it * 256;
            int row = idx4 >> 3, col = (idx4 & 7) << 3;
            uint4 vh = ((const uint4*)qhg)[idx4];
            uint4 vl = ((const uint4*)qlg)[idx4];
            uint32_t off = (uint32_t)(row * LDQK + col) * 2u;
            asm volatile("st.shared.v4.b32 [%0], {%1,%2,%3,%4};"
                :: "r"(aQhi + off), "r"(vh.x), "r"(vh.y), "r"(vh.z), "r"(vh.w)
                : "memory");
            asm volatile("st.shared.v4.b32 [%0], {%1,%2,%3,%4};"
                :: "r"(aQlo + off), "r"(vl.x), "r"(vl.y), "r"(vl.z), "r"(vl.w)
                : "memory");
        }
    }

    float m[2] = {-1e30f, -1e30f};
    float l[2] = {0.f, 0.f};
    float o[8][4];
#pragma unroll
    for (int dt = 0; dt < 8; dt++)
#pragma unroll
        for (int e = 0; e < 4; e++) o[dt][e] = 0.f;

    for (int kb = 0; kb <= qb; kb++) {
        bool more = (kb + 1 <= qb);
        if (more)
            attn_issue_kv(sb + OFF_STAGE0 + ((kb + 1) & 1) * KV_STAGE, h, kb + 1, tid);
        if (more) cpa_wait<1>(); else cpa_wait<0>();
        __syncthreads();

        uint32_t skv = sb + OFF_STAGE0 + (kb & 1) * KV_STAGE;
        uint32_t aKhi = skv, aKlo = skv + QBUF;
        uint32_t aVhi = skv + 2 * QBUF, aVlo = skv + 2 * QBUF + VBUF;

        // ---- scores
        float sc[16][4];
#pragma unroll
        for (int nt = 0; nt < 16; nt++)
#pragma unroll
            for (int e = 0; e < 4; e++) sc[nt][e] = 0.f;

#pragma unroll
        for (int ks = 0; ks < 4; ks++) {
            int k0 = ks * 16;
            uint32_t ah[4], al[4];
            ldsm_x4(ah, addrA(aQhi, m0, k0, lane, LDQK));
            ldsm_x4(al, addrA(aQlo, m0, k0, lane, LDQK));
#pragma unroll
            for (int p = 0; p < 8; p++) {
                uint32_t bh[4], bl[4];
                ldsm_x4(bh, addrB4(aKhi, p * 16, k0, lane, LDQK));
                ldsm_x4(bl, addrB4(aKlo, p * 16, k0, lane, LDQK));
                mma_bf16(sc[2 * p], ah, bh);
                mma_bf16(sc[2 * p], ah, bl);
                mma_bf16(sc[2 * p], al, bh);
                mma_bf16(sc[2 * p + 1], ah, bh + 2);
                mma_bf16(sc[2 * p + 1], ah, bl + 2);
                mma_bf16(sc[2 * p + 1], al, bh + 2);
            }
        }

        // ---- causal mask on diagonal tile
        if (kb == qb) {
#pragma unroll
            for (int nt = 0; nt < 16; nt++)
#pragma unroll
                for (int e = 0; e < 4; e++) {
                    int qi = m0 + rq + ((e >> 1) << 3);
                    int kj = nt * 8 + cq + (e & 1);
                    if (kj > qi) sc[nt][e] = -1e30f;
                }
        }

        // ---- online softmax
#pragma unroll
        for (int r = 0; r < 2; r++) {
            float mx = -1e30f;
#pragma unroll
            for (int nt = 0; nt < 16; nt++)
                mx = fmaxf(mx, fmaxf(sc[nt][2 * r], sc[nt][2 * r + 1]));
            mx = fmaxf(mx, __shfl_xor_sync(0xffffffffu, mx, 1));
            mx = fmaxf(mx, __shfl_xor_sync(0xffffffffu, mx, 2));
            float mn = fmaxf(m[r], mx);
            float corr = __expf(m[r] - mn);
            m[r] = mn;
            float rs = 0.f;
#pragma unroll
            for (int nt = 0; nt < 16; nt++) {
                float p0 = __expf(sc[nt][2 * r] - mn);
                float p1 = __expf(sc[nt][2 * r + 1] - mn);
                sc[nt][2 * r] = p0;
                sc[nt][2 * r + 1] = p1;
                rs += p0 + p1;
            }
            l[r] = l[r] * corr + rs;
#pragma unroll
            for (int dt = 0; dt < 8; dt++) {
                o[dt][2 * r] *= corr;
                o[dt][2 * r + 1] *= corr;
            }
        }

        // ---- PV (P C-frags repack to A-frags)
#pragma unroll
        for (int kp = 0; kp < 8; kp++) {
            uint32_t ph[4], pl[4];
            split2(sc[2 * kp][0], sc[2 * kp][1], ph[0], pl[0]);
            split2(sc[2 * kp][2], sc[2 * kp][3], ph[1], pl[1]);
            split2(sc[2 * kp + 1][0], sc[2 * kp + 1][1], ph[2], pl[2]);
            split2(sc[2 * kp + 1][2], sc[2 * kp + 1][3], ph[3], pl[3]);
            int k0 = kp * 16;
#pragma unroll
            for (int p = 0; p < 4; p++) {
                uint32_t bh[4], bl[4];
                ldsm_x4(bh, addrB4(aVhi, p * 16, k0, lane, LDV));
                ldsm_x4(bl, addrB4(aVlo, p * 16, k0, lane, LDV));
                mma_bf16(o[2 * p], ph, bh);
                mma_bf16(o[2 * p], ph, bl);
                mma_bf16(o[2 * p], pl, bh);
                mma_bf16(o[2 * p + 1], ph, bh + 2);
                mma_bf16(o[2 * p + 1], ph, bl + 2);
                mma_bf16(o[2 * p + 1], pl, bh + 2);
            }
        }
        __syncthreads();  // stage reusable by issue at next+1 iteration
    }

    // ---- finalize
#pragma unroll
    for (int r = 0; r < 2; r++) {
        l[r] += __shfl_xor_sync(0xffffffffu, l[r], 1);
        l[r] += __shfl_xor_sync(0xffffffffu, l[r], 2);
    }
    float inv0 = 1.f / l[0], inv1 = 1.f / l[1];
    int r0 = qb * 128 + m0 + rq;
    size_t ob = (size_t)r0 * D_MODEL + h * HEAD_DIM + cq;
#pragma unroll
    for (int dt = 0; dt < 8; dt++) {
        uint32_t hh, ll;
        split2(o[dt][0] * inv0, o[dt][1] * inv0, hh, ll);
        *(uint32_t*)(g_ahi + ob + dt * 8) = hh;
        *(uint32_t*)(g_alo + ob + dt * 8) = ll;
        split2(o[dt][2] * inv1, o[dt][3] * inv1, hh, ll);
        *(uint32_t*)(g_ahi + ob + 8 * D_MODEL + dt * 8) = hh;
        *(uint32_t*)(g_alo + ob + 8 * D_MODEL + dt * 8) = ll;
    }
}

extern "C" void kernel_launch(void* const* d_in, const int* in_sizes, int n_in,
                              void* d_out, int out_size)
{
    const float* x    = (const float*)d_in[0];
    const float* fcos = (const float*)d_in[2];
    const float* fsin = (const float*)d_in[3];
    const float* wq  = (const float*)d_in[5];
    const float* wqb = (const float*)d_in[6];
    const float* wk  = (const float*)d_in[7];
    const float* wkb = (const float*)d_in[8];
    const float* wv  = (const float*)d_in[9];
    const float* wvb = (const float*)d_in[10];
    const float* wo  = (const float*)d_in[11];
    const float* wob = (const float*)d_in[12];
    float* out = (float*)d_out;

    static bool attr_set = false;
    if (!attr_set) {
        cudaFuncSetAttribute(attn_k,
                             cudaFuncAttributeMaxDynamicSharedMemorySize,
                             ATTN_SMEM);
        cudaFuncSetAttribute(gemm_qkv,
                             cudaFuncAttributeMaxDynamicSharedMemorySize,
                             GEMM_SMEM);
        cudaFuncSetAttribute(gemm_o,
                             cudaFuncAttributeMaxDynamicSharedMemorySize,
                             GEMM_SMEM);
        attr_set = true;
    }

    conv_all<<<(NX + 4 * NW) / 256, 256>>>(x, wq, wk, wv, wo);
    gemm_qkv<<<dim3(D_MODEL / 128, S_LEN / 128, 3), 256, GEMM_SMEM>>>(
        wqb, wkb, wvb, fcos, fsin);
    attn_k<<<dim3(S_LEN / 128, N_HEADS), 256, ATTN_SMEM>>>();
    gemm_o<<<dim3(D_MODEL / 128, S_LEN / 128), 256, GEMM_SMEM>>>(wob, out);
}

// round 8
// speedup vs baseline: 1.0029x; 1.0029x over previous
#include <cuda_runtime.h>
#include <cuda_bf16.h>
#include <cstdint>

#define S_LEN 4096
#define D_MODEL 1024
#define N_HEADS 16
#define HEAD_DIM 64
#define HALF_DIM 32

// ---------------- split-bf16 scratch (device globals) ----------------------
__device__ __align__(16) __nv_bfloat16 g_xhi[S_LEN * D_MODEL];
__device__ __align__(16) __nv_bfloat16 g_xlo[S_LEN * D_MODEL];
__device__ __align__(16) __nv_bfloat16 g_whi[4][D_MODEL * D_MODEL];
__device__ __align__(16) __nv_bfloat16 g_wlo[4][D_MODEL * D_MODEL];
__device__ __align__(16) __nv_bfloat16 g_qhi[N_HEADS * S_LEN * HEAD_DIM]; // [h][s][d] RoPE'd, /8
__device__ __align__(16) __nv_bfloat16 g_qlo[N_HEADS * S_LEN * HEAD_DIM];
__device__ __align__(16) __nv_bfloat16 g_khi[N_HEADS * S_LEN * HEAD_DIM]; // [h][s][d] RoPE'd
__device__ __align__(16) __nv_bfloat16 g_klo[N_HEADS * S_LEN * HEAD_DIM];
__device__ __align__(16) __nv_bfloat16 g_vhi[N_HEADS * HEAD_DIM * S_LEN]; // [h][d][s]
__device__ __align__(16) __nv_bfloat16 g_vlo[N_HEADS * HEAD_DIM * S_LEN];
__device__ __align__(16) __nv_bfloat16 g_ahi[S_LEN * D_MODEL];            // attn out
__device__ __align__(16) __nv_bfloat16 g_alo[S_LEN * D_MODEL];

// ---------------- helpers ---------------------------------------------------
__device__ __forceinline__ uint32_t smem_u32(const void* p) {
    uint32_t a;
    asm("{ .reg .u64 t; cvta.to.shared.u64 t, %1; cvt.u32.u64 %0, t; }"
        : "=r"(a) : "l"(p));
    return a;
}

__device__ __forceinline__ void cpa16(uint32_t dst, const void* src) {
    asm volatile("cp.async.cg.shared.global [%0], [%1], 16;"
                 :: "r"(dst), "l"(src));
}
__device__ __forceinline__ void cpa_commit() {
    asm volatile("cp.async.commit_group;");
}
template <int N>
__device__ __forceinline__ void cpa_wait() {
    asm volatile("cp.async.wait_group %0;" :: "n"(N));
}

__device__ __forceinline__ void ldsm_x4(uint32_t* r, uint32_t addr) {
    asm volatile("ldmatrix.sync.aligned.m8n8.x4.shared.b16 {%0,%1,%2,%3}, [%4];"
                 : "=r"(r[0]), "=r"(r[1]), "=r"(r[2]), "=r"(r[3]) : "r"(addr));
}

__device__ __forceinline__ void mma_bf16(float* c, const uint32_t* a,
                                         const uint32_t* b) {
    asm volatile(
        "mma.sync.aligned.m16n8k16.row.col.f32.bf16.bf16.f32 "
        "{%0,%1,%2,%3}, {%4,%5,%6,%7}, {%8,%9}, {%0,%1,%2,%3};"
        : "+f"(c[0]), "+f"(c[1]), "+f"(c[2]), "+f"(c[3])
        : "r"(a[0]), "r"(a[1]), "r"(a[2]), "r"(a[3]), "r"(b[0]), "r"(b[1]));
}

__device__ __forceinline__ uint32_t pk_bf2(__nv_bfloat16 a, __nv_bfloat16 b) {
    __nv_bfloat162 t = __halves2bfloat162(a, b);
    return *reinterpret_cast<uint32_t*>(&t);
}

__device__ __forceinline__ void split2(float a, float b,
                                       uint32_t& hi, uint32_t& lo) {
    __nv_bfloat16 ha = __float2bfloat16_rn(a);
    __nv_bfloat16 hb = __float2bfloat16_rn(b);
    __nv_bfloat16 la = __float2bfloat16_rn(a - __bfloat162float(ha));
    __nv_bfloat16 lb = __float2bfloat16_rn(b - __bfloat162float(hb));
    hi = pk_bf2(ha, hb);
    lo = pk_bf2(la, lb);
}

__device__ __forceinline__ void store_split1(__nv_bfloat16* hi, __nv_bfloat16* lo,
                                             size_t i, float v) {
    __nv_bfloat16 h = __float2bfloat16_rn(v);
    hi[i] = h;
    lo[i] = __float2bfloat16_rn(v - __bfloat162float(h));
}

__device__ __forceinline__ uint32_t addrA(uint32_t base, int m0, int k0,
                                          int lane, int ld) {
    int r = m0 + (lane & 15);
    int c = k0 + ((lane >> 4) << 3);
    return base + (uint32_t)(r * ld + c) * 2u;
}
__device__ __forceinline__ uint32_t addrB4(uint32_t base, int n0, int k0,
                                           int lane, int ld) {
    int g = lane >> 3;                         // 0..3
    int r = n0 + ((g >> 1) << 3) + (lane & 7); // tiles n0, n0+8
    int c = k0 + ((g & 1) << 3);
    return base + (uint32_t)(r * ld + c) * 2u;
}

// ---------------- pre-pass: f32 -> split-bf16 (fused, one launch) ----------
#define NX (S_LEN * D_MODEL / 4)
#define NW (D_MODEL * D_MODEL / 4)

__global__ void __launch_bounds__(256) conv_all(
    const float* __restrict__ x, const float* __restrict__ wq,
    const float* __restrict__ wk, const float* __restrict__ wv,
    const float* __restrict__ wo)
{
    int idx = blockIdx.x * 256 + threadIdx.x;
    const float* src;
    __nv_bfloat16 *hi, *lo;
    int off;
    if (idx < NX) {
        src = x; hi = g_xhi; lo = g_xlo; off = idx;
    } else {
        int j = idx - NX;
        int t = j >> 18;           // NW = 2^18
        off = j & (NW - 1);
        src = (t == 0) ? wq : (t == 1) ? wk : (t == 2) ? wv : wo;
        hi = g_whi[t]; lo = g_wlo[t];
    }
    float4 f = ((const float4*)src)[off];
    uint32_t h0, h1, l0, l1;
    split2(f.x, f.y, h0, l0);
    split2(f.z, f.w, h1, l1);
    ((uint2*)hi)[off] = make_uint2(h0, h1);
    ((uint2*)lo)[off] = make_uint2(l0, l1);
}

// ------------------- tensor-core GEMM (cp.async, double-buffered) ----------
#define LDT 40
#define GEMM_BUF (128 * LDT * 2)
#define GEMM_STAGE (4 * GEMM_BUF)
#define GEMM_SMEM (2 * GEMM_STAGE)

__device__ __forceinline__ void gemm_issue(
    uint32_t sb, uint32_t soff,
    const __nv_bfloat16* pAh, const __nv_bfloat16* pAl,
    const __nv_bfloat16* pBh, const __nv_bfloat16* pBl, int c)
{
    int go = c * 32;
    cpa16(sb + soff,                       pAh + go);
    cpa16(sb + soff + 16,                  pAh + go + 8);
    cpa16(sb + GEMM_BUF + soff,            pAl + go);
    cpa16(sb + GEMM_BUF + soff + 16,       pAl + go + 8);
    cpa16(sb + 2 * GEMM_BUF + soff,        pBh + go);
    cpa16(sb + 2 * GEMM_BUF + soff + 16,   pBh + go + 8);
    cpa16(sb + 3 * GEMM_BUF + soff,        pBl + go);
    cpa16(sb + 3 * GEMM_BUF + soff + 16,   pBl + go + 8);
    cpa_commit();
}

// GEMM core, term-major MMA order for accumulator ILP.
__device__ __forceinline__ void gemm_core(
    uint32_t sb0, uint32_t soff,
    const __nv_bfloat16* pAh, const __nv_bfloat16* pAl,
    const __nv_bfloat16* pBh, const __nv_bfloat16* pBl,
    int m0, int n0, int lane, float acc[4][4][4])
{
    gemm_issue(sb0, soff, pAh, pAl, pBh, pBl, 0);
    gemm_issue(sb0 + GEMM_STAGE, soff, pAh, pAl, pBh, pBl, 1);

    for (int c = 0; c < 32; c++) {
        if (c < 31) cpa_wait<1>(); else cpa_wait<0>();
        __syncthreads();
        uint32_t sb = sb0 + (c & 1) * GEMM_STAGE;
        uint32_t aAhi = sb, aAlo = sb + GEMM_BUF;
        uint32_t aBhi = sb + 2 * GEMM_BUF, aBlo = sb + 3 * GEMM_BUF;
#pragma unroll
        for (int ks = 0; ks < 2; ks++) {
            int k0 = ks * 16;
            uint32_t ah[4][4], al[4][4];
#pragma unroll
            for (int mt = 0; mt < 4; mt++) {
                ldsm_x4(ah[mt], addrA(aAhi, m0 + mt * 16, k0, lane, LDT));
                ldsm_x4(al[mt], addrA(aAlo, m0 + mt * 16, k0, lane, LDT));
            }
            uint32_t bh[2][4], bl[2][4];
#pragma unroll
            for (int p = 0; p < 2; p++) {
                ldsm_x4(bh[p], addrB4(aBhi, n0 + p * 16, k0, lane, LDT));
                ldsm_x4(bl[p], addrB4(aBlo, n0 + p * 16, k0, lane, LDT));
            }
            // term-major: 16 independent MMAs between same-acc reuses
#pragma unroll
            for (int mt = 0; mt < 4; mt++)
#pragma unroll
                for (int nt = 0; nt < 4; nt++)
                    mma_bf16(acc[mt][nt], ah[mt], &bh[nt >> 1][(nt & 1) * 2]);
#pragma unroll
            for (int mt = 0; mt < 4; mt++)
#pragma unroll
                for (int nt = 0; nt < 4; nt++)
                    mma_bf16(acc[mt][nt], ah[mt], &bl[nt >> 1][(nt & 1) * 2]);
#pragma unroll
            for (int mt = 0; mt < 4; mt++)
#pragma unroll
                for (int nt = 0; nt < 4; nt++)
                    mma_bf16(acc[mt][nt], al[mt], &bh[nt >> 1][(nt & 1) * 2]);
        }
        __syncthreads();
        if (c + 2 < 32)
            gemm_issue(sb0 + (c & 1) * GEMM_STAGE, soff, pAh, pAl, pBh, pBl, c + 2);
    }
}

// QKV fused: blockIdx.z = mode (0=Q,1=K,2=V)
__global__ void __launch_bounds__(256, 1) gemm_qkv(
    const float* __restrict__ bq, const float* __restrict__ bk,
    const float* __restrict__ bv, const float* __restrict__ fcos,
    const float* __restrict__ fsin)
{
    extern __shared__ __align__(16) char dsm[];
    uint32_t sb0 = smem_u32(dsm);

    int mode = blockIdx.z;
    const float* bias = (mode == 0) ? bq : (mode == 1) ? bk : bv;
    const __nv_bfloat16* Bhi = g_whi[mode];
    const __nv_bfloat16* Blo = g_wlo[mode];

    int tid = threadIdx.x, wid = tid >> 5, lane = tid & 31;
    int m0 = (wid >> 2) * 64, n0 = (wid & 3) * 32;
    int bm = blockIdx.y * 128, bn = blockIdx.x * 128;

    int lrow = tid >> 1, lks = (tid & 1) * 16;
    uint32_t soff = (uint32_t)(lrow * LDT + lks) * 2u;
    const __nv_bfloat16* pAh = g_xhi + (size_t)(bm + lrow) * D_MODEL + lks;
    const __nv_bfloat16* pAl = g_xlo + (size_t)(bm + lrow) * D_MODEL + lks;
    const __nv_bfloat16* pBh = Bhi + (size_t)(bn + lrow) * D_MODEL + lks;
    const __nv_bfloat16* pBl = Blo + (size_t)(bn + lrow) * D_MODEL + lks;

    float acc[4][4][4];
#pragma unroll
    for (int i = 0; i < 4; i++)
#pragma unroll
        for (int j = 0; j < 4; j++)
#pragma unroll
            for (int e = 0; e < 4; e++) acc[i][j][e] = 0.f;

    gemm_core(sb0, soff, pAh, pAl, pBh, pBl, m0, n0, lane, acc);

    int rq = lane >> 2, cq = (lane & 3) * 2;
    float scale = (mode == 0) ? 0.125f : 1.f;
#pragma unroll
    for (int mt = 0; mt < 4; mt++) {
#pragma unroll
        for (int nt = 0; nt < 4; nt++) {
            int r0 = bm + m0 + mt * 16 + rq;
            int cg = bn + n0 + nt * 8 + cq;
            float b0 = bias[cg], b1 = bias[cg + 1];
            float v00 = acc[mt][nt][0] + b0, v01 = acc[mt][nt][1] + b1;
            float v10 = acc[mt][nt][2] + b0, v11 = acc[mt][nt][3] + b1;
            int h = cg >> 6, d = cg & 63;
            if (mode == 2) {
                size_t o0 = ((size_t)h * HEAD_DIM + d) * S_LEN;
                store_split1(g_vhi, g_vlo, o0 + r0, v00);
                store_split1(g_vhi, g_vlo, o0 + r0 + 8, v10);
                store_split1(g_vhi, g_vlo, o0 + S_LEN + r0, v01);
                store_split1(g_vhi, g_vlo, o0 + S_LEN + r0 + 8, v11);
            } else {
                float c0 = fcos[(size_t)r0 * HALF_DIM + (d >> 1)];
                float s0 = fsin[(size_t)r0 * HALF_DIM + (d >> 1)];
                float c1 = fcos[(size_t)(r0 + 8) * HALF_DIM + (d >> 1)];
                float s1 = fsin[(size_t)(r0 + 8) * HALF_DIM + (d >> 1)];
                float q00 = (v00 * c0 - v01 * s0) * scale;
                float q01 = (v00 * s0 + v01 * c0) * scale;
                float q10 = (v10 * c1 - v11 * s1) * scale;
                float q11 = (v10 * s1 + v11 * c1) * scale;
                __nv_bfloat16* dh = (mode == 0) ? g_qhi : g_khi;
                __nv_bfloat16* dl = (mode == 0) ? g_qlo : g_klo;
                size_t o0 = ((size_t)h * S_LEN + r0) * HEAD_DIM + d;
                uint32_t hh, ll;
                split2(q00, q01, hh, ll);
                *(uint32_t*)(dh + o0) = hh;
                *(uint32_t*)(dl + o0) = ll;
                split2(q10, q11, hh, ll);
                *(uint32_t*)(dh + o0 + 8 * HEAD_DIM) = hh;
                *(uint32_t*)(dl + o0 + 8 * HEAD_DIM) = ll;
            }
        }
    }
}

__global__ void __launch_bounds__(256, 1) gemm_o(
    const float* __restrict__ bias, float* __restrict__ oout)
{
    extern __shared__ __align__(16) char dsm[];
    uint32_t sb0 = smem_u32(dsm);

    int tid = threadIdx.x, wid = tid >> 5, lane = tid & 31;
    int m0 = (wid >> 2) * 64, n0 = (wid & 3) * 32;
    int bm = blockIdx.y * 128, bn = blockIdx.x * 128;

    int lrow = tid >> 1, lks = (tid & 1) * 16;
    uint32_t soff = (uint32_t)(lrow * LDT + lks) * 2u;
    const __nv_bfloat16* pAh = g_ahi + (size_t)(bm + lrow) * D_MODEL + lks;
    const __nv_bfloat16* pAl = g_alo + (size_t)(bm + lrow) * D_MODEL + lks;
    const __nv_bfloat16* pBh = g_whi[3] + (size_t)(bn + lrow) * D_MODEL + lks;
    const __nv_bfloat16* pBl = g_wlo[3] + (size_t)(bn + lrow) * D_MODEL + lks;

    float acc[4][4][4];
#pragma unroll
    for (int i = 0; i < 4; i++)
#pragma unroll
        for (int j = 0; j < 4; j++)
#pragma unroll
            for (int e = 0; e < 4; e++) acc[i][j][e] = 0.f;

    gemm_core(sb0, soff, pAh, pAl, pBh, pBl, m0, n0, lane, acc);

    int rq = lane >> 2, cq = (lane & 3) * 2;
#pragma unroll
    for (int mt = 0; mt < 4; mt++) {
#pragma unroll
        for (int nt = 0; nt < 4; nt++) {
            int r0 = bm + m0 + mt * 16 + rq;
            int cg = bn + n0 + nt * 8 + cq;
            float b0 = bias[cg], b1 = bias[cg + 1];
            *(float2*)(oout + (size_t)r0 * D_MODEL + cg) =
                make_float2(acc[mt][nt][0] + b0, acc[mt][nt][1] + b1);
            *(float2*)(oout + (size_t)(r0 + 8) * D_MODEL + cg) =
                make_float2(acc[mt][nt][2] + b0, acc[mt][nt][3] + b1);
        }
    }
}

// ------------------- flash attention (cp.async, term-major MMA) ------------
#define LDQK 72
#define LDV 136
#define QBUF (128 * LDQK * 2)
#define VBUF (64 * LDV * 2)
#define KV_STAGE (2 * QBUF + 2 * VBUF)
#define OFF_STAGE0 (2 * QBUF)
#define ATTN_SMEM (2 * QBUF + 2 * KV_STAGE)

__device__ __forceinline__ void attn_issue_kv(
    uint32_t sbase, int h, int kb, int tid)
{
    const __nv_bfloat16* khg = g_khi + ((size_t)h * S_LEN + kb * 128) * HEAD_DIM;
    const __nv_bfloat16* klg = g_klo + ((size_t)h * S_LEN + kb * 128) * HEAD_DIM;
    const __nv_bfloat16* vhg = g_vhi + (size_t)h * HEAD_DIM * S_LEN + kb * 128;
    const __nv_bfloat16* vlg = g_vlo + (size_t)h * HEAD_DIM * S_LEN + kb * 128;
    uint32_t aKhi = sbase, aKlo = sbase + QBUF;
    uint32_t aVhi = sbase + 2 * QBUF, aVlo = sbase + 2 * QBUF + VBUF;
#pragma unroll
    for (int it = 0; it < 4; it++) {
        int idx4 = tid + it * 256;
        int row = idx4 >> 3, col = (idx4 & 7) << 3;
        uint32_t koff = (uint32_t)(row * LDQK + col) * 2u;
        cpa16(aKhi + koff, khg + (size_t)row * HEAD_DIM + col);
        cpa16(aKlo + koff, klg + (size_t)row * HEAD_DIM + col);
        int vrow = idx4 >> 4, vcol = (idx4 & 15) << 3;
        uint32_t voff = (uint32_t)(vrow * LDV + vcol) * 2u;
        cpa16(aVhi + voff, vhg + (size_t)vrow * S_LEN + vcol);
        cpa16(aVlo + voff, vlg + (size_t)vrow * S_LEN + vcol);
    }
    cpa_commit();
}

__global__ void __launch_bounds__(256, 1) attn_k()
{
    extern __shared__ __align__(16) char smraw[];
    uint32_t sb = smem_u32(smraw);
    uint32_t aQhi = sb, aQlo = sb + QBUF;

    int qb = gridDim.x - 1 - blockIdx.x;
    int h = blockIdx.y;
    int tid = threadIdx.x, wid = tid >> 5, lane = tid & 31;
    int m0 = wid * 16;
    int rq = lane >> 2, cq = (lane & 3) * 2;

    attn_issue_kv(sb + OFF_STAGE0, h, 0, tid);

    {
        const __nv_bfloat16* qhg = g_qhi + ((size_t)h * S_LEN + qb * 128) * HEAD_DIM;
        const __nv_bfloat16* qlg = g_qlo + ((size_t)h * S_LEN + qb * 128) * HEAD_DIM;
#pragma unroll
        for (int it = 0; it < 4; it++) {
            int idx4 = tid + it * 256;
            int row = idx4 >> 3, col = (idx4 & 7) << 3;
            uint4 vh = ((const uint4*)qhg)[idx4];
            uint4 vl = ((const uint4*)qlg)[idx4];
            uint32_t off = (uint32_t)(row * LDQK + col) * 2u;
            asm volatile("st.shared.v4.b32 [%0], {%1,%2,%3,%4};"
                :: "r"(aQhi + off), "r"(vh.x), "r"(vh.y), "r"(vh.z), "r"(vh.w)
                : "memory");
            asm volatile("st.shared.v4.b32 [%0], {%1,%2,%3,%4};"
                :: "r"(aQlo + off), "r"(vl.x), "r"(vl.y), "r"(vl.z), "r"(vl.w)
                : "memory");
        }
    }

    float m[2] = {-1e30f, -1e30f};
    float l[2] = {0.f, 0.f};
    float o[8][4];
#pragma unroll
    for (int dt = 0; dt < 8; dt++)
#pragma unroll
        for (int e = 0; e < 4; e++) o[dt][e] = 0.f;

    for (int kb = 0; kb <= qb; kb++) {
        bool more = (kb + 1 <= qb);
        if (more)
            attn_issue_kv(sb + OFF_STAGE0 + ((kb + 1) & 1) * KV_STAGE, h, kb + 1, tid);
        if (more) cpa_wait<1>(); else cpa_wait<0>();
        __syncthreads();

        uint32_t skv = sb + OFF_STAGE0 + (kb & 1) * KV_STAGE;
        uint32_t aKhi = skv, aKlo = skv + QBUF;
        uint32_t aVhi = skv + 2 * QBUF, aVlo = skv + 2 * QBUF + VBUF;

        // ---- scores: term-major across 4 chains per pair of K-tile groups
        float sc[16][4];
#pragma unroll
        for (int nt = 0; nt < 16; nt++)
#pragma unroll
            for (int e = 0; e < 4; e++) sc[nt][e] = 0.f;

#pragma unroll
        for (int ks = 0; ks < 4; ks++) {
            int k0 = ks * 16;
            uint32_t ah[4], al[4];
            ldsm_x4(ah, addrA(aQhi, m0, k0, lane, LDQK));
            ldsm_x4(al, addrA(aQlo, m0, k0, lane, LDQK));
#pragma unroll
            for (int pp = 0; pp < 4; pp++) {
                int p0 = 2 * pp, p1 = 2 * pp + 1;
                uint32_t bh0[4], bl0[4], bh1[4], bl1[4];
                ldsm_x4(bh0, addrB4(aKhi, p0 * 16, k0, lane, LDQK));
                ldsm_x4(bl0, addrB4(aKlo, p0 * 16, k0, lane, LDQK));
                ldsm_x4(bh1, addrB4(aKhi, p1 * 16, k0, lane, LDQK));
                ldsm_x4(bl1, addrB4(aKlo, p1 * 16, k0, lane, LDQK));
                float* s0 = sc[4 * pp + 0];
                float* s1 = sc[4 * pp + 1];
                float* s2 = sc[4 * pp + 2];
                float* s3 = sc[4 * pp + 3];
                mma_bf16(s0, ah, bh0); mma_bf16(s1, ah, bh0 + 2);
                mma_bf16(s2, ah, bh1); mma_bf16(s3, ah, bh1 + 2);
                mma_bf16(s0, ah, bl0); mma_bf16(s1, ah, bl0 + 2);
                mma_bf16(s2, ah, bl1); mma_bf16(s3, ah, bl1 + 2);
                mma_bf16(s0, al, bh0); mma_bf16(s1, al, bh0 + 2);
                mma_bf16(s2, al, bh1); mma_bf16(s3, al, bh1 + 2);
            }
        }

        // ---- causal mask on diagonal tile
        if (kb == qb) {
#pragma unroll
            for (int nt = 0; nt < 16; nt++)
#pragma unroll
                for (int e = 0; e < 4; e++) {
                    int qi = m0 + rq + ((e >> 1) << 3);
                    int kj = nt * 8 + cq + (e & 1);
                    if (kj > qi) sc[nt][e] = -1e30f;
                }
        }

        // ---- online softmax
#pragma unroll
        for (int r = 0; r < 2; r++) {
            float mx = -1e30f;
#pragma unroll
            for (int nt = 0; nt < 16; nt++)
                mx = fmaxf(mx, fmaxf(sc[nt][2 * r], sc[nt][2 * r + 1]));
            mx = fmaxf(mx, __shfl_xor_sync(0xffffffffu, mx, 1));
            mx = fmaxf(mx, __shfl_xor_sync(0xffffffffu, mx, 2));
            float mn = fmaxf(m[r], mx);
            float corr = __expf(m[r] - mn);
            m[r] = mn;
            float rs = 0.f;
#pragma unroll
            for (int nt = 0; nt < 16; nt++) {
                float p0 = __expf(sc[nt][2 * r] - mn);
                float p1 = __expf(sc[nt][2 * r + 1] - mn);
                sc[nt][2 * r] = p0;
                sc[nt][2 * r + 1] = p1;
                rs += p0 + p1;
            }
            l[r] = l[r] * corr + rs;
#pragma unroll
            for (int dt = 0; dt < 8; dt++) {
                o[dt][2 * r] *= corr;
                o[dt][2 * r + 1] *= corr;
            }
        }

        // ---- PV: term-major across 4 output chains per V-tile pair
#pragma unroll
        for (int kp = 0; kp < 8; kp++) {
            uint32_t ph[4], pl[4];
            split2(sc[2 * kp][0], sc[2 * kp][1], ph[0], pl[0]);
            split2(sc[2 * kp][2], sc[2 * kp][3], ph[1], pl[1]);
            split2(sc[2 * kp + 1][0], sc[2 * kp + 1][1], ph[2], pl[2]);
            split2(sc[2 * kp + 1][2], sc[2 * kp + 1][3], ph[3], pl[3]);
            int k0 = kp * 16;
#pragma unroll
            for (int pp = 0; pp < 2; pp++) {
                int p0 = 2 * pp, p1 = 2 * pp + 1;
                uint32_t bh0[4], bl0[4], bh1[4], bl1[4];
                ldsm_x4(bh0, addrB4(aVhi, p0 * 16, k0, lane, LDV));
                ldsm_x4(bl0, addrB4(aVlo, p0 * 16, k0, lane, LDV));
                ldsm_x4(bh1, addrB4(aVhi, p1 * 16, k0, lane, LDV));
                ldsm_x4(bl1, addrB4(aVlo, p1 * 16, k0, lane, LDV));
                float* o0 = o[4 * pp + 0];
                float* o1 = o[4 * pp + 1];
                float* o2 = o[4 * pp + 2];
                float* o3 = o[4 * pp + 3];
                mma_bf16(o0, ph, bh0); mma_bf16(o1, ph, bh0 + 2);
                mma_bf16(o2, ph, bh1); mma_bf16(o3, ph, bh1 + 2);
                mma_bf16(o0, ph, bl0); mma_bf16(o1, ph, bl0 + 2);
                mma_bf16(o2, ph, bl1); mma_bf16(o3, ph, bl1 + 2);
                mma_bf16(o0, pl, bh0); mma_bf16(o1, pl, bh0 + 2);
                mma_bf16(o2, pl, bh1); mma_bf16(o3, pl, bh1 + 2);
            }
        }
        __syncthreads();
    }

    // ---- finalize
#pragma unroll
    for (int r = 0; r < 2; r++) {
        l[r] += __shfl_xor_sync(0xffffffffu, l[r], 1);
        l[r] += __shfl_xor_sync(0xffffffffu, l[r], 2);
    }
    float inv0 = 1.f / l[0], inv1 = 1.f / l[1];
    int r0 = qb * 128 + m0 + rq;
    size_t ob = (size_t)r0 * D_MODEL + h * HEAD_DIM + cq;
#pragma unroll
    for (int dt = 0; dt < 8; dt++) {
        uint32_t hh, ll;
        split2(o[dt][0] * inv0, o[dt][1] * inv0, hh, ll);
        *(uint32_t*)(g_ahi + ob + dt * 8) = hh;
        *(uint32_t*)(g_alo + ob + dt * 8) = ll;
        split2(o[dt][2] * inv1, o[dt][3] * inv1, hh, ll);
        *(uint32_t*)(g_ahi + ob + 8 * D_MODEL + dt * 8) = hh;
        *(uint32_t*)(g_alo + ob + 8 * D_MODEL + dt * 8) = ll;
    }
}

extern "C" void kernel_launch(void* const* d_in, const int* in_sizes, int n_in,
                              void* d_out, int out_size)
{
    const float* x    = (const float*)d_in[0];
    const float* fcos = (const float*)d_in[2];
    const float* fsin = (const float*)d_in[3];
    const float* wq  = (const float*)d_in[5];
    const float* wqb = (const float*)d_in[6];
    const float* wk  = (const float*)d_in[7];
    const float* wkb = (const float*)d_in[8];
    const float* wv  = (const float*)d_in[9];
    const float* wvb = (const float*)d_in[10];
    const float* wo  = (const float*)d_in[11];
    const float* wob = (const float*)d_in[12];
    float* out = (float*)d_out;

    static bool attr_set = false;
    if (!attr_set) {
        cudaFuncSetAttribute(attn_k,
                             cudaFuncAttributeMaxDynamicSharedMemorySize,
                             ATTN_SMEM);
        cudaFuncSetAttribute(gemm_qkv,
                             cudaFuncAttributeMaxDynamicSharedMemorySize,
                             GEMM_SMEM);
        cudaFuncSetAttribute(gemm_o,
                             cudaFuncAttributeMaxDynamicSharedMemorySize,
                             GEMM_SMEM);
        attr_set = true;
    }

    conv_all<<<(NX + 4 * NW) / 256, 256>>>(x, wq, wk, wv, wo);
    gemm_qkv<<<dim3(D_MODEL / 128, S_LEN / 128, 3), 256, GEMM_SMEM>>>(
        wqb, wkb, wvb, fcos, fsin);
    attn_k<<<dim3(S_LEN / 128, N_HEADS), 256, ATTN_SMEM>>>();
    gemm_o<<<dim3(D_MODEL / 128, S_LEN / 128), 256, GEMM_SMEM>>>(wob, out);
}

// round 9
// speedup vs baseline: 1.0520x; 1.0489x over previous
#include <cuda_runtime.h>
#include <cuda_bf16.h>
#include <cstdint>

#define S_LEN 4096
#define D_MODEL 1024
#define N_HEADS 16
#define HEAD_DIM 64
#define HALF_DIM 32

// ---------------- split-bf16 scratch (device globals) ----------------------
__device__ __align__(16) __nv_bfloat16 g_xhi[S_LEN * D_MODEL];
__device__ __align__(16) __nv_bfloat16 g_xlo[S_LEN * D_MODEL];
__device__ __align__(16) __nv_bfloat16 g_whi[4][D_MODEL * D_MODEL];
__device__ __align__(16) __nv_bfloat16 g_wlo[4][D_MODEL * D_MODEL];
__device__ __align__(16) __nv_bfloat16 g_qhi[N_HEADS * S_LEN * HEAD_DIM]; // [h][s][d] RoPE'd, /8
__device__ __align__(16) __nv_bfloat16 g_qlo[N_HEADS * S_LEN * HEAD_DIM];
__device__ __align__(16) __nv_bfloat16 g_khi[N_HEADS * S_LEN * HEAD_DIM]; // [h][s][d] RoPE'd
__device__ __align__(16) __nv_bfloat16 g_klo[N_HEADS * S_LEN * HEAD_DIM];
__device__ __align__(16) __nv_bfloat16 g_vhi[N_HEADS * HEAD_DIM * S_LEN]; // [h][d][s]
__device__ __align__(16) __nv_bfloat16 g_vlo[N_HEADS * HEAD_DIM * S_LEN];
__device__ __align__(16) __nv_bfloat16 g_ahi[S_LEN * D_MODEL];            // attn out
__device__ __align__(16) __nv_bfloat16 g_alo[S_LEN * D_MODEL];

// ---------------- helpers ---------------------------------------------------
__device__ __forceinline__ uint32_t smem_u32(const void* p) {
    uint32_t a;
    asm("{ .reg .u64 t; cvta.to.shared.u64 t, %1; cvt.u32.u64 %0, t; }"
        : "=r"(a) : "l"(p));
    return a;
}

__device__ __forceinline__ void cpa16(uint32_t dst, const void* src) {
    asm volatile("cp.async.cg.shared.global [%0], [%1], 16;"
                 :: "r"(dst), "l"(src));
}
__device__ __forceinline__ void cpa_commit() {
    asm volatile("cp.async.commit_group;");
}
template <int N>
__device__ __forceinline__ void cpa_wait() {
    asm volatile("cp.async.wait_group %0;" :: "n"(N));
}

__device__ __forceinline__ void ldsm_x4(uint32_t* r, uint32_t addr) {
    asm volatile("ldmatrix.sync.aligned.m8n8.x4.shared.b16 {%0,%1,%2,%3}, [%4];"
                 : "=r"(r[0]), "=r"(r[1]), "=r"(r[2]), "=r"(r[3]) : "r"(addr));
}

__device__ __forceinline__ void mma_bf16(float* c, const uint32_t* a,
                                         const uint32_t* b) {
    asm volatile(
        "mma.sync.aligned.m16n8k16.row.col.f32.bf16.bf16.f32 "
        "{%0,%1,%2,%3}, {%4,%5,%6,%7}, {%8,%9}, {%0,%1,%2,%3};"
        : "+f"(c[0]), "+f"(c[1]), "+f"(c[2]), "+f"(c[3])
        : "r"(a[0]), "r"(a[1]), "r"(a[2]), "r"(a[3]), "r"(b[0]), "r"(b[1]));
}

__device__ __forceinline__ uint32_t pk_bf2(__nv_bfloat16 a, __nv_bfloat16 b) {
    __nv_bfloat162 t = __halves2bfloat162(a, b);
    return *reinterpret_cast<uint32_t*>(&t);
}

__device__ __forceinline__ void split2(float a, float b,
                                       uint32_t& hi, uint32_t& lo) {
    __nv_bfloat16 ha = __float2bfloat16_rn(a);
    __nv_bfloat16 hb = __float2bfloat16_rn(b);
    __nv_bfloat16 la = __float2bfloat16_rn(a - __bfloat162float(ha));
    __nv_bfloat16 lb = __float2bfloat16_rn(b - __bfloat162float(hb));
    hi = pk_bf2(ha, hb);
    lo = pk_bf2(la, lb);
}

__device__ __forceinline__ void store_split1(__nv_bfloat16* hi, __nv_bfloat16* lo,
                                             size_t i, float v) {
    __nv_bfloat16 h = __float2bfloat16_rn(v);
    hi[i] = h;
    lo[i] = __float2bfloat16_rn(v - __bfloat162float(h));
}

__device__ __forceinline__ uint32_t addrA(uint32_t base, int m0, int k0,
                                          int lane, int ld) {
    int r = m0 + (lane & 15);
    int c = k0 + ((lane >> 4) << 3);
    return base + (uint32_t)(r * ld + c) * 2u;
}
__device__ __forceinline__ uint32_t addrB4(uint32_t base, int n0, int k0,
                                           int lane, int ld) {
    int g = lane >> 3;
    int r = n0 + ((g >> 1) << 3) + (lane & 7);
    int c = k0 + ((g & 1) << 3);
    return base + (uint32_t)(r * ld + c) * 2u;
}

// ---------------- pre-pass: f32 -> split-bf16 (fused, one launch) ----------
#define NX (S_LEN * D_MODEL / 4)
#define NW (D_MODEL * D_MODEL / 4)

__global__ void __launch_bounds__(256) conv_all(
    const float* __restrict__ x, const float* __restrict__ wq,
    const float* __restrict__ wk, const float* __restrict__ wv,
    const float* __restrict__ wo)
{
    int idx = blockIdx.x * 256 + threadIdx.x;
    const float* src;
    __nv_bfloat16 *hi, *lo;
    int off;
    if (idx < NX) {
        src = x; hi = g_xhi; lo = g_xlo; off = idx;
    } else {
        int j = idx - NX;
        int t = j >> 18;
        off = j & (NW - 1);
        src = (t == 0) ? wq : (t == 1) ? wk : (t == 2) ? wv : wo;
        hi = g_whi[t]; lo = g_wlo[t];
    }
    float4 f = ((const float4*)src)[off];
    uint32_t h0, h1, l0, l1;
    split2(f.x, f.y, h0, l0);
    split2(f.z, f.w, h1, l1);
    ((uint2*)hi)[off] = make_uint2(h0, h1);
    ((uint2*)lo)[off] = make_uint2(l0, l1);
}

// ------------------- tensor-core GEMM (cp.async, double-buffered) ----------
#define LDT 40
#define GEMM_BUF (128 * LDT * 2)
#define GEMM_STAGE (4 * GEMM_BUF)
#define GEMM_SMEM (2 * GEMM_STAGE)   // 80 KB -> 2 CTAs/SM

__device__ __forceinline__ void gemm_issue(
    uint32_t sb, uint32_t soff,
    const __nv_bfloat16* pAh, const __nv_bfloat16* pAl,
    const __nv_bfloat16* pBh, const __nv_bfloat16* pBl, int c)
{
    int go = c * 32;
    cpa16(sb + soff,                       pAh + go);
    cpa16(sb + soff + 16,                  pAh + go + 8);
    cpa16(sb + GEMM_BUF + soff,            pAl + go);
    cpa16(sb + GEMM_BUF + soff + 16,       pAl + go + 8);
    cpa16(sb + 2 * GEMM_BUF + soff,        pBh + go);
    cpa16(sb + 2 * GEMM_BUF + soff + 16,   pBh + go + 8);
    cpa16(sb + 3 * GEMM_BUF + soff,        pBl + go);
    cpa16(sb + 3 * GEMM_BUF + soff + 16,   pBl + go + 8);
    cpa_commit();
}

__device__ __forceinline__ void gemm_core(
    uint32_t sb0, uint32_t soff,
    const __nv_bfloat16* pAh, const __nv_bfloat16* pAl,
    const __nv_bfloat16* pBh, const __nv_bfloat16* pBl,
    int m0, int n0, int lane, float acc[4][4][4])
{
    gemm_issue(sb0, soff, pAh, pAl, pBh, pBl, 0);
    gemm_issue(sb0 + GEMM_STAGE, soff, pAh, pAl, pBh, pBl, 1);

    for (int c = 0; c < 32; c++) {
        if (c < 31) cpa_wait<1>(); else cpa_wait<0>();
        __syncthreads();
        uint32_t sb = sb0 + (c & 1) * GEMM_STAGE;
        uint32_t aAhi = sb, aAlo = sb + GEMM_BUF;
        uint32_t aBhi = sb + 2 * GEMM_BUF, aBlo = sb + 3 * GEMM_BUF;
#pragma unroll
        for (int ks = 0; ks < 2; ks++) {
            int k0 = ks * 16;
            uint32_t bh[2][4], bl[2][4];
#pragma unroll
            for (int p = 0; p < 2; p++) {
                ldsm_x4(bh[p], addrB4(aBhi, n0 + p * 16, k0, lane, LDT));
                ldsm_x4(bl[p], addrB4(aBlo, n0 + p * 16, k0, lane, LDT));
            }
#pragma unroll
            for (int mt = 0; mt < 4; mt++) {
                uint32_t ah[4], al[4];
                ldsm_x4(ah, addrA(aAhi, m0 + mt * 16, k0, lane, LDT));
                ldsm_x4(al, addrA(aAlo, m0 + mt * 16, k0, lane, LDT));
#pragma unroll
                for (int nt = 0; nt < 4; nt++) {
                    const uint32_t* pbh = &bh[nt >> 1][(nt & 1) * 2];
                    const uint32_t* pbl = &bl[nt >> 1][(nt & 1) * 2];
                    mma_bf16(acc[mt][nt], ah, pbh);
                    mma_bf16(acc[mt][nt], ah, pbl);
                    mma_bf16(acc[mt][nt], al, pbh);
                }
            }
        }
        __syncthreads();
        if (c + 2 < 32)
            gemm_issue(sb0 + (c & 1) * GEMM_STAGE, soff, pAh, pAl, pBh, pBl, c + 2);
    }
}

// QKV fused: blockIdx.z = mode (0=Q,1=K,2=V)
__global__ void __launch_bounds__(256, 2) gemm_qkv(
    const float* __restrict__ bq, const float* __restrict__ bk,
    const float* __restrict__ bv, const float* __restrict__ fcos,
    const float* __restrict__ fsin)
{
    extern __shared__ __align__(16) char dsm[];
    uint32_t sb0 = smem_u32(dsm);

    int mode = blockIdx.z;
    const float* bias = (mode == 0) ? bq : (mode == 1) ? bk : bv;

    int tid = threadIdx.x, wid = tid >> 5, lane = tid & 31;
    int m0 = (wid >> 2) * 64, n0 = (wid & 3) * 32;
    int bm = blockIdx.y * 128, bn = blockIdx.x * 128;

    int lrow = tid >> 1, lks = (tid & 1) * 16;
    uint32_t soff = (uint32_t)(lrow * LDT + lks) * 2u;
    const __nv_bfloat16* pAh = g_xhi + (size_t)(bm + lrow) * D_MODEL + lks;
    const __nv_bfloat16* pAl = g_xlo + (size_t)(bm + lrow) * D_MODEL + lks;
    const __nv_bfloat16* pBh = g_whi[mode] + (size_t)(bn + lrow) * D_MODEL + lks;
    const __nv_bfloat16* pBl = g_wlo[mode] + (size_t)(bn + lrow) * D_MODEL + lks;

    float acc[4][4][4];
#pragma unroll
    for (int i = 0; i < 4; i++)
#pragma unroll
        for (int j = 0; j < 4; j++)
#pragma unroll
            for (int e = 0; e < 4; e++) acc[i][j][e] = 0.f;

    gemm_core(sb0, soff, pAh, pAl, pBh, pBl, m0, n0, lane, acc);

    int rq = lane >> 2, cq = (lane & 3) * 2;
    float scale = (mode == 0) ? 0.125f : 1.f;
#pragma unroll
    for (int mt = 0; mt < 4; mt++) {
#pragma unroll
        for (int nt = 0; nt < 4; nt++) {
            int r0 = bm + m0 + mt * 16 + rq;
            int cg = bn + n0 + nt * 8 + cq;
            float b0 = bias[cg], b1 = bias[cg + 1];
            float v00 = acc[mt][nt][0] + b0, v01 = acc[mt][nt][1] + b1;
            float v10 = acc[mt][nt][2] + b0, v11 = acc[mt][nt][3] + b1;
            int h = cg >> 6, d = cg & 63;
            if (mode == 2) {
                size_t o0 = ((size_t)h * HEAD_DIM + d) * S_LEN;
                store_split1(g_vhi, g_vlo, o0 + r0, v00);
                store_split1(g_vhi, g_vlo, o0 + r0 + 8, v10);
                store_split1(g_vhi, g_vlo, o0 + S_LEN + r0, v01);
                store_split1(g_vhi, g_vlo, o0 + S_LEN + r0 + 8, v11);
            } else {
                float c0 = fcos[(size_t)r0 * HALF_DIM + (d >> 1)];
                float s0 = fsin[(size_t)r0 * HALF_DIM + (d >> 1)];
                float c1 = fcos[(size_t)(r0 + 8) * HALF_DIM + (d >> 1)];
                float s1 = fsin[(size_t)(r0 + 8) * HALF_DIM + (d >> 1)];
                float q00 = (v00 * c0 - v01 * s0) * scale;
                float q01 = (v00 * s0 + v01 * c0) * scale;
                float q10 = (v10 * c1 - v11 * s1) * scale;
                float q11 = (v10 * s1 + v11 * c1) * scale;
                __nv_bfloat16* dh = (mode == 0) ? g_qhi : g_khi;
                __nv_bfloat16* dl = (mode == 0) ? g_qlo : g_klo;
                size_t o0 = ((size_t)h * S_LEN + r0) * HEAD_DIM + d;
                uint32_t hh, ll;
                split2(q00, q01, hh, ll);
                *(uint32_t*)(dh + o0) = hh;
                *(uint32_t*)(dl + o0) = ll;
                split2(q10, q11, hh, ll);
                *(uint32_t*)(dh + o0 + 8 * HEAD_DIM) = hh;
                *(uint32_t*)(dl + o0 + 8 * HEAD_DIM) = ll;
            }
        }
    }
}

__global__ void __launch_bounds__(256, 2) gemm_o(
    const float* __restrict__ bias, float* __restrict__ oout)
{
    extern __shared__ __align__(16) char dsm[];
    uint32_t sb0 = smem_u32(dsm);

    int tid = threadIdx.x, wid = tid >> 5, lane = tid & 31;
    int m0 = (wid >> 2) * 64, n0 = (wid & 3) * 32;
    int bm = blockIdx.y * 128, bn = blockIdx.x * 128;

    int lrow = tid >> 1, lks = (tid & 1) * 16;
    uint32_t soff = (uint32_t)(lrow * LDT + lks) * 2u;
    const __nv_bfloat16* pAh = g_ahi + (size_t)(bm + lrow) * D_MODEL + lks;
    const __nv_bfloat16* pAl = g_alo + (size_t)(bm + lrow) * D_MODEL + lks;
    const __nv_bfloat16* pBh = g_whi[3] + (size_t)(bn + lrow) * D_MODEL + lks;
    const __nv_bfloat16* pBl = g_wlo[3] + (size_t)(bn + lrow) * D_MODEL + lks;

    float acc[4][4][4];
#pragma unroll
    for (int i = 0; i < 4; i++)
#pragma unroll
        for (int j = 0; j < 4; j++)
#pragma unroll
            for (int e = 0; e < 4; e++) acc[i][j][e] = 0.f;

    gemm_core(sb0, soff, pAh, pAl, pBh, pBl, m0, n0, lane, acc);

    int rq = lane >> 2, cq = (lane & 3) * 2;
#pragma unroll
    for (int mt = 0; mt < 4; mt++) {
#pragma unroll
        for (int nt = 0; nt < 4; nt++) {
            int r0 = bm + m0 + mt * 16 + rq;
            int cg = bn + n0 + nt * 8 + cq;
            float b0 = bias[cg], b1 = bias[cg + 1];
            *(float2*)(oout + (size_t)r0 * D_MODEL + cg) =
                make_float2(acc[mt][nt][0] + b0, acc[mt][nt][1] + b1);
            *(float2*)(oout + (size_t)(r0 + 8) * D_MODEL + cg) =
                make_float2(acc[mt][nt][2] + b0, acc[mt][nt][3] + b1);
        }
    }
}

// ------------------- flash attention: 2 CTAs/SM, half-tile softmax ---------
// 128q x 128k tile, keys processed as two 64-col halves (exact online softmax).
// Single-stage K/V smem; cross-CTA overlap hides load latency.
#define LDQK 72
#define LDV 136
#define QBUF (128 * LDQK * 2)          // 18432 (also KBUF)
#define VBUF (64 * LDV * 2)            // 17408
#define OFF_K (2 * QBUF)
#define OFF_V (4 * QBUF)
#define ATTN_SMEM (4 * QBUF + 2 * VBUF)  // 108544 -> 2 CTAs/SM

__global__ void __launch_bounds__(256, 2) attn_k()
{
    extern __shared__ __align__(16) char smraw[];
    uint32_t sb = smem_u32(smraw);
    uint32_t aQhi = sb, aQlo = sb + QBUF;
    uint32_t aKhi = sb + OFF_K, aKlo = sb + OFF_K + QBUF;
    uint32_t aVhi = sb + OFF_V, aVlo = sb + OFF_V + VBUF;

    int qb = gridDim.x - 1 - blockIdx.x;
    int h = blockIdx.y;
    int tid = threadIdx.x, wid = tid >> 5, lane = tid & 31;
    int m0 = wid * 16;
    int rq = lane >> 2, cq = (lane & 3) * 2;

    // load Q tile (blocking, once)
    {
        const __nv_bfloat16* qhg = g_qhi + ((size_t)h * S_LEN + qb * 128) * HEAD_DIM;
        const __nv_bfloat16* qlg = g_qlo + ((size_t)h * S_LEN + qb * 128) * HEAD_DIM;
#pragma unroll
        for (int it = 0; it < 4; it++) {
            int idx4 = tid + it * 256;
            int row = idx4 >> 3, col = (idx4 & 7) << 3;
            uint32_t off = (uint32_t)(row * LDQK + col) * 2u;
            cpa16(aQhi + off, qhg + (size_t)row * HEAD_DIM + col);
            cpa16(aQlo + off, qlg + (size_t)row * HEAD_DIM + col);
        }
        cpa_commit();
    }

    float m[2] = {-1e30f, -1e30f};
    float l[2] = {0.f, 0.f};
    float o[8][4];
#pragma unroll
    for (int dt = 0; dt < 8; dt++)
#pragma unroll
        for (int e = 0; e < 4; e++) o[dt][e] = 0.f;

    const __nv_bfloat16* khg0 = g_khi + (size_t)h * S_LEN * HEAD_DIM;
    const __nv_bfloat16* klg0 = g_klo + (size_t)h * S_LEN * HEAD_DIM;
    const __nv_bfloat16* vhg0 = g_vhi + (size_t)h * HEAD_DIM * S_LEN;
    const __nv_bfloat16* vlg0 = g_vlo + (size_t)h * HEAD_DIM * S_LEN;

    for (int kb = 0; kb <= qb; kb++) {
        __syncthreads();  // prev iter's smem reads done
        // ---- load K/V tile (single stage)
        {
            const __nv_bfloat16* khg = khg0 + (size_t)(kb * 128) * HEAD_DIM;
            const __nv_bfloat16* klg = klg0 + (size_t)(kb * 128) * HEAD_DIM;
            const __nv_bfloat16* vhg = vhg0 + kb * 128;
            const __nv_bfloat16* vlg = vlg0 + kb * 128;
#pragma unroll
            for (int it = 0; it < 4; it++) {
                int idx4 = tid + it * 256;
                int row = idx4 >> 3, col = (idx4 & 7) << 3;
                uint32_t koff = (uint32_t)(row * LDQK + col) * 2u;
                cpa16(aKhi + koff, khg + (size_t)row * HEAD_DIM + col);
                cpa16(aKlo + koff, klg + (size_t)row * HEAD_DIM + col);
                int vrow = idx4 >> 4, vcol = (idx4 & 15) << 3;
                uint32_t voff = (uint32_t)(vrow * LDV + vcol) * 2u;
                cpa16(aVhi + voff, vhg + (size_t)vrow * S_LEN + vcol);
                cpa16(aVlo + voff, vlg + (size_t)vrow * S_LEN + vcol);
            }
            cpa_commit();
            cpa_wait<0>();
        }
        __syncthreads();

        // ---- two 64-column halves
#pragma unroll
        for (int half = 0; half < 2; half++) {
            int nb = half * 64;

            float sc[8][4];
#pragma unroll
            for (int nt = 0; nt < 8; nt++)
#pragma unroll
                for (int e = 0; e < 4; e++) sc[nt][e] = 0.f;

#pragma unroll
            for (int ks = 0; ks < 4; ks++) {
                int k0 = ks * 16;
                uint32_t ah[4], al[4];
                ldsm_x4(ah, addrA(aQhi, m0, k0, lane, LDQK));
                ldsm_x4(al, addrA(aQlo, m0, k0, lane, LDQK));
#pragma unroll
                for (int pg = 0; pg < 2; pg++) {
                    int p0 = nb + pg * 32;
                    uint32_t bh0[4], bl0[4], bh1[4], bl1[4];
                    ldsm_x4(bh0, addrB4(aKhi, p0, k0, lane, LDQK));
                    ldsm_x4(bl0, addrB4(aKlo, p0, k0, lane, LDQK));
                    ldsm_x4(bh1, addrB4(aKhi, p0 + 16, k0, lane, LDQK));
                    ldsm_x4(bl1, addrB4(aKlo, p0 + 16, k0, lane, LDQK));
                    float* s0 = sc[4 * pg + 0];
                    float* s1 = sc[4 * pg + 1];
                    float* s2 = sc[4 * pg + 2];
                    float* s3 = sc[4 * pg + 3];
                    mma_bf16(s0, ah, bh0); mma_bf16(s1, ah, bh0 + 2);
                    mma_bf16(s2, ah, bh1); mma_bf16(s3, ah, bh1 + 2);
                    mma_bf16(s0, ah, bl0); mma_bf16(s1, ah, bl0 + 2);
                    mma_bf16(s2, ah, bl1); mma_bf16(s3, ah, bl1 + 2);
                    mma_bf16(s0, al, bh0); mma_bf16(s1, al, bh0 + 2);
                    mma_bf16(s2, al, bh1); mma_bf16(s3, al, bh1 + 2);
                }
            }

            // ---- causal mask on diagonal tile
            if (kb == qb) {
#pragma unroll
                for (int nt = 0; nt < 8; nt++)
#pragma unroll
                    for (int e = 0; e < 4; e++) {
                        int qi = m0 + rq + ((e >> 1) << 3);
                        int kj = nb + nt * 8 + cq + (e & 1);
                        if (kj > qi) sc[nt][e] = -1e30f;
                    }
            }

            // ---- online softmax over this half
#pragma unroll
            for (int r = 0; r < 2; r++) {
                float mx = -1e30f;
#pragma unroll
                for (int nt = 0; nt < 8; nt++)
                    mx = fmaxf(mx, fmaxf(sc[nt][2 * r], sc[nt][2 * r + 1]));
                mx = fmaxf(mx, __shfl_xor_sync(0xffffffffu, mx, 1));
                mx = fmaxf(mx, __shfl_xor_sync(0xffffffffu, mx, 2));
                float mn = fmaxf(m[r], mx);
                float corr = __expf(m[r] - mn);
                m[r] = mn;
                float rs = 0.f;
#pragma unroll
                for (int nt = 0; nt < 8; nt++) {
                    float p0 = __expf(sc[nt][2 * r] - mn);
                    float p1 = __expf(sc[nt][2 * r + 1] - mn);
                    sc[nt][2 * r] = p0;
                    sc[nt][2 * r + 1] = p1;
                    rs += p0 + p1;
                }
                l[r] = l[r] * corr + rs;
#pragma unroll
                for (int dt = 0; dt < 8; dt++) {
                    o[dt][2 * r] *= corr;
                    o[dt][2 * r + 1] *= corr;
                }
            }

            // ---- PV for this half
#pragma unroll
            for (int kp = 0; kp < 4; kp++) {
                uint32_t ph[4], pl[4];
                split2(sc[2 * kp][0], sc[2 * kp][1], ph[0], pl[0]);
                split2(sc[2 * kp][2], sc[2 * kp][3], ph[1], pl[1]);
                split2(sc[2 * kp + 1][0], sc[2 * kp + 1][1], ph[2], pl[2]);
                split2(sc[2 * kp + 1][2], sc[2 * kp + 1][3], ph[3], pl[3]);
                int k0 = nb + kp * 16;
#pragma unroll
                for (int pg = 0; pg < 2; pg++) {
                    int p0 = pg * 32;
                    uint32_t bh0[4], bl0[4], bh1[4], bl1[4];
                    ldsm_x4(bh0, addrB4(aVhi, p0, k0, lane, LDV));
                    ldsm_x4(bl0, addrB4(aVlo, p0, k0, lane, LDV));
                    ldsm_x4(bh1, addrB4(aVhi, p0 + 16, k0, lane, LDV));
                    ldsm_x4(bl1, addrB4(aVlo, p0 + 16, k0, lane, LDV));
                    float* o0 = o[4 * pg + 0];
                    float* o1 = o[4 * pg + 1];
                    float* o2 = o[4 * pg + 2];
                    float* o3 = o[4 * pg + 3];
                    mma_bf16(o0, ph, bh0); mma_bf16(o1, ph, bh0 + 2);
                    mma_bf16(o2, ph, bh1); mma_bf16(o3, ph, bh1 + 2);
                    mma_bf16(o0, ph, bl0); mma_bf16(o1, ph, bl0 + 2);
                    mma_bf16(o2, ph, bl1); mma_bf16(o3, ph, bl1 + 2);
                    mma_bf16(o0, pl, bh0); mma_bf16(o1, pl, bh0 + 2);
                    mma_bf16(o2, pl, bh1); mma_bf16(o3, pl, bh1 + 2);
                }
            }
        }
    }

    // ---- finalize
#pragma unroll
    for (int r = 0; r < 2; r++) {
        l[r] += __shfl_xor_sync(0xffffffffu, l[r], 1);
        l[r] += __shfl_xor_sync(0xffffffffu, l[r], 2);
    }
    float inv0 = 1.f / l[0], inv1 = 1.f / l[1];
    int r0 = qb * 128 + m0 + rq;
    size_t ob = (size_t)r0 * D_MODEL + h * HEAD_DIM + cq;
#pragma unroll
    for (int dt = 0; dt < 8; dt++) {
        uint32_t hh, ll;
        split2(o[dt][0] * inv0, o[dt][1] * inv0, hh, ll);
        *(uint32_t*)(g_ahi + ob + dt * 8) = hh;
        *(uint32_t*)(g_alo + ob + dt * 8) = ll;
        split2(o[dt][2] * inv1, o[dt][3] * inv1, hh, ll);
        *(uint32_t*)(g_ahi + ob + 8 * D_MODEL + dt * 8) = hh;
        *(uint32_t*)(g_alo + ob + 8 * D_MODEL + dt * 8) = ll;
    }
}

extern "C" void kernel_launch(void* const* d_in, const int* in_sizes, int n_in,
                              void* d_out, int out_size)
{
    const float* x    = (const float*)d_in[0];
    const float* fcos = (const float*)d_in[2];
    const float* fsin = (const float*)d_in[3];
    const float* wq  = (const float*)d_in[5];
    const float* wqb = (const float*)d_in[6];
    const float* wk  = (const float*)d_in[7];
    const float* wkb = (const float*)d_in[8];
    const float* wv  = (const float*)d_in[9];
    const float* wvb = (const float*)d_in[10];
    const float* wo  = (const float*)d_in[11];
    const float* wob = (const float*)d_in[12];
    float* out = (float*)d_out;

    static bool attr_set = false;
    if (!attr_set) {
        cudaFuncSetAttribute(attn_k,
                             cudaFuncAttributeMaxDynamicSharedMemorySize,
                             ATTN_SMEM);
        cudaFuncSetAttribute(gemm_qkv,
                             cudaFuncAttributeMaxDynamicSharedMemorySize,
                             GEMM_SMEM);
        cudaFuncSetAttribute(gemm_o,
                             cudaFuncAttributeMaxDynamicSharedMemorySize,
                             GEMM_SMEM);
        attr_set = true;
    }

    conv_all<<<(NX + 4 * NW) / 256, 256>>>(x, wq, wk, wv, wo);
    gemm_qkv<<<dim3(D_MODEL / 128, S_LEN / 128, 3), 256, GEMM_SMEM>>>(
        wqb, wkb, wvb, fcos, fsin);
    attn_k<<<dim3(S_LEN / 128, N_HEADS), 256, ATTN_SMEM>>>();
    gemm_o<<<dim3(D_MODEL / 128, S_LEN / 128), 256, GEMM_SMEM>>>(wob, out);
}

// round 11
// speedup vs baseline: 1.1428x; 1.0864x over previous
#include <cuda_runtime.h>
#include <cuda_bf16.h>
#include <cuda_fp16.h>
#include <cstdint>

#define S_LEN 4096
#define D_MODEL 1024
#define N_HEADS 16
#define HEAD_DIM 64
#define HALF_DIM 32

// ---------------- split-precision scratch (device globals) -----------------
__device__ __align__(16) __nv_bfloat16 g_xhi[S_LEN * D_MODEL];
__device__ __align__(16) __nv_bfloat16 g_xlo[S_LEN * D_MODEL];
__device__ __align__(16) __nv_bfloat16 g_whi[4][D_MODEL * D_MODEL];
__device__ __align__(16) __nv_bfloat16 g_wlo[4][D_MODEL * D_MODEL];
__device__ __align__(16) __nv_bfloat16 g_qhi[N_HEADS * S_LEN * HEAD_DIM]; // RoPE'd, *log2e/8
__device__ __align__(16) __nv_bfloat16 g_qlo[N_HEADS * S_LEN * HEAD_DIM];
__device__ __align__(16) __nv_bfloat16 g_khi[N_HEADS * S_LEN * HEAD_DIM]; // RoPE'd
__device__ __align__(16) __nv_bfloat16 g_klo[N_HEADS * S_LEN * HEAD_DIM];
__device__ __align__(16) __half       g_vhi[N_HEADS * HEAD_DIM * S_LEN];  // [h][d][s] fp16 split
__device__ __align__(16) __half       g_vlo[N_HEADS * HEAD_DIM * S_LEN];
__device__ __align__(16) __nv_bfloat16 g_ahi[S_LEN * D_MODEL];            // attn out
__device__ __align__(16) __nv_bfloat16 g_alo[S_LEN * D_MODEL];

// ---------------- helpers ---------------------------------------------------
__device__ __forceinline__ uint32_t smem_u32(const void* p) {
    uint32_t a;
    asm("{ .reg .u64 t; cvta.to.shared.u64 t, %1; cvt.u32.u64 %0, t; }"
        : "=r"(a) : "l"(p));
    return a;
}

__device__ __forceinline__ void cpa16(uint32_t dst, const void* src) {
    asm volatile("cp.async.cg.shared.global [%0], [%1], 16;"
                 :: "r"(dst), "l"(src));
}
__device__ __forceinline__ void cpa_commit() {
    asm volatile("cp.async.commit_group;");
}
template <int N>
__device__ __forceinline__ void cpa_wait() {
    asm volatile("cp.async.wait_group %0;" :: "n"(N));
}

__device__ __forceinline__ void ldsm_x4(uint32_t* r, uint32_t addr) {
    asm volatile("ldmatrix.sync.aligned.m8n8.x4.shared.b16 {%0,%1,%2,%3}, [%4];"
                 : "=r"(r[0]), "=r"(r[1]), "=r"(r[2]), "=r"(r[3]) : "r"(addr));
}

__device__ __forceinline__ void mma_bf16(float* c, const uint32_t* a,
                                         const uint32_t* b) {
    asm volatile(
        "mma.sync.aligned.m16n8k16.row.col.f32.bf16.bf16.f32 "
        "{%0,%1,%2,%3}, {%4,%5,%6,%7}, {%8,%9}, {%0,%1,%2,%3};"
        : "+f"(c[0]), "+f"(c[1]), "+f"(c[2]), "+f"(c[3])
        : "r"(a[0]), "r"(a[1]), "r"(a[2]), "r"(a[3]), "r"(b[0]), "r"(b[1]));
}

__device__ __forceinline__ void mma_f16(float* c, const uint32_t* a,
                                        const uint32_t* b) {
    asm volatile(
        "mma.sync.aligned.m16n8k16.row.col.f32.f16.f16.f32 "
        "{%0,%1,%2,%3}, {%4,%5,%6,%7}, {%8,%9}, {%0,%1,%2,%3};"
        : "+f"(c[0]), "+f"(c[1]), "+f"(c[2]), "+f"(c[3])
        : "r"(a[0]), "r"(a[1]), "r"(a[2]), "r"(a[3]), "r"(b[0]), "r"(b[1]));
}

__device__ __forceinline__ float ex2f(float x) {
    float y;
    asm("ex2.approx.f32 %0, %1;" : "=f"(y) : "f"(x));
    return y;
}

__device__ __forceinline__ uint32_t pk_bf2(__nv_bfloat16 a, __nv_bfloat16 b) {
    __nv_bfloat162 t = __halves2bfloat162(a, b);
    return *reinterpret_cast<uint32_t*>(&t);
}

__device__ __forceinline__ uint32_t pk_h2(float a, float b) {
    __half2 t = __floats2half2_rn(a, b);
    return *reinterpret_cast<uint32_t*>(&t);
}

__device__ __forceinline__ void split2(float a, float b,
                                       uint32_t& hi, uint32_t& lo) {
    __nv_bfloat16 ha = __float2bfloat16_rn(a);
    __nv_bfloat16 hb = __float2bfloat16_rn(b);
    __nv_bfloat16 la = __float2bfloat16_rn(a - __bfloat162float(ha));
    __nv_bfloat16 lb = __float2bfloat16_rn(b - __bfloat162float(hb));
    hi = pk_bf2(ha, hb);
    lo = pk_bf2(la, lb);
}

__device__ __forceinline__ void store_split1h(__half* hi, __half* lo,
                                              size_t i, float v) {
    __half h = __float2half_rn(v);
    hi[i] = h;
    lo[i] = __float2half_rn(v - __half2float(h));
}

__device__ __forceinline__ uint32_t addrA(uint32_t base, int m0, int k0,
                                          int lane, int ld) {
    int r = m0 + (lane & 15);
    int c = k0 + ((lane >> 4) << 3);
    return base + (uint32_t)(r * ld + c) * 2u;
}
__device__ __forceinline__ uint32_t addrB4(uint32_t base, int n0, int k0,
                                           int lane, int ld) {
    int g = lane >> 3;
    int r = n0 + ((g >> 1) << 3) + (lane & 7);
    int c = k0 + ((g & 1) << 3);
    return base + (uint32_t)(r * ld + c) * 2u;
}

// ---------------- pre-pass: f32 -> split-bf16 (fused, one launch) ----------
#define NX (S_LEN * D_MODEL / 4)
#define NW (D_MODEL * D_MODEL / 4)

__global__ void __launch_bounds__(256) conv_all(
    const float* __restrict__ x, const float* __restrict__ wq,
    const float* __restrict__ wk, const float* __restrict__ wv,
    const float* __restrict__ wo)
{
    int idx = blockIdx.x * 256 + threadIdx.x;
    const float* src;
    __nv_bfloat16 *hi, *lo;
    int off;
    if (idx < NX) {
        src = x; hi = g_xhi; lo = g_xlo; off = idx;
    } else {
        int j = idx - NX;
        int t = j >> 18;
        off = j & (NW - 1);
        src = (t == 0) ? wq : (t == 1) ? wk : (t == 2) ? wv : wo;
        hi = g_whi[t]; lo = g_wlo[t];
    }
    float4 f = ((const float4*)src)[off];
    uint32_t h0, h1, l0, l1;
    split2(f.x, f.y, h0, l0);
    split2(f.z, f.w, h1, l1);
    ((uint2*)hi)[off] = make_uint2(h0, h1);
    ((uint2*)lo)[off] = make_uint2(l0, l1);
}

// ------------------- tensor-core GEMM (cp.async, double-buffered) ----------
#define LDT 40
#define GEMM_BUF (128 * LDT * 2)
#define GEMM_STAGE (4 * GEMM_BUF)
#define GEMM_SMEM (2 * GEMM_STAGE)   // 80 KB -> 2 CTAs/SM

__device__ __forceinline__ void gemm_issue(
    uint32_t sb, uint32_t soff,
    const __nv_bfloat16* pAh, const __nv_bfloat16* pAl,
    const __nv_bfloat16* pBh, const __nv_bfloat16* pBl, int c)
{
    int go = c * 32;
    cpa16(sb + soff,                       pAh + go);
    cpa16(sb + soff + 16,                  pAh + go + 8);
    cpa16(sb + GEMM_BUF + soff,            pAl + go);
    cpa16(sb + GEMM_BUF + soff + 16,       pAl + go + 8);
    cpa16(sb + 2 * GEMM_BUF + soff,        pBh + go);
    cpa16(sb + 2 * GEMM_BUF + soff + 16,   pBh + go + 8);
    cpa16(sb + 3 * GEMM_BUF + soff,        pBl + go);
    cpa16(sb + 3 * GEMM_BUF + soff + 16,   pBl + go + 8);
    cpa_commit();
}

__device__ __forceinline__ void gemm_core(
    uint32_t sb0, uint32_t soff,
    const __nv_bfloat16* pAh, const __nv_bfloat16* pAl,
    const __nv_bfloat16* pBh, const __nv_bfloat16* pBl,
    int m0, int n0, int lane, float acc[4][4][4])
{
    gemm_issue(sb0, soff, pAh, pAl, pBh, pBl, 0);
    gemm_issue(sb0 + GEMM_STAGE, soff, pAh, pAl, pBh, pBl, 1);

    for (int c = 0; c < 32; c++) {
        if (c < 31) cpa_wait<1>(); else cpa_wait<0>();
        __syncthreads();
        uint32_t sb = sb0 + (c & 1) * GEMM_STAGE;
        uint32_t aAhi = sb, aAlo = sb + GEMM_BUF;
        uint32_t aBhi = sb + 2 * GEMM_BUF, aBlo = sb + 3 * GEMM_BUF;
#pragma unroll
        for (int ks = 0; ks < 2; ks++) {
            int k0 = ks * 16;
            uint32_t bh[2][4], bl[2][4];
#pragma unroll
            for (int p = 0; p < 2; p++) {
                ldsm_x4(bh[p], addrB4(aBhi, n0 + p * 16, k0, lane, LDT));
                ldsm_x4(bl[p], addrB4(aBlo, n0 + p * 16, k0, lane, LDT));
            }
#pragma unroll
            for (int mt = 0; mt < 4; mt++) {
                uint32_t ah[4], al[4];
                ldsm_x4(ah, addrA(aAhi, m0 + mt * 16, k0, lane, LDT));
                ldsm_x4(al, addrA(aAlo, m0 + mt * 16, k0, lane, LDT));
#pragma unroll
                for (int nt = 0; nt < 4; nt++) {
                    const uint32_t* pbh = &bh[nt >> 1][(nt & 1) * 2];
                    const uint32_t* pbl = &bl[nt >> 1][(nt & 1) * 2];
                    mma_bf16(acc[mt][nt], ah, pbh);
                    mma_bf16(acc[mt][nt], ah, pbl);
                    mma_bf16(acc[mt][nt], al, pbh);
                }
            }
        }
        __syncthreads();
        if (c + 2 < 32)
            gemm_issue(sb0 + (c & 1) * GEMM_STAGE, soff, pAh, pAl, pBh, pBl, c + 2);
    }
}

// QKV fused: blockIdx.z = mode (0=Q,1=K,2=V)
__global__ void __launch_bounds__(256, 2) gemm_qkv(
    const float* __restrict__ bq, const float* __restrict__ bk,
    const float* __restrict__ bv, const float* __restrict__ fcos,
    const float* __restrict__ fsin)
{
    extern __shared__ __align__(16) char dsm[];
    uint32_t sb0 = smem_u32(dsm);

    int mode = blockIdx.z;
    const float* bias = (mode == 0) ? bq : (mode == 1) ? bk : bv;

    int tid = threadIdx.x, wid = tid >> 5, lane = tid & 31;
    int m0 = (wid >> 2) * 64, n0 = (wid & 3) * 32;
    int bm = blockIdx.y * 128, bn = blockIdx.x * 128;

    int lrow = tid >> 1, lks = (tid & 1) * 16;
    uint32_t soff = (uint32_t)(lrow * LDT + lks) * 2u;
    const __nv_bfloat16* pAh = g_xhi + (size_t)(bm + lrow) * D_MODEL + lks;
    const __nv_bfloat16* pAl = g_xlo + (size_t)(bm + lrow) * D_MODEL + lks;
    const __nv_bfloat16* pBh = g_whi[mode] + (size_t)(bn + lrow) * D_MODEL + lks;
    const __nv_bfloat16* pBl = g_wlo[mode] + (size_t)(bn + lrow) * D_MODEL + lks;

    float acc[4][4][4];
#pragma unroll
    for (int i = 0; i < 4; i++)
#pragma unroll
        for (int j = 0; j < 4; j++)
#pragma unroll
            for (int e = 0; e < 4; e++) acc[i][j][e] = 0.f;

    gemm_core(sb0, soff, pAh, pAl, pBh, pBl, m0, n0, lane, acc);

    int rq = lane >> 2, cq = (lane & 3) * 2;
    // Q pre-scale folds softmax 1/sqrt(64) AND log2(e) for ex2-based softmax
    float scale = (mode == 0) ? (0.125f * 1.4426950408889634f) : 1.f;
#pragma unroll
    for (int mt = 0; mt < 4; mt++) {
#pragma unroll
        for (int nt = 0; nt < 4; nt++) {
            int r0 = bm + m0 + mt * 16 + rq;
            int cg = bn + n0 + nt * 8 + cq;
            float b0 = bias[cg], b1 = bias[cg + 1];
            float v00 = acc[mt][nt][0] + b0, v01 = acc[mt][nt][1] + b1;
            float v10 = acc[mt][nt][2] + b0, v11 = acc[mt][nt][3] + b1;
            int h = cg >> 6, d = cg & 63;
            if (mode == 2) {
                size_t o0 = ((size_t)h * HEAD_DIM + d) * S_LEN;
                store_split1h(g_vhi, g_vlo, o0 + r0, v00);
                store_split1h(g_vhi, g_vlo, o0 + r0 + 8, v10);
                store_split1h(g_vhi, g_vlo, o0 + S_LEN + r0, v01);
                store_split1h(g_vhi, g_vlo, o0 + S_LEN + r0 + 8, v11);
            } else {
                float c0 = fcos[(size_t)r0 * HALF_DIM + (d >> 1)];
                float s0 = fsin[(size_t)r0 * HALF_DIM + (d >> 1)];
                float c1 = fcos[(size_t)(r0 + 8) * HALF_DIM + (d >> 1)];
                float s1 = fsin[(size_t)(r0 + 8) * HALF_DIM + (d >> 1)];
                float q00 = (v00 * c0 - v01 * s0) * scale;
                float q01 = (v00 * s0 + v01 * c0) * scale;
                float q10 = (v10 * c1 - v11 * s1) * scale;
                float q11 = (v10 * s1 + v11 * c1) * scale;
                __nv_bfloat16* dh = (mode == 0) ? g_qhi : g_khi;
                __nv_bfloat16* dl = (mode == 0) ? g_qlo : g_klo;
                size_t o0 = ((size_t)h * S_LEN + r0) * HEAD_DIM + d;
                uint32_t hh, ll;
                split2(q00, q01, hh, ll);
                *(uint32_t*)(dh + o0) = hh;
                *(uint32_t*)(dl + o0) = ll;
                split2(q10, q11, hh, ll);
                *(uint32_t*)(dh + o0 + 8 * HEAD_DIM) = hh;
                *(uint32_t*)(dl + o0 + 8 * HEAD_DIM) = ll;
            }
        }
    }
}

__global__ void __launch_bounds__(256, 2) gemm_o(
    const float* __restrict__ bias, float* __restrict__ oout)
{
    extern __shared__ __align__(16) char dsm[];
    uint32_t sb0 = smem_u32(dsm);

    int tid = threadIdx.x, wid = tid >> 5, lane = tid & 31;
    int m0 = (wid >> 2) * 64, n0 = (wid & 3) * 32;
    int bm = blockIdx.y * 128, bn = blockIdx.x * 128;

    int lrow = tid >> 1, lks = (tid & 1) * 16;
    uint32_t soff = (uint32_t)(lrow * LDT + lks) * 2u;
    const __nv_bfloat16* pAh = g_ahi + (size_t)(bm + lrow) * D_MODEL + lks;
    const __nv_bfloat16* pAl = g_alo + (size_t)(bm + lrow) * D_MODEL + lks;
    const __nv_bfloat16* pBh = g_whi[3] + (size_t)(bn + lrow) * D_MODEL + lks;
    const __nv_bfloat16* pBl = g_wlo[3] + (size_t)(bn + lrow) * D_MODEL + lks;

    float acc[4][4][4];
#pragma unroll
    for (int i = 0; i < 4; i++)
#pragma unroll
        for (int j = 0; j < 4; j++)
#pragma unroll
            for (int e = 0; e < 4; e++) acc[i][j][e] = 0.f;

    gemm_core(sb0, soff, pAh, pAl, pBh, pBl, m0, n0, lane, acc);

    int rq = lane >> 2, cq = (lane & 3) * 2;
#pragma unroll
    for (int mt = 0; mt < 4; mt++) {
#pragma unroll
        for (int nt = 0; nt < 4; nt++) {
            int r0 = bm + m0 + mt * 16 + rq;
            int cg = bn + n0 + nt * 8 + cq;
            float b0 = bias[cg], b1 = bias[cg + 1];
            *(float2*)(oout + (size_t)r0 * D_MODEL + cg) =
                make_float2(acc[mt][nt][0] + b0, acc[mt][nt][1] + b1);
            *(float2*)(oout + (size_t)(r0 + 8) * D_MODEL + cg) =
                make_float2(acc[mt][nt][2] + b0, acc[mt][nt][3] + b1);
        }
    }
}

// ------------------- flash attention: 2 CTAs/SM, fp16 PV -------------------
#define LDQK 72
#define LDV 136
#define QBUF (128 * LDQK * 2)
#define VBUF (64 * LDV * 2)
#define OFF_K (2 * QBUF)
#define OFF_V (4 * QBUF)
#define ATTN_SMEM (4 * QBUF + 2 * VBUF)  // 108544 -> 2 CTAs/SM

__global__ void __launch_bounds__(256, 2) attn_k()
{
    extern __shared__ __align__(16) char smraw[];
    uint32_t sb = smem_u32(smraw);
    uint32_t aQhi = sb, aQlo = sb + QBUF;
    uint32_t aKhi = sb + OFF_K, aKlo = sb + OFF_K + QBUF;
    uint32_t aVhi = sb + OFF_V, aVlo = sb + OFF_V + VBUF;

    int qb = gridDim.x - 1 - blockIdx.x;
    int h = blockIdx.y;
    int tid = threadIdx.x, wid = tid >> 5, lane = tid & 31;
    int m0 = wid * 16;
    int rq = lane >> 2, cq = (lane & 3) * 2;

    // load Q tile (blocking, once)
    {
        const __nv_bfloat16* qhg = g_qhi + ((size_t)h * S_LEN + qb * 128) * HEAD_DIM;
        const __nv_bfloat16* qlg = g_qlo + ((size_t)h * S_LEN + qb * 128) * HEAD_DIM;
#pragma unroll
        for (int it = 0; it < 4; it++) {
            int idx4 = tid + it * 256;
            int row = idx4 >> 3, col = (idx4 & 7) << 3;
            uint32_t off = (uint32_t)(row * LDQK + col) * 2u;
            cpa16(aQhi + off, qhg + (size_t)row * HEAD_DIM + col);
            cpa16(aQlo + off, qlg + (size_t)row * HEAD_DIM + col);
        }
        cpa_commit();
    }

    float m[2] = {-1e30f, -1e30f};
    float l[2] = {0.f, 0.f};
    float o[8][4];
#pragma unroll
    for (int dt = 0; dt < 8; dt++)
#pragma unroll
        for (int e = 0; e < 4; e++) o[dt][e] = 0.f;

    const __nv_bfloat16* khg0 = g_khi + (size_t)h * S_LEN * HEAD_DIM;
    const __nv_bfloat16* klg0 = g_klo + (size_t)h * S_LEN * HEAD_DIM;
    const __half* vhg0 = g_vhi + (size_t)h * HEAD_DIM * S_LEN;
    const __half* vlg0 = g_vlo + (size_t)h * HEAD_DIM * S_LEN;

    for (int kb = 0; kb <= qb; kb++) {
        __syncthreads();
        // ---- load K/V tile (single stage)
        {
            const __nv_bfloat16* khg = khg0 + (size_t)(kb * 128) * HEAD_DIM;
            const __nv_bfloat16* klg = klg0 + (size_t)(kb * 128) * HEAD_DIM;
            const __half* vhg = vhg0 + kb * 128;
            const __half* vlg = vlg0 + kb * 128;
#pragma unroll
            for (int it = 0; it < 4; it++) {
                int idx4 = tid + it * 256;
                int row = idx4 >> 3, col = (idx4 & 7) << 3;
                uint32_t koff = (uint32_t)(row * LDQK + col) * 2u;
                cpa16(aKhi + koff, khg + (size_t)row * HEAD_DIM + col);
                cpa16(aKlo + koff, klg + (size_t)row * HEAD_DIM + col);
                int vrow = idx4 >> 4, vcol = (idx4 & 15) << 3;
                uint32_t voff = (uint32_t)(vrow * LDV + vcol) * 2u;
                cpa16(aVhi + voff, vhg + (size_t)vrow * S_LEN + vcol);
                cpa16(aVlo + voff, vlg + (size_t)vrow * S_LEN + vcol);
            }
            cpa_commit();
            cpa_wait<0>();
        }
        __syncthreads();

        // ---- two 64-column halves
#pragma unroll
        for (int half = 0; half < 2; half++) {
            int nb = half * 64;

            float sc[8][4];
#pragma unroll
            for (int nt = 0; nt < 8; nt++)
#pragma unroll
                for (int e = 0; e < 4; e++) sc[nt][e] = 0.f;

#pragma unroll
            for (int ks = 0; ks < 4; ks++) {
                int k0 = ks * 16;
                uint32_t ah[4], al[4];
                ldsm_x4(ah, addrA(aQhi, m0, k0, lane, LDQK));
                ldsm_x4(al, addrA(aQlo, m0, k0, lane, LDQK));
#pragma unroll
                for (int pg = 0; pg < 2; pg++) {
                    int p0 = nb + pg * 32;
                    uint32_t bh0[4], bl0[4], bh1[4], bl1[4];
                    ldsm_x4(bh0, addrB4(aKhi, p0, k0, lane, LDQK));
                    ldsm_x4(bl0, addrB4(aKlo, p0, k0, lane, LDQK));
                    ldsm_x4(bh1, addrB4(aKhi, p0 + 16, k0, lane, LDQK));
                    ldsm_x4(bl1, addrB4(aKlo, p0 + 16, k0, lane, LDQK));
                    float* s0 = sc[4 * pg + 0];
                    float* s1 = sc[4 * pg + 1];
                    float* s2 = sc[4 * pg + 2];
                    float* s3 = sc[4 * pg + 3];
                    mma_bf16(s0, ah, bh0); mma_bf16(s1, ah, bh0 + 2);
                    mma_bf16(s2, ah, bh1); mma_bf16(s3, ah, bh1 + 2);
                    mma_bf16(s0, ah, bl0); mma_bf16(s1, ah, bl0 + 2);
                    mma_bf16(s2, ah, bl1); mma_bf16(s3, ah, bl1 + 2);
                    mma_bf16(s0, al, bh0); mma_bf16(s1, al, bh0 + 2);
                    mma_bf16(s2, al, bh1); mma_bf16(s3, al, bh1 + 2);
                }
            }

            // ---- causal mask on diagonal tile
            if (kb == qb) {
#pragma unroll
                for (int nt = 0; nt < 8; nt++)
#pragma unroll
                    for (int e = 0; e < 4; e++) {
                        int qi = m0 + rq + ((e >> 1) << 3);
                        int kj = nb + nt * 8 + cq + (e & 1);
                        if (kj > qi) sc[nt][e] = -1e30f;
                    }
            }

            // ---- online softmax (log2 domain, ex2)
#pragma unroll
            for (int r = 0; r < 2; r++) {
                float mx = -1e30f;
#pragma unroll
                for (int nt = 0; nt < 8; nt++)
                    mx = fmaxf(mx, fmaxf(sc[nt][2 * r], sc[nt][2 * r + 1]));
                mx = fmaxf(mx, __shfl_xor_sync(0xffffffffu, mx, 1));
                mx = fmaxf(mx, __shfl_xor_sync(0xffffffffu, mx, 2));
                float mn = fmaxf(m[r], mx);
                float corr = ex2f(m[r] - mn);
                m[r] = mn;
                float rs = 0.f;
#pragma unroll
                for (int nt = 0; nt < 8; nt++) {
                    float p0 = ex2f(sc[nt][2 * r] - mn);
                    float p1 = ex2f(sc[nt][2 * r + 1] - mn);
                    sc[nt][2 * r] = p0;
                    sc[nt][2 * r + 1] = p1;
                    rs += p0 + p1;
                }
                l[r] = l[r] * corr + rs;
#pragma unroll
                for (int dt = 0; dt < 8; dt++) {
                    o[dt][2 * r] *= corr;
                    o[dt][2 * r + 1] *= corr;
                }
            }

            // ---- PV: single-fp16 P, 2-term fp16 V (2 MMAs per term pair)
#pragma unroll
            for (int kp = 0; kp < 4; kp++) {
                uint32_t pa[4];
                pa[0] = pk_h2(sc[2 * kp][0], sc[2 * kp][1]);
                pa[1] = pk_h2(sc[2 * kp][2], sc[2 * kp][3]);
                pa[2] = pk_h2(sc[2 * kp + 1][0], sc[2 * kp + 1][1]);
                pa[3] = pk_h2(sc[2 * kp + 1][2], sc[2 * kp + 1][3]);
                int k0 = nb + kp * 16;
#pragma unroll
                for (int pg = 0; pg < 2; pg++) {
                    int p0 = pg * 32;
                    uint32_t vh0[4], vl0[4], vh1[4], vl1[4];
                    ldsm_x4(vh0, addrB4(aVhi, p0, k0, lane, LDV));
                    ldsm_x4(vl0, addrB4(aVlo, p0, k0, lane, LDV));
                    ldsm_x4(vh1, addrB4(aVhi, p0 + 16, k0, lane, LDV));
                    ldsm_x4(vl1, addrB4(aVlo, p0 + 16, k0, lane, LDV));
                    float* o0 = o[4 * pg + 0];
                    float* o1 = o[4 * pg + 1];
                    float* o2 = o[4 * pg + 2];
                    float* o3 = o[4 * pg + 3];
                    mma_f16(o0, pa, vh0); mma_f16(o1, pa, vh0 + 2);
                    mma_f16(o2, pa, vh1); mma_f16(o3, pa, vh1 + 2);
                    mma_f16(o0, pa, vl0); mma_f16(o1, pa, vl0 + 2);
                    mma_f16(o2, pa, vl1); mma_f16(o3, pa, vl1 + 2);
                }
            }
        }
    }

    // ---- finalize
#pragma unroll
    for (int r = 0; r < 2; r++) {
        l[r] += __shfl_xor_sync(0xffffffffu, l[r], 1);
        l[r] += __shfl_xor_sync(0xffffffffu, l[r], 2);
    }
    float inv0 = 1.f / l[0], inv1 = 1.f / l[1];
    int r0 = qb * 128 + m0 + rq;
    size_t ob = (size_t)r0 * D_MODEL + h * HEAD_DIM + cq;
#pragma unroll
    for (int dt = 0; dt < 8; dt++) {
        uint32_t hh, ll;
        split2(o[dt][0] * inv0, o[dt][1] * inv0, hh, ll);
        *(uint32_t*)(g_ahi + ob + dt * 8) = hh;
        *(uint32_t*)(g_alo + ob + dt * 8) = ll;
        split2(o[dt][2] * inv1, o[dt][3] * inv1, hh, ll);
        *(uint32_t*)(g_ahi + ob + 8 * D_MODEL + dt * 8) = hh;
        *(uint32_t*)(g_alo + ob + 8 * D_MODEL + dt * 8) = ll;
    }
}

extern "C" void kernel_launch(void* const* d_in, const int* in_sizes, int n_in,
                              void* d_out, int out_size)
{
    const float* x    = (const float*)d_in[0];
    const float* fcos = (const float*)d_in[2];
    const float* fsin = (const float*)d_in[3];
    const float* wq  = (const float*)d_in[5];
    const float* wqb = (const float*)d_in[6];
    const float* wk  = (const float*)d_in[7];
    const float* wkb = (const float*)d_in[8];
    const float* wv  = (const float*)d_in[9];
    const float* wvb = (const float*)d_in[10];
    const float* wo  = (const float*)d_in[11];
    const float* wob = (const float*)d_in[12];
    float* out = (float*)d_out;

    static bool attr_set = false;
    if (!attr_set) {
        cudaFuncSetAttribute(attn_k,
                             cudaFuncAttributeMaxDynamicSharedMemorySize,
                             ATTN_SMEM);
        cudaFuncSetAttribute(gemm_qkv,
                             cudaFuncAttributeMaxDynamicSharedMemorySize,
                             GEMM_SMEM);
        cudaFuncSetAttribute(gemm_o,
                             cudaFuncAttributeMaxDynamicSharedMemorySize,
                             GEMM_SMEM);
        attr_set = true;
    }

    conv_all<<<(NX + 4 * NW) / 256, 256>>>(x, wq, wk, wv, wo);
    gemm_qkv<<<dim3(D_MODEL / 128, S_LEN / 128, 3), 256, GEMM_SMEM>>>(
        wqb, wkb, wvb, fcos, fsin);
    attn_k<<<dim3(S_LEN / 128, N_HEADS), 256, ATTN_SMEM>>>();
    gemm_o<<<dim3(D_MODEL / 128, S_LEN / 128), 256, GEMM_SMEM>>>(wob, out);
}

// round 12
// speedup vs baseline: 1.1572x; 1.0126x over previous
#include <cuda_runtime.h>
#include <cuda_bf16.h>
#include <cuda_fp16.h>
#include <cstdint>

#define S_LEN 4096
#define D_MODEL 1024
#define N_HEADS 16
#define HEAD_DIM 64
#define HALF_DIM 32

// ---------------- split-precision scratch (device globals) -----------------
__device__ __align__(16) __nv_bfloat16 g_xhi[S_LEN * D_MODEL];
__device__ __align__(16) __nv_bfloat16 g_xlo[S_LEN * D_MODEL];
__device__ __align__(16) __nv_bfloat16 g_whi[4][D_MODEL * D_MODEL];
__device__ __align__(16) __nv_bfloat16 g_wlo[4][D_MODEL * D_MODEL];
__device__ __align__(16) __nv_bfloat16 g_qhi[N_HEADS * S_LEN * HEAD_DIM]; // RoPE'd, *log2e/8
__device__ __align__(16) __nv_bfloat16 g_qlo[N_HEADS * S_LEN * HEAD_DIM];
__device__ __align__(16) __nv_bfloat16 g_khi[N_HEADS * S_LEN * HEAD_DIM]; // RoPE'd
__device__ __align__(16) __nv_bfloat16 g_klo[N_HEADS * S_LEN * HEAD_DIM];
__device__ __align__(16) __half       g_vhi[N_HEADS * HEAD_DIM * S_LEN];  // [h][d][s] fp16 split
__device__ __align__(16) __half       g_vlo[N_HEADS * HEAD_DIM * S_LEN];
__device__ __align__(16) __nv_bfloat16 g_ahi[S_LEN * D_MODEL];            // attn out
__device__ __align__(16) __nv_bfloat16 g_alo[S_LEN * D_MODEL];

// ---------------- helpers ---------------------------------------------------
__device__ __forceinline__ uint32_t smem_u32(const void* p) {
    uint32_t a;
    asm("{ .reg .u64 t; cvta.to.shared.u64 t, %1; cvt.u32.u64 %0, t; }"
        : "=r"(a) : "l"(p));
    return a;
}

__device__ __forceinline__ void cpa16(uint32_t dst, const void* src) {
    asm volatile("cp.async.cg.shared.global [%0], [%1], 16;"
                 :: "r"(dst), "l"(src));
}
__device__ __forceinline__ void cpa_commit() {
    asm volatile("cp.async.commit_group;");
}
template <int N>
__device__ __forceinline__ void cpa_wait() {
    asm volatile("cp.async.wait_group %0;" :: "n"(N));
}

__device__ __forceinline__ void ldsm_x4(uint32_t* r, uint32_t addr) {
    asm volatile("ldmatrix.sync.aligned.m8n8.x4.shared.b16 {%0,%1,%2,%3}, [%4];"
                 : "=r"(r[0]), "=r"(r[1]), "=r"(r[2]), "=r"(r[3]) : "r"(addr));
}

__device__ __forceinline__ void mma_bf16(float* c, const uint32_t* a,
                                         const uint32_t* b) {
    asm volatile(
        "mma.sync.aligned.m16n8k16.row.col.f32.bf16.bf16.f32 "
        "{%0,%1,%2,%3}, {%4,%5,%6,%7}, {%8,%9}, {%0,%1,%2,%3};"
        : "+f"(c[0]), "+f"(c[1]), "+f"(c[2]), "+f"(c[3])
        : "r"(a[0]), "r"(a[1]), "r"(a[2]), "r"(a[3]), "r"(b[0]), "r"(b[1]));
}

__device__ __forceinline__ void mma_f16(float* c, const uint32_t* a,
                                        const uint32_t* b) {
    asm volatile(
        "mma.sync.aligned.m16n8k16.row.col.f32.f16.f16.f32 "
        "{%0,%1,%2,%3}, {%4,%5,%6,%7}, {%8,%9}, {%0,%1,%2,%3};"
        : "+f"(c[0]), "+f"(c[1]), "+f"(c[2]), "+f"(c[3])
        : "r"(a[0]), "r"(a[1]), "r"(a[2]), "r"(a[3]), "r"(b[0]), "r"(b[1]));
}

__device__ __forceinline__ float ex2f(float x) {
    float y;
    asm("ex2.approx.f32 %0, %1;" : "=f"(y) : "f"(x));
    return y;
}

__device__ __forceinline__ uint32_t pk_bf2(__nv_bfloat16 a, __nv_bfloat16 b) {
    __nv_bfloat162 t = __halves2bfloat162(a, b);
    return *reinterpret_cast<uint32_t*>(&t);
}

__device__ __forceinline__ uint32_t pk_h2(float a, float b) {
    __half2 t = __floats2half2_rn(a, b);
    return *reinterpret_cast<uint32_t*>(&t);
}

__device__ __forceinline__ void split2(float a, float b,
                                       uint32_t& hi, uint32_t& lo) {
    __nv_bfloat16 ha = __float2bfloat16_rn(a);
    __nv_bfloat16 hb = __float2bfloat16_rn(b);
    __nv_bfloat16 la = __float2bfloat16_rn(a - __bfloat162float(ha));
    __nv_bfloat16 lb = __float2bfloat16_rn(b - __bfloat162float(hb));
    hi = pk_bf2(ha, hb);
    lo = pk_bf2(la, lb);
}

__device__ __forceinline__ void store_split1h(__half* hi, __half* lo,
                                              size_t i, float v) {
    __half h = __float2half_rn(v);
    hi[i] = h;
    lo[i] = __float2half_rn(v - __half2float(h));
}

__device__ __forceinline__ uint32_t addrA(uint32_t base, int m0, int k0,
                                          int lane, int ld) {
    int r = m0 + (lane & 15);
    int c = k0 + ((lane >> 4) << 3);
    return base + (uint32_t)(r * ld + c) * 2u;
}
__device__ __forceinline__ uint32_t addrB4(uint32_t base, int n0, int k0,
                                           int lane, int ld) {
    int g = lane >> 3;
    int r = n0 + ((g >> 1) << 3) + (lane & 7);
    int c = k0 + ((g & 1) << 3);
    return base + (uint32_t)(r * ld + c) * 2u;
}

// ---------------- pre-pass: f32 -> split-bf16 (fused, one launch) ----------
#define NX (S_LEN * D_MODEL / 4)
#define NW (D_MODEL * D_MODEL / 4)

__global__ void __launch_bounds__(256) conv_all(
    const float* __restrict__ x, const float* __restrict__ wq,
    const float* __restrict__ wk, const float* __restrict__ wv,
    const float* __restrict__ wo)
{
    int idx = blockIdx.x * 256 + threadIdx.x;
    const float* src;
    __nv_bfloat16 *hi, *lo;
    int off;
    if (idx < NX) {
        src = x; hi = g_xhi; lo = g_xlo; off = idx;
    } else {
        int j = idx - NX;
        int t = j >> 18;
        off = j & (NW - 1);
        src = (t == 0) ? wq : (t == 1) ? wk : (t == 2) ? wv : wo;
        hi = g_whi[t]; lo = g_wlo[t];
    }
    float4 f = ((const float4*)src)[off];
    uint32_t h0, h1, l0, l1;
    split2(f.x, f.y, h0, l0);
    split2(f.z, f.w, h1, l1);
    ((uint2*)hi)[off] = make_uint2(h0, h1);
    ((uint2*)lo)[off] = make_uint2(l0, l1);
}

// ------------------- tensor-core GEMM (cp.async, double-buffered) ----------
#define LDT 40
#define GEMM_BUF (128 * LDT * 2)
#define GEMM_STAGE (4 * GEMM_BUF)
#define GEMM_SMEM (2 * GEMM_STAGE)   // 80 KB -> 2 CTAs/SM

__device__ __forceinline__ void gemm_issue(
    uint32_t sb, uint32_t soff,
    const __nv_bfloat16* pAh, const __nv_bfloat16* pAl,
    const __nv_bfloat16* pBh, const __nv_bfloat16* pBl, int c)
{
    int go = c * 32;
    cpa16(sb + soff,                       pAh + go);
    cpa16(sb + soff + 16,                  pAh + go + 8);
    cpa16(sb + GEMM_BUF + soff,            pAl + go);
    cpa16(sb + GEMM_BUF + soff + 16,       pAl + go + 8);
    cpa16(sb + 2 * GEMM_BUF + soff,        pBh + go);
    cpa16(sb + 2 * GEMM_BUF + soff + 16,   pBh + go + 8);
    cpa16(sb + 3 * GEMM_BUF + soff,        pBl + go);
    cpa16(sb + 3 * GEMM_BUF + soff + 16,   pBl + go + 8);
    cpa_commit();
}

__device__ __forceinline__ void gemm_core(
    uint32_t sb0, uint32_t soff,
    const __nv_bfloat16* pAh, const __nv_bfloat16* pAl,
    const __nv_bfloat16* pBh, const __nv_bfloat16* pBl,
    int m0, int n0, int lane, float acc[4][4][4])
{
    gemm_issue(sb0, soff, pAh, pAl, pBh, pBl, 0);
    gemm_issue(sb0 + GEMM_STAGE, soff, pAh, pAl, pBh, pBl, 1);

    for (int c = 0; c < 32; c++) {
        if (c < 31) cpa_wait<1>(); else cpa_wait<0>();
        __syncthreads();
        uint32_t sb = sb0 + (c & 1) * GEMM_STAGE;
        uint32_t aAhi = sb, aAlo = sb + GEMM_BUF;
        uint32_t aBhi = sb + 2 * GEMM_BUF, aBlo = sb + 3 * GEMM_BUF;
#pragma unroll
        for (int ks = 0; ks < 2; ks++) {
            int k0 = ks * 16;
            uint32_t bh[2][4], bl[2][4];
#pragma unroll
            for (int p = 0; p < 2; p++) {
                ldsm_x4(bh[p], addrB4(aBhi, n0 + p * 16, k0, lane, LDT));
                ldsm_x4(bl[p], addrB4(aBlo, n0 + p * 16, k0, lane, LDT));
            }
#pragma unroll
            for (int mt = 0; mt < 4; mt++) {
                uint32_t ah[4], al[4];
                ldsm_x4(ah, addrA(aAhi, m0 + mt * 16, k0, lane, LDT));
                ldsm_x4(al, addrA(aAlo, m0 + mt * 16, k0, lane, LDT));
#pragma unroll
                for (int nt = 0; nt < 4; nt++) {
                    const uint32_t* pbh = &bh[nt >> 1][(nt & 1) * 2];
                    const uint32_t* pbl = &bl[nt >> 1][(nt & 1) * 2];
                    mma_bf16(acc[mt][nt], ah, pbh);
                    mma_bf16(acc[mt][nt], ah, pbl);
                    mma_bf16(acc[mt][nt], al, pbh);
                }
            }
        }
        __syncthreads();
        if (c + 2 < 32)
            gemm_issue(sb0 + (c & 1) * GEMM_STAGE, soff, pAh, pAl, pBh, pBl, c + 2);
    }
}

// QKV fused: blockIdx.z = mode (0=Q,1=K,2=V)
__global__ void __launch_bounds__(256, 2) gemm_qkv(
    const float* __restrict__ bq, const float* __restrict__ bk,
    const float* __restrict__ bv, const float* __restrict__ fcos,
    const float* __restrict__ fsin)
{
    extern __shared__ __align__(16) char dsm[];
    uint32_t sb0 = smem_u32(dsm);

    int mode = blockIdx.z;
    const float* bias = (mode == 0) ? bq : (mode == 1) ? bk : bv;

    int tid = threadIdx.x, wid = tid >> 5, lane = tid & 31;
    int m0 = (wid >> 2) * 64, n0 = (wid & 3) * 32;
    int bm = blockIdx.y * 128, bn = blockIdx.x * 128;

    int lrow = tid >> 1, lks = (tid & 1) * 16;
    uint32_t soff = (uint32_t)(lrow * LDT + lks) * 2u;
    const __nv_bfloat16* pAh = g_xhi + (size_t)(bm + lrow) * D_MODEL + lks;
    const __nv_bfloat16* pAl = g_xlo + (size_t)(bm + lrow) * D_MODEL + lks;
    const __nv_bfloat16* pBh = g_whi[mode] + (size_t)(bn + lrow) * D_MODEL + lks;
    const __nv_bfloat16* pBl = g_wlo[mode] + (size_t)(bn + lrow) * D_MODEL + lks;

    float acc[4][4][4];
#pragma unroll
    for (int i = 0; i < 4; i++)
#pragma unroll
        for (int j = 0; j < 4; j++)
#pragma unroll
            for (int e = 0; e < 4; e++) acc[i][j][e] = 0.f;

    gemm_core(sb0, soff, pAh, pAl, pBh, pBl, m0, n0, lane, acc);

    int rq = lane >> 2, cq = (lane & 3) * 2;
    // Q pre-scale folds softmax 1/sqrt(64) AND log2(e) for ex2-based softmax
    float scale = (mode == 0) ? (0.125f * 1.4426950408889634f) : 1.f;
#pragma unroll
    for (int mt = 0; mt < 4; mt++) {
#pragma unroll
        for (int nt = 0; nt < 4; nt++) {
            int r0 = bm + m0 + mt * 16 + rq;
            int cg = bn + n0 + nt * 8 + cq;
            float b0 = bias[cg], b1 = bias[cg + 1];
            float v00 = acc[mt][nt][0] + b0, v01 = acc[mt][nt][1] + b1;
            float v10 = acc[mt][nt][2] + b0, v11 = acc[mt][nt][3] + b1;
            int h = cg >> 6, d = cg & 63;
            if (mode == 2) {
                size_t o0 = ((size_t)h * HEAD_DIM + d) * S_LEN;
                store_split1h(g_vhi, g_vlo, o0 + r0, v00);
                store_split1h(g_vhi, g_vlo, o0 + r0 + 8, v10);
                store_split1h(g_vhi, g_vlo, o0 + S_LEN + r0, v01);
                store_split1h(g_vhi, g_vlo, o0 + S_LEN + r0 + 8, v11);
            } else {
                float c0 = fcos[(size_t)r0 * HALF_DIM + (d >> 1)];
                float s0 = fsin[(size_t)r0 * HALF_DIM + (d >> 1)];
                float c1 = fcos[(size_t)(r0 + 8) * HALF_DIM + (d >> 1)];
                float s1 = fsin[(size_t)(r0 + 8) * HALF_DIM + (d >> 1)];
                float q00 = (v00 * c0 - v01 * s0) * scale;
                float q01 = (v00 * s0 + v01 * c0) * scale;
                float q10 = (v10 * c1 - v11 * s1) * scale;
                float q11 = (v10 * s1 + v11 * c1) * scale;
                __nv_bfloat16* dh = (mode == 0) ? g_qhi : g_khi;
                __nv_bfloat16* dl = (mode == 0) ? g_qlo : g_klo;
                size_t o0 = ((size_t)h * S_LEN + r0) * HEAD_DIM + d;
                uint32_t hh, ll;
                split2(q00, q01, hh, ll);
                *(uint32_t*)(dh + o0) = hh;
                *(uint32_t*)(dl + o0) = ll;
                split2(q10, q11, hh, ll);
                *(uint32_t*)(dh + o0 + 8 * HEAD_DIM) = hh;
                *(uint32_t*)(dl + o0 + 8 * HEAD_DIM) = ll;
            }
        }
    }
}

__global__ void __launch_bounds__(256, 2) gemm_o(
    const float* __restrict__ bias, float* __restrict__ oout)
{
    extern __shared__ __align__(16) char dsm[];
    uint32_t sb0 = smem_u32(dsm);

    int tid = threadIdx.x, wid = tid >> 5, lane = tid & 31;
    int m0 = (wid >> 2) * 64, n0 = (wid & 3) * 32;
    int bm = blockIdx.y * 128, bn = blockIdx.x * 128;

    int lrow = tid >> 1, lks = (tid & 1) * 16;
    uint32_t soff = (uint32_t)(lrow * LDT + lks) * 2u;
    const __nv_bfloat16* pAh = g_ahi + (size_t)(bm + lrow) * D_MODEL + lks;
    const __nv_bfloat16* pAl = g_alo + (size_t)(bm + lrow) * D_MODEL + lks;
    const __nv_bfloat16* pBh = g_whi[3] + (size_t)(bn + lrow) * D_MODEL + lks;
    const __nv_bfloat16* pBl = g_wlo[3] + (size_t)(bn + lrow) * D_MODEL + lks;

    float acc[4][4][4];
#pragma unroll
    for (int i = 0; i < 4; i++)
#pragma unroll
        for (int j = 0; j < 4; j++)
#pragma unroll
            for (int e = 0; e < 4; e++) acc[i][j][e] = 0.f;

    gemm_core(sb0, soff, pAh, pAl, pBh, pBl, m0, n0, lane, acc);

    int rq = lane >> 2, cq = (lane & 3) * 2;
#pragma unroll
    for (int mt = 0; mt < 4; mt++) {
#pragma unroll
        for (int nt = 0; nt < 4; nt++) {
            int r0 = bm + m0 + mt * 16 + rq;
            int cg = bn + n0 + nt * 8 + cq;
            float b0 = bias[cg], b1 = bias[cg + 1];
            *(float2*)(oout + (size_t)r0 * D_MODEL + cg) =
                make_float2(acc[mt][nt][0] + b0, acc[mt][nt][1] + b1);
            *(float2*)(oout + (size_t)(r0 + 8) * D_MODEL + cg) =
                make_float2(acc[mt][nt][2] + b0, acc[mt][nt][3] + b1);
        }
    }
}

// ------------- flash attention: 128 thr, 4 warps x 32 q-rows ---------------
// 128q x 128k tile. Each warp owns 2 m16 tiles -> every K/V ldmatrix feeds
// 2x MMAs (total CTA LDSM traffic -44% vs 8-warp x 16-row layout).
#define LDQK 72
#define LDV 136
#define QBUF (128 * LDQK * 2)
#define VBUF (64 * LDV * 2)
#define OFF_K (2 * QBUF)
#define OFF_V (4 * QBUF)
#define ATTN_SMEM (4 * QBUF + 2 * VBUF)  // 108544 -> 2 CTAs/SM

__global__ void __launch_bounds__(128, 2) attn_k()
{
    extern __shared__ __align__(16) char smraw[];
    uint32_t sb = smem_u32(smraw);
    uint32_t aQhi = sb, aQlo = sb + QBUF;
    uint32_t aKhi = sb + OFF_K, aKlo = sb + OFF_K + QBUF;
    uint32_t aVhi = sb + OFF_V, aVlo = sb + OFF_V + VBUF;

    int qb = gridDim.x - 1 - blockIdx.x;
    int h = blockIdx.y;
    int tid = threadIdx.x, wid = tid >> 5, lane = tid & 31;
    int m0 = wid * 32;                    // warp's 32 query rows (2 m-tiles)
    int rq = lane >> 2, cq = (lane & 3) * 2;

    // load Q tile (blocking, once)
    {
        const __nv_bfloat16* qhg = g_qhi + ((size_t)h * S_LEN + qb * 128) * HEAD_DIM;
        const __nv_bfloat16* qlg = g_qlo + ((size_t)h * S_LEN + qb * 128) * HEAD_DIM;
#pragma unroll
        for (int it = 0; it < 8; it++) {
            int idx4 = tid + it * 128;
            int row = idx4 >> 3, col = (idx4 & 7) << 3;
            uint32_t off = (uint32_t)(row * LDQK + col) * 2u;
            cpa16(aQhi + off, qhg + (size_t)row * HEAD_DIM + col);
            cpa16(aQlo + off, qlg + (size_t)row * HEAD_DIM + col);
        }
        cpa_commit();
    }

    float m[2][2], l[2][2], o[2][8][4];
#pragma unroll
    for (int mt = 0; mt < 2; mt++) {
        m[mt][0] = m[mt][1] = -1e30f;
        l[mt][0] = l[mt][1] = 0.f;
#pragma unroll
        for (int dt = 0; dt < 8; dt++)
#pragma unroll
            for (int e = 0; e < 4; e++) o[mt][dt][e] = 0.f;
    }

    const __nv_bfloat16* khg0 = g_khi + (size_t)h * S_LEN * HEAD_DIM;
    const __nv_bfloat16* klg0 = g_klo + (size_t)h * S_LEN * HEAD_DIM;
    const __half* vhg0 = g_vhi + (size_t)h * HEAD_DIM * S_LEN;
    const __half* vlg0 = g_vlo + (size_t)h * HEAD_DIM * S_LEN;

    for (int kb = 0; kb <= qb; kb++) {
        __syncthreads();
        // ---- load K/V tile (single stage; co-resident CTA hides latency)
        {
            const __nv_bfloat16* khg = khg0 + (size_t)(kb * 128) * HEAD_DIM;
            const __nv_bfloat16* klg = klg0 + (size_t)(kb * 128) * HEAD_DIM;
            const __half* vhg = vhg0 + kb * 128;
            const __half* vlg = vlg0 + kb * 128;
#pragma unroll
            for (int it = 0; it < 8; it++) {
                int idx4 = tid + it * 128;
                int row = idx4 >> 3, col = (idx4 & 7) << 3;
                uint32_t koff = (uint32_t)(row * LDQK + col) * 2u;
                cpa16(aKhi + koff, khg + (size_t)row * HEAD_DIM + col);
                cpa16(aKlo + koff, klg + (size_t)row * HEAD_DIM + col);
                int vrow = idx4 >> 4, vcol = (idx4 & 15) << 3;
                uint32_t voff = (uint32_t)(vrow * LDV + vcol) * 2u;
                cpa16(aVhi + voff, vhg + (size_t)vrow * S_LEN + vcol);
                cpa16(aVlo + voff, vlg + (size_t)vrow * S_LEN + vcol);
            }
            cpa_commit();
            cpa_wait<0>();
        }
        __syncthreads();

        // ---- two 64-column halves
#pragma unroll
        for (int half = 0; half < 2; half++) {
            int nb = half * 64;

            float sc[2][8][4];
#pragma unroll
            for (int mt = 0; mt < 2; mt++)
#pragma unroll
                for (int nt = 0; nt < 8; nt++)
#pragma unroll
                    for (int e = 0; e < 4; e++) sc[mt][nt][e] = 0.f;

#pragma unroll
            for (int ks = 0; ks < 4; ks++) {
                int k0 = ks * 16;
                uint32_t ah[2][4], al[2][4];
                ldsm_x4(ah[0], addrA(aQhi, m0, k0, lane, LDQK));
                ldsm_x4(al[0], addrA(aQlo, m0, k0, lane, LDQK));
                ldsm_x4(ah[1], addrA(aQhi, m0 + 16, k0, lane, LDQK));
                ldsm_x4(al[1], addrA(aQlo, m0 + 16, k0, lane, LDQK));
#pragma unroll
                for (int pg = 0; pg < 2; pg++) {
                    int p0 = nb + pg * 32;
                    uint32_t bh0[4], bl0[4], bh1[4], bl1[4];
                    ldsm_x4(bh0, addrB4(aKhi, p0, k0, lane, LDQK));
                    ldsm_x4(bl0, addrB4(aKlo, p0, k0, lane, LDQK));
                    ldsm_x4(bh1, addrB4(aKhi, p0 + 16, k0, lane, LDQK));
                    ldsm_x4(bl1, addrB4(aKlo, p0 + 16, k0, lane, LDQK));
#pragma unroll
                    for (int mt = 0; mt < 2; mt++) {
                        float* s0 = sc[mt][4 * pg + 0];
                        float* s1 = sc[mt][4 * pg + 1];
                        float* s2 = sc[mt][4 * pg + 2];
                        float* s3 = sc[mt][4 * pg + 3];
                        mma_bf16(s0, ah[mt], bh0); mma_bf16(s1, ah[mt], bh0 + 2);
                        mma_bf16(s2, ah[mt], bh1); mma_bf16(s3, ah[mt], bh1 + 2);
                        mma_bf16(s0, ah[mt], bl0); mma_bf16(s1, ah[mt], bl0 + 2);
                        mma_bf16(s2, ah[mt], bl1); mma_bf16(s3, ah[mt], bl1 + 2);
                        mma_bf16(s0, al[mt], bh0); mma_bf16(s1, al[mt], bh0 + 2);
                        mma_bf16(s2, al[mt], bh1); mma_bf16(s3, al[mt], bh1 + 2);
                    }
                }
            }

            // ---- causal mask on diagonal tile
            if (kb == qb) {
#pragma unroll
                for (int mt = 0; mt < 2; mt++)
#pragma unroll
                    for (int nt = 0; nt < 8; nt++)
#pragma unroll
                        for (int e = 0; e < 4; e++) {
                            int qi = m0 + mt * 16 + rq + ((e >> 1) << 3);
                            int kj = nb + nt * 8 + cq + (e & 1);
                            if (kj > qi) sc[mt][nt][e] = -1e30f;
                        }
            }

            // ---- online softmax (log2 domain, ex2)
#pragma unroll
            for (int mt = 0; mt < 2; mt++)
#pragma unroll
                for (int r = 0; r < 2; r++) {
                    float mx = -1e30f;
#pragma unroll
                    for (int nt = 0; nt < 8; nt++)
                        mx = fmaxf(mx, fmaxf(sc[mt][nt][2 * r],
                                             sc[mt][nt][2 * r + 1]));
                    mx = fmaxf(mx, __shfl_xor_sync(0xffffffffu, mx, 1));
                    mx = fmaxf(mx, __shfl_xor_sync(0xffffffffu, mx, 2));
                    float mn = fmaxf(m[mt][r], mx);
                    float corr = ex2f(m[mt][r] - mn);
                    m[mt][r] = mn;
                    float rs = 0.f;
#pragma unroll
                    for (int nt = 0; nt < 8; nt++) {
                        float p0 = ex2f(sc[mt][nt][2 * r] - mn);
                        float p1 = ex2f(sc[mt][nt][2 * r + 1] - mn);
                        sc[mt][nt][2 * r] = p0;
                        sc[mt][nt][2 * r + 1] = p1;
                        rs += p0 + p1;
                    }
                    l[mt][r] = l[mt][r] * corr + rs;
#pragma unroll
                    for (int dt = 0; dt < 8; dt++) {
                        o[mt][dt][2 * r] *= corr;
                        o[mt][dt][2 * r + 1] *= corr;
                    }
                }

            // ---- PV: single-fp16 P, 2-term fp16 V
#pragma unroll
            for (int kp = 0; kp < 4; kp++) {
                uint32_t pa[2][4];
#pragma unroll
                for (int mt = 0; mt < 2; mt++) {
                    pa[mt][0] = pk_h2(sc[mt][2 * kp][0], sc[mt][2 * kp][1]);
                    pa[mt][1] = pk_h2(sc[mt][2 * kp][2], sc[mt][2 * kp][3]);
                    pa[mt][2] = pk_h2(sc[mt][2 * kp + 1][0], sc[mt][2 * kp + 1][1]);
                    pa[mt][3] = pk_h2(sc[mt][2 * kp + 1][2], sc[mt][2 * kp + 1][3]);
                }
                int k0 = nb + kp * 16;
#pragma unroll
                for (int pg = 0; pg < 2; pg++) {
                    int p0 = pg * 32;
                    uint32_t vh0[4], vl0[4], vh1[4], vl1[4];
                    ldsm_x4(vh0, addrB4(aVhi, p0, k0, lane, LDV));
                    ldsm_x4(vl0, addrB4(aVlo, p0, k0, lane, LDV));
                    ldsm_x4(vh1, addrB4(aVhi, p0 + 16, k0, lane, LDV));
                    ldsm_x4(vl1, addrB4(aVlo, p0 + 16, k0, lane, LDV));
#pragma unroll
                    for (int mt = 0; mt < 2; mt++) {
                        float* o0 = o[mt][4 * pg + 0];
                        float* o1 = o[mt][4 * pg + 1];
                        float* o2 = o[mt][4 * pg + 2];
                        float* o3 = o[mt][4 * pg + 3];
                        mma_f16(o0, pa[mt], vh0); mma_f16(o1, pa[mt], vh0 + 2);
                        mma_f16(o2, pa[mt], vh1); mma_f16(o3, pa[mt], vh1 + 2);
                        mma_f16(o0, pa[mt], vl0); mma_f16(o1, pa[mt], vl0 + 2);
                        mma_f16(o2, pa[mt], vl1); mma_f16(o3, pa[mt], vl1 + 2);
                    }
                }
            }
        }
    }

    // ---- finalize
#pragma unroll
    for (int mt = 0; mt < 2; mt++) {
#pragma unroll
        for (int r = 0; r < 2; r++) {
            l[mt][r] += __shfl_xor_sync(0xffffffffu, l[mt][r], 1);
            l[mt][r] += __shfl_xor_sync(0xffffffffu, l[mt][r], 2);
        }
        float inv0 = 1.f / l[mt][0], inv1 = 1.f / l[mt][1];
        int r0 = qb * 128 + m0 + mt * 16 + rq;
        size_t ob = (size_t)r0 * D_MODEL + h * HEAD_DIM + cq;
#pragma unroll
        for (int dt = 0; dt < 8; dt++) {
            uint32_t hh, ll;
            split2(o[mt][dt][0] * inv0, o[mt][dt][1] * inv0, hh, ll);
            *(uint32_t*)(g_ahi + ob + dt * 8) = hh;
            *(uint32_t*)(g_alo + ob + dt * 8) = ll;
            split2(o[mt][dt][2] * inv1, o[mt][dt][3] * inv1, hh, ll);
            *(uint32_t*)(g_ahi + ob + 8 * D_MODEL + dt * 8) = hh;
            *(uint32_t*)(g_alo + ob + 8 * D_MODEL + dt * 8) = ll;
        }
    }
}

extern "C" void kernel_launch(void* const* d_in, const int* in_sizes, int n_in,
                              void* d_out, int out_size)
{
    const float* x    = (const float*)d_in[0];
    const float* fcos = (const float*)d_in[2];
    const float* fsin = (const float*)d_in[3];
    const float* wq  = (const float*)d_in[5];
    const float* wqb = (const float*)d_in[6];
    const float* wk  = (const float*)d_in[7];
    const float* wkb = (const float*)d_in[8];
    const float* wv  = (const float*)d_in[9];
    const float* wvb = (const float*)d_in[10];
    const float* wo  = (const float*)d_in[11];
    const float* wob = (const float*)d_in[12];
    float* out = (float*)d_out;

    static bool attr_set = false;
    if (!attr_set) {
        cudaFuncSetAttribute(attn_k,
                             cudaFuncAttributeMaxDynamicSharedMemorySize,
                             ATTN_SMEM);
        cudaFuncSetAttribute(gemm_qkv,
                             cudaFuncAttributeMaxDynamicSharedMemorySize,
                             GEMM_SMEM);
        cudaFuncSetAttribute(gemm_o,
                             cudaFuncAttributeMaxDynamicSharedMemorySize,
                             GEMM_SMEM);
        attr_set = true;
    }

    conv_all<<<(NX + 4 * NW) / 256, 256>>>(x, wq, wk, wv, wo);
    gemm_qkv<<<dim3(D_MODEL / 128, S_LEN / 128, 3), 256, GEMM_SMEM>>>(
        wqb, wkb, wvb, fcos, fsin);
    attn_k<<<dim3(S_LEN / 128, N_HEADS), 128, ATTN_SMEM>>>();
    gemm_o<<<dim3(D_MODEL / 128, S_LEN / 128), 256, GEMM_SMEM>>>(wob, out);
}

// round 13
// speedup vs baseline: 1.3679x; 1.1821x over previous
#include <cuda_runtime.h>
#include <cuda_fp16.h>
#include <cstdint>

#define S_LEN 4096
#define D_MODEL 1024
#define N_HEADS 16
#define HEAD_DIM 64
#define HALF_DIM 32

// ---------------- fp16-split scratch (device globals) ----------------------
__device__ __align__(16) __half g_xhi[S_LEN * D_MODEL];
__device__ __align__(16) __half g_xlo[S_LEN * D_MODEL];
__device__ __align__(16) __half g_whi[4][D_MODEL * D_MODEL];
__device__ __align__(16) __half g_wlo[4][D_MODEL * D_MODEL];
__device__ __align__(16) __half g_qhi[N_HEADS * S_LEN * HEAD_DIM]; // RoPE'd, *log2e/8
__device__ __align__(16) __half g_qlo[N_HEADS * S_LEN * HEAD_DIM];
__device__ __align__(16) __half g_khi[N_HEADS * S_LEN * HEAD_DIM]; // RoPE'd
__device__ __align__(16) __half g_klo[N_HEADS * S_LEN * HEAD_DIM];
__device__ __align__(16) __half g_vhi[N_HEADS * HEAD_DIM * S_LEN]; // [h][d][s]
__device__ __align__(16) __half g_vlo[N_HEADS * HEAD_DIM * S_LEN];
__device__ __align__(16) __half g_ahi[S_LEN * D_MODEL];            // attn out
__device__ __align__(16) __half g_alo[S_LEN * D_MODEL];

// ---------------- helpers ---------------------------------------------------
__device__ __forceinline__ uint32_t smem_u32(const void* p) {
    uint32_t a;
    asm("{ .reg .u64 t; cvta.to.shared.u64 t, %1; cvt.u32.u64 %0, t; }"
        : "=r"(a) : "l"(p));
    return a;
}

__device__ __forceinline__ void cpa16(uint32_t dst, const void* src) {
    asm volatile("cp.async.cg.shared.global [%0], [%1], 16;"
                 :: "r"(dst), "l"(src));
}
__device__ __forceinline__ void cpa_commit() {
    asm volatile("cp.async.commit_group;");
}
template <int N>
__device__ __forceinline__ void cpa_wait() {
    asm volatile("cp.async.wait_group %0;" :: "n"(N));
}

__device__ __forceinline__ void ldsm_x4(uint32_t* r, uint32_t addr) {
    asm volatile("ldmatrix.sync.aligned.m8n8.x4.shared.b16 {%0,%1,%2,%3}, [%4];"
                 : "=r"(r[0]), "=r"(r[1]), "=r"(r[2]), "=r"(r[3]) : "r"(addr));
}

__device__ __forceinline__ void mma_f16(float* c, const uint32_t* a,
                                        const uint32_t* b) {
    asm volatile(
        "mma.sync.aligned.m16n8k16.row.col.f32.f16.f16.f32 "
        "{%0,%1,%2,%3}, {%4,%5,%6,%7}, {%8,%9}, {%0,%1,%2,%3};"
        : "+f"(c[0]), "+f"(c[1]), "+f"(c[2]), "+f"(c[3])
        : "r"(a[0]), "r"(a[1]), "r"(a[2]), "r"(a[3]), "r"(b[0]), "r"(b[1]));
}

__device__ __forceinline__ float ex2f(float x) {
    float y;
    asm("ex2.approx.f32 %0, %1;" : "=f"(y) : "f"(x));
    return y;
}

__device__ __forceinline__ uint32_t pk_h2(float a, float b) {
    __half2 t = __floats2half2_rn(a, b);
    return *reinterpret_cast<uint32_t*>(&t);
}

// fp16 hi/lo split of a float pair
__device__ __forceinline__ void split2h(float a, float b,
                                        uint32_t& hi, uint32_t& lo) {
    __half ha = __float2half_rn(a);
    __half hb = __float2half_rn(b);
    __half la = __float2half_rn(a - __half2float(ha));
    __half lb = __float2half_rn(b - __half2float(hb));
    __half2 th = __halves2half2(ha, hb);
    __half2 tl = __halves2half2(la, lb);
    hi = *reinterpret_cast<uint32_t*>(&th);
    lo = *reinterpret_cast<uint32_t*>(&tl);
}

__device__ __forceinline__ void store_split1h(__half* hi, __half* lo,
                                              size_t i, float v) {
    __half h = __float2half_rn(v);
    hi[i] = h;
    lo[i] = __float2half_rn(v - __half2float(h));
}

__device__ __forceinline__ uint32_t addrA(uint32_t base, int m0, int k0,
                                          int lane, int ld) {
    int r = m0 + (lane & 15);
    int c = k0 + ((lane >> 4) << 3);
    return base + (uint32_t)(r * ld + c) * 2u;
}
__device__ __forceinline__ uint32_t addrB4(uint32_t base, int n0, int k0,
                                           int lane, int ld) {
    int g = lane >> 3;
    int r = n0 + ((g >> 1) << 3) + (lane & 7);
    int c = k0 + ((g & 1) << 3);
    return base + (uint32_t)(r * ld + c) * 2u;
}

// ---------------- pre-pass: f32 -> fp16 split (fused, one launch) -----------
#define NX (S_LEN * D_MODEL / 4)
#define NW (D_MODEL * D_MODEL / 4)

__global__ void __launch_bounds__(256) conv_all(
    const float* __restrict__ x, const float* __restrict__ wq,
    const float* __restrict__ wk, const float* __restrict__ wv,
    const float* __restrict__ wo)
{
    int idx = blockIdx.x * 256 + threadIdx.x;
    const float* src;
    __half *hi, *lo;
    int off;
    if (idx < NX) {
        src = x; hi = g_xhi; lo = g_xlo; off = idx;
    } else {
        int j = idx - NX;
        int t = j >> 18;
        off = j & (NW - 1);
        src = (t == 0) ? wq : (t == 1) ? wk : (t == 2) ? wv : wo;
        hi = g_whi[t]; lo = g_wlo[t];
    }
    float4 f = ((const float4*)src)[off];
    uint32_t h0, h1, l0, l1;
    split2h(f.x, f.y, h0, l0);
    split2h(f.z, f.w, h1, l1);
    ((uint2*)hi)[off] = make_uint2(h0, h1);
    ((uint2*)lo)[off] = make_uint2(l0, l1);
}

// ------------------- tensor-core GEMM (cp.async, double-buffered) ----------
// TERMS=3: Ah*Bh + Ah*Bl + Al*Bh (Q/K).  TERMS=2: Ah*Bh + Al*Bh (V/O).
#define LDT 40
#define GEMM_BUF (128 * LDT * 2)
#define GEMM_STAGE (4 * GEMM_BUF)
#define GEMM_SMEM (2 * GEMM_STAGE)   // 80 KB -> 2 CTAs/SM

template <int TERMS>
__device__ __forceinline__ void gemm_issue(
    uint32_t sb, uint32_t soff,
    const __half* pAh, const __half* pAl,
    const __half* pBh, const __half* pBl, int c)
{
    int go = c * 32;
    cpa16(sb + soff,                       pAh + go);
    cpa16(sb + soff + 16,                  pAh + go + 8);
    cpa16(sb + GEMM_BUF + soff,            pAl + go);
    cpa16(sb + GEMM_BUF + soff + 16,       pAl + go + 8);
    cpa16(sb + 2 * GEMM_BUF + soff,        pBh + go);
    cpa16(sb + 2 * GEMM_BUF + soff + 16,   pBh + go + 8);
    if (TERMS == 3) {
        cpa16(sb + 3 * GEMM_BUF + soff,      pBl + go);
        cpa16(sb + 3 * GEMM_BUF + soff + 16, pBl + go + 8);
    }
    cpa_commit();
}

template <int TERMS>
__device__ __forceinline__ void gemm_core(
    uint32_t sb0, uint32_t soff,
    const __half* pAh, const __half* pAl,
    const __half* pBh, const __half* pBl,
    int m0, int n0, int lane, float acc[4][4][4])
{
    gemm_issue<TERMS>(sb0, soff, pAh, pAl, pBh, pBl, 0);
    gemm_issue<TERMS>(sb0 + GEMM_STAGE, soff, pAh, pAl, pBh, pBl, 1);

    for (int c = 0; c < 32; c++) {
        if (c < 31) cpa_wait<1>(); else cpa_wait<0>();
        __syncthreads();
        uint32_t sb = sb0 + (c & 1) * GEMM_STAGE;
        uint32_t aAhi = sb, aAlo = sb + GEMM_BUF;
        uint32_t aBhi = sb + 2 * GEMM_BUF, aBlo = sb + 3 * GEMM_BUF;
#pragma unroll
        for (int ks = 0; ks < 2; ks++) {
            int k0 = ks * 16;
            uint32_t bh[2][4], bl[2][4];
#pragma unroll
            for (int p = 0; p < 2; p++) {
                ldsm_x4(bh[p], addrB4(aBhi, n0 + p * 16, k0, lane, LDT));
                if (TERMS == 3)
                    ldsm_x4(bl[p], addrB4(aBlo, n0 + p * 16, k0, lane, LDT));
            }
#pragma unroll
            for (int mt = 0; mt < 4; mt++) {
                uint32_t ah[4], al[4];
                ldsm_x4(ah, addrA(aAhi, m0 + mt * 16, k0, lane, LDT));
                ldsm_x4(al, addrA(aAlo, m0 + mt * 16, k0, lane, LDT));
#pragma unroll
                for (int nt = 0; nt < 4; nt++) {
                    const uint32_t* pbh = &bh[nt >> 1][(nt & 1) * 2];
                    mma_f16(acc[mt][nt], ah, pbh);
                    if (TERMS == 3) {
                        const uint32_t* pbl = &bl[nt >> 1][(nt & 1) * 2];
                        mma_f16(acc[mt][nt], ah, pbl);
                    }
                    mma_f16(acc[mt][nt], al, pbh);
                }
            }
        }
        __syncthreads();
        if (c + 2 < 32)
            gemm_issue<TERMS>(sb0 + (c & 1) * GEMM_STAGE, soff,
                              pAh, pAl, pBh, pBl, c + 2);
    }
}

// QKV fused: blockIdx.z = mode (0=Q,1=K,2=V)
__global__ void __launch_bounds__(256, 2) gemm_qkv(
    const float* __restrict__ bq, const float* __restrict__ bk,
    const float* __restrict__ bv, const float* __restrict__ fcos,
    const float* __restrict__ fsin)
{
    extern __shared__ __align__(16) char dsm[];
    uint32_t sb0 = smem_u32(dsm);

    int mode = blockIdx.z;
    const float* bias = (mode == 0) ? bq : (mode == 1) ? bk : bv;

    int tid = threadIdx.x, wid = tid >> 5, lane = tid & 31;
    int m0 = (wid >> 2) * 64, n0 = (wid & 3) * 32;
    int bm = blockIdx.y * 128, bn = blockIdx.x * 128;

    int lrow = tid >> 1, lks = (tid & 1) * 16;
    uint32_t soff = (uint32_t)(lrow * LDT + lks) * 2u;
    const __half* pAh = g_xhi + (size_t)(bm + lrow) * D_MODEL + lks;
    const __half* pAl = g_xlo + (size_t)(bm + lrow) * D_MODEL + lks;
    const __half* pBh = g_whi[mode] + (size_t)(bn + lrow) * D_MODEL + lks;
    const __half* pBl = g_wlo[mode] + (size_t)(bn + lrow) * D_MODEL + lks;

    float acc[4][4][4];
#pragma unroll
    for (int i = 0; i < 4; i++)
#pragma unroll
        for (int j = 0; j < 4; j++)
#pragma unroll
            for (int e = 0; e < 4; e++) acc[i][j][e] = 0.f;

    if (mode == 2)
        gemm_core<2>(sb0, soff, pAh, pAl, pBh, pBl, m0, n0, lane, acc);
    else
        gemm_core<3>(sb0, soff, pAh, pAl, pBh, pBl, m0, n0, lane, acc);

    int rq = lane >> 2, cq = (lane & 3) * 2;
    // Q pre-scale folds softmax 1/sqrt(64) AND log2(e) for ex2-based softmax
    float scale = (mode == 0) ? (0.125f * 1.4426950408889634f) : 1.f;
#pragma unroll
    for (int mt = 0; mt < 4; mt++) {
#pragma unroll
        for (int nt = 0; nt < 4; nt++) {
            int r0 = bm + m0 + mt * 16 + rq;
            int cg = bn + n0 + nt * 8 + cq;
            float b0 = bias[cg], b1 = bias[cg + 1];
            float v00 = acc[mt][nt][0] + b0, v01 = acc[mt][nt][1] + b1;
            float v10 = acc[mt][nt][2] + b0, v11 = acc[mt][nt][3] + b1;
            int h = cg >> 6, d = cg & 63;
            if (mode == 2) {
                size_t o0 = ((size_t)h * HEAD_DIM + d) * S_LEN;
                store_split1h(g_vhi, g_vlo, o0 + r0, v00);
                store_split1h(g_vhi, g_vlo, o0 + r0 + 8, v10);
                store_split1h(g_vhi, g_vlo, o0 + S_LEN + r0, v01);
                store_split1h(g_vhi, g_vlo, o0 + S_LEN + r0 + 8, v11);
            } else {
                float c0 = fcos[(size_t)r0 * HALF_DIM + (d >> 1)];
                float s0 = fsin[(size_t)r0 * HALF_DIM + (d >> 1)];
                float c1 = fcos[(size_t)(r0 + 8) * HALF_DIM + (d >> 1)];
                float s1 = fsin[(size_t)(r0 + 8) * HALF_DIM + (d >> 1)];
                float q00 = (v00 * c0 - v01 * s0) * scale;
                float q01 = (v00 * s0 + v01 * c0) * scale;
                float q10 = (v10 * c1 - v11 * s1) * scale;
                float q11 = (v10 * s1 + v11 * c1) * scale;
                __half* dh = (mode == 0) ? g_qhi : g_khi;
                __half* dl = (mode == 0) ? g_qlo : g_klo;
                size_t o0 = ((size_t)h * S_LEN + r0) * HEAD_DIM + d;
                uint32_t hh, ll;
                split2h(q00, q01, hh, ll);
                *(uint32_t*)(dh + o0) = hh;
                *(uint32_t*)(dl + o0) = ll;
                split2h(q10, q11, hh, ll);
                *(uint32_t*)(dh + o0 + 8 * HEAD_DIM) = hh;
                *(uint32_t*)(dl + o0 + 8 * HEAD_DIM) = ll;
            }
        }
    }
}

__global__ void __launch_bounds__(256, 2) gemm_o(
    const float* __restrict__ bias, float* __restrict__ oout)
{
    extern __shared__ __align__(16) char dsm[];
    uint32_t sb0 = smem_u32(dsm);

    int tid = threadIdx.x, wid = tid >> 5, lane = tid & 31;
    int m0 = (wid >> 2) * 64, n0 = (wid & 3) * 32;
    int bm = blockIdx.y * 128, bn = blockIdx.x * 128;

    int lrow = tid >> 1, lks = (tid & 1) * 16;
    uint32_t soff = (uint32_t)(lrow * LDT + lks) * 2u;
    const __half* pAh = g_ahi + (size_t)(bm + lrow) * D_MODEL + lks;
    const __half* pAl = g_alo + (size_t)(bm + lrow) * D_MODEL + lks;
    const __half* pBh = g_whi[3] + (size_t)(bn + lrow) * D_MODEL + lks;
    const __half* pBl = g_wlo[3] + (size_t)(bn + lrow) * D_MODEL + lks;

    float acc[4][4][4];
#pragma unroll
    for (int i = 0; i < 4; i++)
#pragma unroll
        for (int j = 0; j < 4; j++)
#pragma unroll
            for (int e = 0; e < 4; e++) acc[i][j][e] = 0.f;

    gemm_core<2>(sb0, soff, pAh, pAl, pBh, pBl, m0, n0, lane, acc);

    int rq = lane >> 2, cq = (lane & 3) * 2;
#pragma unroll
    for (int mt = 0; mt < 4; mt++) {
#pragma unroll
        for (int nt = 0; nt < 4; nt++) {
            int r0 = bm + m0 + mt * 16 + rq;
            int cg = bn + n0 + nt * 8 + cq;
            float b0 = bias[cg], b1 = bias[cg + 1];
            *(float2*)(oout + (size_t)r0 * D_MODEL + cg) =
                make_float2(acc[mt][nt][0] + b0, acc[mt][nt][1] + b1);
            *(float2*)(oout + (size_t)(r0 + 8) * D_MODEL + cg) =
                make_float2(acc[mt][nt][2] + b0, acc[mt][nt][3] + b1);
        }
    }
}

// ------------- flash attention: paired causal tiles, 4 warps x 32 q --------
// Each CTA processes q-tiles (31-pair) and (pair): constant 33 units of work
// -> 256 CTAs at 2/SM = one perfectly balanced wave.
#define LDQK 72
#define LDV 136
#define QBUF (128 * LDQK * 2)
#define VBUF (64 * LDV * 2)
#define OFF_K (2 * QBUF)
#define OFF_V (4 * QBUF)
#define ATTN_SMEM (4 * QBUF + 2 * VBUF)  // 108544 -> 2 CTAs/SM

__global__ void __launch_bounds__(128, 2) attn_k()
{
    extern __shared__ __align__(16) char smraw[];
    uint32_t sb = smem_u32(smraw);
    uint32_t aQhi = sb, aQlo = sb + QBUF;
    uint32_t aKhi = sb + OFF_K, aKlo = sb + OFF_K + QBUF;
    uint32_t aVhi = sb + OFF_V, aVlo = sb + OFF_V + VBUF;

    int pairi = blockIdx.x;               // 0..15
    int h = blockIdx.y;
    int tid = threadIdx.x, wid = tid >> 5, lane = tid & 31;
    int m0 = wid * 32;                    // warp's 32 query rows (2 m-tiles)
    int rq = lane >> 2, cq = (lane & 3) * 2;

    const __half* khg0 = g_khi + (size_t)h * S_LEN * HEAD_DIM;
    const __half* klg0 = g_klo + (size_t)h * S_LEN * HEAD_DIM;
    const __half* vhg0 = g_vhi + (size_t)h * HEAD_DIM * S_LEN;
    const __half* vlg0 = g_vlo + (size_t)h * HEAD_DIM * S_LEN;

    for (int ti = 0; ti < 2; ti++) {
        int qb = (ti == 0) ? (31 - pairi) : pairi;  // big tile first

        __syncthreads();  // prev tile's Q reads done before overwrite
        // load Q tile (cp.async, once per tile)
        {
            const __half* qhg = g_qhi + ((size_t)h * S_LEN + qb * 128) * HEAD_DIM;
            const __half* qlg = g_qlo + ((size_t)h * S_LEN + qb * 128) * HEAD_DIM;
#pragma unroll
            for (int it = 0; it < 8; it++) {
                int idx4 = tid + it * 128;
                int row = idx4 >> 3, col = (idx4 & 7) << 3;
                uint32_t off = (uint32_t)(row * LDQK + col) * 2u;
                cpa16(aQhi + off, qhg + (size_t)row * HEAD_DIM + col);
                cpa16(aQlo + off, qlg + (size_t)row * HEAD_DIM + col);
            }
            cpa_commit();
        }

        float m[2][2], l[2][2], o[2][8][4];
#pragma unroll
        for (int mt = 0; mt < 2; mt++) {
            m[mt][0] = m[mt][1] = -1e30f;
            l[mt][0] = l[mt][1] = 0.f;
#pragma unroll
            for (int dt = 0; dt < 8; dt++)
#pragma unroll
                for (int e = 0; e < 4; e++) o[mt][dt][e] = 0.f;
        }

        for (int kb = 0; kb <= qb; kb++) {
            __syncthreads();
            // ---- load K/V tile (single stage; co-resident CTA hides latency)
            {
                const __half* khg = khg0 + (size_t)(kb * 128) * HEAD_DIM;
                const __half* klg = klg0 + (size_t)(kb * 128) * HEAD_DIM;
                const __half* vhg = vhg0 + kb * 128;
                const __half* vlg = vlg0 + kb * 128;
#pragma unroll
                for (int it = 0; it < 8; it++) {
                    int idx4 = tid + it * 128;
                    int row = idx4 >> 3, col = (idx4 & 7) << 3;
                    uint32_t koff = (uint32_t)(row * LDQK + col) * 2u;
                    cpa16(aKhi + koff, khg + (size_t)row * HEAD_DIM + col);
                    cpa16(aKlo + koff, klg + (size_t)row * HEAD_DIM + col);
                    int vrow = idx4 >> 4, vcol = (idx4 & 15) << 3;
                    uint32_t voff = (uint32_t)(vrow * LDV + vcol) * 2u;
                    cpa16(aVhi + voff, vhg + (size_t)vrow * S_LEN + vcol);
                    cpa16(aVlo + voff, vlg + (size_t)vrow * S_LEN + vcol);
                }
                cpa_commit();
                cpa_wait<0>();
            }
            __syncthreads();

            // ---- two 64-column halves
#pragma unroll
            for (int half = 0; half < 2; half++) {
                int nb = half * 64;

                float sc[2][8][4];
#pragma unroll
                for (int mt = 0; mt < 2; mt++)
#pragma unroll
                    for (int nt = 0; nt < 8; nt++)
#pragma unroll
                        for (int e = 0; e < 4; e++) sc[mt][nt][e] = 0.f;

#pragma unroll
                for (int ks = 0; ks < 4; ks++) {
                    int k0 = ks * 16;
                    uint32_t ah[2][4], al[2][4];
                    ldsm_x4(ah[0], addrA(aQhi, m0, k0, lane, LDQK));
                    ldsm_x4(al[0], addrA(aQlo, m0, k0, lane, LDQK));
                    ldsm_x4(ah[1], addrA(aQhi, m0 + 16, k0, lane, LDQK));
                    ldsm_x4(al[1], addrA(aQlo, m0 + 16, k0, lane, LDQK));
#pragma unroll
                    for (int pg = 0; pg < 2; pg++) {
                        int p0 = nb + pg * 32;
                        uint32_t bh0[4], bl0[4], bh1[4], bl1[4];
                        ldsm_x4(bh0, addrB4(aKhi, p0, k0, lane, LDQK));
                        ldsm_x4(bl0, addrB4(aKlo, p0, k0, lane, LDQK));
                        ldsm_x4(bh1, addrB4(aKhi, p0 + 16, k0, lane, LDQK));
                        ldsm_x4(bl1, addrB4(aKlo, p0 + 16, k0, lane, LDQK));
#pragma unroll
                        for (int mt = 0; mt < 2; mt++) {
                            float* s0 = sc[mt][4 * pg + 0];
                            float* s1 = sc[mt][4 * pg + 1];
                            float* s2 = sc[mt][4 * pg + 2];
                            float* s3 = sc[mt][4 * pg + 3];
                            mma_f16(s0, ah[mt], bh0); mma_f16(s1, ah[mt], bh0 + 2);
                            mma_f16(s2, ah[mt], bh1); mma_f16(s3, ah[mt], bh1 + 2);
                            mma_f16(s0, ah[mt], bl0); mma_f16(s1, ah[mt], bl0 + 2);
                            mma_f16(s2, ah[mt], bl1); mma_f16(s3, ah[mt], bl1 + 2);
                            mma_f16(s0, al[mt], bh0); mma_f16(s1, al[mt], bh0 + 2);
                            mma_f16(s2, al[mt], bh1); mma_f16(s3, al[mt], bh1 + 2);
                        }
                    }
                }

                // ---- causal mask on diagonal tile
                if (kb == qb) {
#pragma unroll
                    for (int mt = 0; mt < 2; mt++)
#pragma unroll
                        for (int nt = 0; nt < 8; nt++)
#pragma unroll
                            for (int e = 0; e < 4; e++) {
                                int qi = m0 + mt * 16 + rq + ((e >> 1) << 3);
                                int kj = nb + nt * 8 + cq + (e & 1);
                                if (kj > qi) sc[mt][nt][e] = -1e30f;
                            }
                }

                // ---- online softmax (log2 domain, ex2)
#pragma unroll
                for (int mt = 0; mt < 2; mt++)
#pragma unroll
                    for (int r = 0; r < 2; r++) {
                        float mx = -1e30f;
#pragma unroll
                        for (int nt = 0; nt < 8; nt++)
                            mx = fmaxf(mx, fmaxf(sc[mt][nt][2 * r],
                                                 sc[mt][nt][2 * r + 1]));
                        mx = fmaxf(mx, __shfl_xor_sync(0xffffffffu, mx, 1));
                        mx = fmaxf(mx, __shfl_xor_sync(0xffffffffu, mx, 2));
                        float mn = fmaxf(m[mt][r], mx);
                        float corr = ex2f(m[mt][r] - mn);
                        m[mt][r] = mn;
                        float rs = 0.f;
#pragma unroll
                        for (int nt = 0; nt < 8; nt++) {
                            float p0 = ex2f(sc[mt][nt][2 * r] - mn);
                            float p1 = ex2f(sc[mt][nt][2 * r + 1] - mn);
                            sc[mt][nt][2 * r] = p0;
                            sc[mt][nt][2 * r + 1] = p1;
                            rs += p0 + p1;
                        }
                        l[mt][r] = l[mt][r] * corr + rs;
#pragma unroll
                        for (int dt = 0; dt < 8; dt++) {
                            o[mt][dt][2 * r] *= corr;
                            o[mt][dt][2 * r + 1] *= corr;
                        }
                    }

                // ---- PV: single-fp16 P, 2-term fp16 V
#pragma unroll
                for (int kp = 0; kp < 4; kp++) {
                    uint32_t pa[2][4];
#pragma unroll
                    for (int mt = 0; mt < 2; mt++) {
                        pa[mt][0] = pk_h2(sc[mt][2 * kp][0], sc[mt][2 * kp][1]);
                        pa[mt][1] = pk_h2(sc[mt][2 * kp][2], sc[mt][2 * kp][3]);
                        pa[mt][2] = pk_h2(sc[mt][2 * kp + 1][0], sc[mt][2 * kp + 1][1]);
                        pa[mt][3] = pk_h2(sc[mt][2 * kp + 1][2], sc[mt][2 * kp + 1][3]);
                    }
                    int k0 = nb + kp * 16;
#pragma unroll
                    for (int pg = 0; pg < 2; pg++) {
                        int p0 = pg * 32;
                        uint32_t vh0[4], vl0[4], vh1[4], vl1[4];
                        ldsm_x4(vh0, addrB4(aVhi, p0, k0, lane, LDV));
                        ldsm_x4(vl0, addrB4(aVlo, p0, k0, lane, LDV));
                        ldsm_x4(vh1, addrB4(aVhi, p0 + 16, k0, lane, LDV));
                        ldsm_x4(vl1, addrB4(aVlo, p0 + 16, k0, lane, LDV));
#pragma unroll
                        for (int mt = 0; mt < 2; mt++) {
                            float* o0 = o[mt][4 * pg + 0];
                            float* o1 = o[mt][4 * pg + 1];
                            float* o2 = o[mt][4 * pg + 2];
                            float* o3 = o[mt][4 * pg + 3];
                            mma_f16(o0, pa[mt], vh0); mma_f16(o1, pa[mt], vh0 + 2);
                            mma_f16(o2, pa[mt], vh1); mma_f16(o3, pa[mt], vh1 + 2);
                            mma_f16(o0, pa[mt], vl0); mma_f16(o1, pa[mt], vl0 + 2);
                            mma_f16(o2, pa[mt], vl1); mma_f16(o3, pa[mt], vl1 + 2);
                        }
                    }
                }
            }
        }

        // ---- finalize this q-tile
#pragma unroll
        for (int mt = 0; mt < 2; mt++) {
#pragma unroll
            for (int r = 0; r < 2; r++) {
                l[mt][r] += __shfl_xor_sync(0xffffffffu, l[mt][r], 1);
                l[mt][r] += __shfl_xor_sync(0xffffffffu, l[mt][r], 2);
            }
            float inv0 = 1.f / l[mt][0], inv1 = 1.f / l[mt][1];
            int r0 = qb * 128 + m0 + mt * 16 + rq;
            size_t ob = (size_t)r0 * D_MODEL + h * HEAD_DIM + cq;
#pragma unroll
            for (int dt = 0; dt < 8; dt++) {
                uint32_t hh, ll;
                split2h(o[mt][dt][0] * inv0, o[mt][dt][1] * inv0, hh, ll);
                *(uint32_t*)(g_ahi + ob + dt * 8) = hh;
                *(uint32_t*)(g_alo + ob + dt * 8) = ll;
                split2h(o[mt][dt][2] * inv1, o[mt][dt][3] * inv1, hh, ll);
                *(uint32_t*)(g_ahi + ob + 8 * D_MODEL + dt * 8) = hh;
                *(uint32_t*)(g_alo + ob + 8 * D_MODEL + dt * 8) = ll;
            }
        }
    }
}

extern "C" void kernel_launch(void* const* d_in, const int* in_sizes, int n_in,
                              void* d_out, int out_size)
{
    const float* x    = (const float*)d_in[0];
    const float* fcos = (const float*)d_in[2];
    const float* fsin = (const float*)d_in[3];
    const float* wq  = (const float*)d_in[5];
    const float* wqb = (const float*)d_in[6];
    const float* wk  = (const float*)d_in[7];
    const float* wkb = (const float*)d_in[8];
    const float* wv  = (const float*)d_in[9];
    const float* wvb = (const float*)d_in[10];
    const float* wo  = (const float*)d_in[11];
    const float* wob = (const float*)d_in[12];
    float* out = (float*)d_out;

    static bool attr_set = false;
    if (!attr_set) {
        cudaFuncSetAttribute(attn_k,
                             cudaFuncAttributeMaxDynamicSharedMemorySize,
                             ATTN_SMEM);
        cudaFuncSetAttribute(gemm_qkv,
                             cudaFuncAttributeMaxDynamicSharedMemorySize,
                             GEMM_SMEM);
        cudaFuncSetAttribute(gemm_o,
                             cudaFuncAttributeMaxDynamicSharedMemorySize,
                             GEMM_SMEM);
        attr_set = true;
    }

    conv_all<<<(NX + 4 * NW) / 256, 256>>>(x, wq, wk, wv, wo);
    gemm_qkv<<<dim3(D_MODEL / 128, S_LEN / 128, 3), 256, GEMM_SMEM>>>(
        wqb, wkb, wvb, fcos, fsin);
    attn_k<<<dim3(16, N_HEADS), 128, ATTN_SMEM>>>();
    gemm_o<<<dim3(D_MODEL / 128, S_LEN / 128), 256, GEMM_SMEM>>>(wob, out);
}

// round 14
// speedup vs baseline: 1.6348x; 1.1951x over previous
#include <cuda_runtime.h>
#include <cuda_fp16.h>
#include <cstdint>

#define S_LEN 4096
#define D_MODEL 1024
#define N_HEADS 16
#define HEAD_DIM 64
#define HALF_DIM 32

// ---------------- fp16-split scratch (device globals) ----------------------
__device__ __align__(16) __half g_xhi[S_LEN * D_MODEL];
__device__ __align__(16) __half g_xlo[S_LEN * D_MODEL];
__device__ __align__(16) __half g_whi[4][D_MODEL * D_MODEL];
__device__ __align__(16) __half g_wlo[4][D_MODEL * D_MODEL];
__device__ __align__(16) __half g_qhi[N_HEADS * S_LEN * HEAD_DIM]; // RoPE'd, *log2e/8
__device__ __align__(16) __half g_qlo[N_HEADS * S_LEN * HEAD_DIM];
__device__ __align__(16) __half g_khi[N_HEADS * S_LEN * HEAD_DIM]; // RoPE'd (fp16)
__device__ __align__(16) __half g_vhi[N_HEADS * HEAD_DIM * S_LEN]; // [h][d][s] fp16
__device__ __align__(16) __half g_ahi[S_LEN * D_MODEL];            // attn out
__device__ __align__(16) __half g_alo[S_LEN * D_MODEL];

// ---------------- helpers ---------------------------------------------------
__device__ __forceinline__ uint32_t smem_u32(const void* p) {
    uint32_t a;
    asm("{ .reg .u64 t; cvta.to.shared.u64 t, %1; cvt.u32.u64 %0, t; }"
        : "=r"(a) : "l"(p));
    return a;
}

__device__ __forceinline__ void cpa16(uint32_t dst, const void* src) {
    asm volatile("cp.async.cg.shared.global [%0], [%1], 16;"
                 :: "r"(dst), "l"(src));
}
__device__ __forceinline__ void cpa_commit() {
    asm volatile("cp.async.commit_group;");
}
template <int N>
__device__ __forceinline__ void cpa_wait() {
    asm volatile("cp.async.wait_group %0;" :: "n"(N));
}

__device__ __forceinline__ void ldsm_x4(uint32_t* r, uint32_t addr) {
    asm volatile("ldmatrix.sync.aligned.m8n8.x4.shared.b16 {%0,%1,%2,%3}, [%4];"
                 : "=r"(r[0]), "=r"(r[1]), "=r"(r[2]), "=r"(r[3]) : "r"(addr));
}

__device__ __forceinline__ void mma_f16(float* c, const uint32_t* a,
                                        const uint32_t* b) {
    asm volatile(
        "mma.sync.aligned.m16n8k16.row.col.f32.f16.f16.f32 "
        "{%0,%1,%2,%3}, {%4,%5,%6,%7}, {%8,%9}, {%0,%1,%2,%3};"
        : "+f"(c[0]), "+f"(c[1]), "+f"(c[2]), "+f"(c[3])
        : "r"(a[0]), "r"(a[1]), "r"(a[2]), "r"(a[3]), "r"(b[0]), "r"(b[1]));
}

__device__ __forceinline__ float ex2f(float x) {
    float y;
    asm("ex2.approx.f32 %0, %1;" : "=f"(y) : "f"(x));
    return y;
}

__device__ __forceinline__ uint32_t pk_h2(float a, float b) {
    __half2 t = __floats2half2_rn(a, b);
    return *reinterpret_cast<uint32_t*>(&t);
}

// fp16 hi/lo split of a float pair
__device__ __forceinline__ void split2h(float a, float b,
                                        uint32_t& hi, uint32_t& lo) {
    __half ha = __float2half_rn(a);
    __half hb = __float2half_rn(b);
    __half la = __float2half_rn(a - __half2float(ha));
    __half lb = __float2half_rn(b - __half2float(hb));
    __half2 th = __halves2half2(ha, hb);
    __half2 tl = __halves2half2(la, lb);
    hi = *reinterpret_cast<uint32_t*>(&th);
    lo = *reinterpret_cast<uint32_t*>(&tl);
}

__device__ __forceinline__ uint32_t addrA(uint32_t base, int m0, int k0,
                                          int lane, int ld) {
    int r = m0 + (lane & 15);
    int c = k0 + ((lane >> 4) << 3);
    return base + (uint32_t)(r * ld + c) * 2u;
}
__device__ __forceinline__ uint32_t addrB4(uint32_t base, int n0, int k0,
                                           int lane, int ld) {
    int g = lane >> 3;
    int r = n0 + ((g >> 1) << 3) + (lane & 7);
    int c = k0 + ((g & 1) << 3);
    return base + (uint32_t)(r * ld + c) * 2u;
}

// ---------------- pre-pass: f32 -> fp16 split (fused, one launch) -----------
#define NX (S_LEN * D_MODEL / 4)
#define NW (D_MODEL * D_MODEL / 4)

__global__ void __launch_bounds__(256) conv_all(
    const float* __restrict__ x, const float* __restrict__ wq,
    const float* __restrict__ wk, const float* __restrict__ wv,
    const float* __restrict__ wo)
{
    int idx = blockIdx.x * 256 + threadIdx.x;
    const float* src;
    __half *hi, *lo;
    int off;
    if (idx < NX) {
        src = x; hi = g_xhi; lo = g_xlo; off = idx;
    } else {
        int j = idx - NX;
        int t = j >> 18;
        off = j & (NW - 1);
        src = (t == 0) ? wq : (t == 1) ? wk : (t == 2) ? wv : wo;
        hi = g_whi[t]; lo = g_wlo[t];
    }
    float4 f = ((const float4*)src)[off];
    uint32_t h0, h1, l0, l1;
    split2h(f.x, f.y, h0, l0);
    split2h(f.z, f.w, h1, l1);
    ((uint2*)hi)[off] = make_uint2(h0, h1);
    ((uint2*)lo)[off] = make_uint2(l0, l1);
}

// ------------------- tensor-core GEMM (cp.async, double-buffered) ----------
// TERMS=3: Ah*Bh + Ah*Bl + Al*Bh (Q/K).  TERMS=2: Ah*Bh + Al*Bh (V/O).
#define LDT 40
#define GEMM_BUF (128 * LDT * 2)
#define GEMM_STAGE (4 * GEMM_BUF)
#define GEMM_SMEM (2 * GEMM_STAGE)   // 80 KB -> 2 CTAs/SM

template <int TERMS>
__device__ __forceinline__ void gemm_issue(
    uint32_t sb, uint32_t soff,
    const __half* pAh, const __half* pAl,
    const __half* pBh, const __half* pBl, int c)
{
    int go = c * 32;
    cpa16(sb + soff,                       pAh + go);
    cpa16(sb + soff + 16,                  pAh + go + 8);
    cpa16(sb + GEMM_BUF + soff,            pAl + go);
    cpa16(sb + GEMM_BUF + soff + 16,       pAl + go + 8);
    cpa16(sb + 2 * GEMM_BUF + soff,        pBh + go);
    cpa16(sb + 2 * GEMM_BUF + soff + 16,   pBh + go + 8);
    if (TERMS == 3) {
        cpa16(sb + 3 * GEMM_BUF + soff,      pBl + go);
        cpa16(sb + 3 * GEMM_BUF + soff + 16, pBl + go + 8);
    }
    cpa_commit();
}

template <int TERMS>
__device__ __forceinline__ void gemm_core(
    uint32_t sb0, uint32_t soff,
    const __half* pAh, const __half* pAl,
    const __half* pBh, const __half* pBl,
    int m0, int n0, int lane, float acc[4][4][4])
{
    gemm_issue<TERMS>(sb0, soff, pAh, pAl, pBh, pBl, 0);
    gemm_issue<TERMS>(sb0 + GEMM_STAGE, soff, pAh, pAl, pBh, pBl, 1);

    for (int c = 0; c < 32; c++) {
        if (c < 31) cpa_wait<1>(); else cpa_wait<0>();
        __syncthreads();
        uint32_t sb = sb0 + (c & 1) * GEMM_STAGE;
        uint32_t aAhi = sb, aAlo = sb + GEMM_BUF;
        uint32_t aBhi = sb + 2 * GEMM_BUF, aBlo = sb + 3 * GEMM_BUF;
#pragma unroll
        for (int ks = 0; ks < 2; ks++) {
            int k0 = ks * 16;
            uint32_t bh[2][4], bl[2][4];
#pragma unroll
            for (int p = 0; p < 2; p++) {
                ldsm_x4(bh[p], addrB4(aBhi, n0 + p * 16, k0, lane, LDT));
                if (TERMS == 3)
                    ldsm_x4(bl[p], addrB4(aBlo, n0 + p * 16, k0, lane, LDT));
            }
#pragma unroll
            for (int mt = 0; mt < 4; mt++) {
                uint32_t ah[4], al[4];
                ldsm_x4(ah, addrA(aAhi, m0 + mt * 16, k0, lane, LDT));
                ldsm_x4(al, addrA(aAlo, m0 + mt * 16, k0, lane, LDT));
#pragma unroll
                for (int nt = 0; nt < 4; nt++) {
                    const uint32_t* pbh = &bh[nt >> 1][(nt & 1) * 2];
                    mma_f16(acc[mt][nt], ah, pbh);
                    if (TERMS == 3) {
                        const uint32_t* pbl = &bl[nt >> 1][(nt & 1) * 2];
                        mma_f16(acc[mt][nt], ah, pbl);
                    }
                    mma_f16(acc[mt][nt], al, pbh);
                }
            }
        }
        __syncthreads();
        if (c + 2 < 32)
            gemm_issue<TERMS>(sb0 + (c & 1) * GEMM_STAGE, soff,
                              pAh, pAl, pBh, pBl, c + 2);
    }
}

// QKV fused: blockIdx.z = mode (0=Q,1=K,2=V)
__global__ void __launch_bounds__(256, 2) gemm_qkv(
    const float* __restrict__ bq, const float* __restrict__ bk,
    const float* __restrict__ bv, const float* __restrict__ fcos,
    const float* __restrict__ fsin)
{
    extern __shared__ __align__(16) char dsm[];
    uint32_t sb0 = smem_u32(dsm);

    int mode = blockIdx.z;
    const float* bias = (mode == 0) ? bq : (mode == 1) ? bk : bv;

    int tid = threadIdx.x, wid = tid >> 5, lane = tid & 31;
    int m0 = (wid >> 2) * 64, n0 = (wid & 3) * 32;
    int bm = blockIdx.y * 128, bn = blockIdx.x * 128;

    int lrow = tid >> 1, lks = (tid & 1) * 16;
    uint32_t soff = (uint32_t)(lrow * LDT + lks) * 2u;
    const __half* pAh = g_xhi + (size_t)(bm + lrow) * D_MODEL + lks;
    const __half* pAl = g_xlo + (size_t)(bm + lrow) * D_MODEL + lks;
    const __half* pBh = g_whi[mode] + (size_t)(bn + lrow) * D_MODEL + lks;
    const __half* pBl = g_wlo[mode] + (size_t)(bn + lrow) * D_MODEL + lks;

    float acc[4][4][4];
#pragma unroll
    for (int i = 0; i < 4; i++)
#pragma unroll
        for (int j = 0; j < 4; j++)
#pragma unroll
            for (int e = 0; e < 4; e++) acc[i][j][e] = 0.f;

    if (mode == 2)
        gemm_core<2>(sb0, soff, pAh, pAl, pBh, pBl, m0, n0, lane, acc);
    else
        gemm_core<3>(sb0, soff, pAh, pAl, pBh, pBl, m0, n0, lane, acc);

    int rq = lane >> 2, cq = (lane & 3) * 2;
    // Q pre-scale folds softmax 1/sqrt(64) AND log2(e) for ex2-based softmax
    float scale = (mode == 0) ? (0.125f * 1.4426950408889634f) : 1.f;
#pragma unroll
    for (int mt = 0; mt < 4; mt++) {
#pragma unroll
        for (int nt = 0; nt < 4; nt++) {
            int r0 = bm + m0 + mt * 16 + rq;
            int cg = bn + n0 + nt * 8 + cq;
            float b0 = bias[cg], b1 = bias[cg + 1];
            float v00 = acc[mt][nt][0] + b0, v01 = acc[mt][nt][1] + b1;
            float v10 = acc[mt][nt][2] + b0, v11 = acc[mt][nt][3] + b1;
            int h = cg >> 6, d = cg & 63;
            if (mode == 2) {
                // V: single fp16 [h][d][s]
                size_t o0 = ((size_t)h * HEAD_DIM + d) * S_LEN;
                g_vhi[o0 + r0]             = __float2half_rn(v00);
                g_vhi[o0 + r0 + 8]         = __float2half_rn(v10);
                g_vhi[o0 + S_LEN + r0]     = __float2half_rn(v01);
                g_vhi[o0 + S_LEN + r0 + 8] = __float2half_rn(v11);
            } else {
                float c0 = fcos[(size_t)r0 * HALF_DIM + (d >> 1)];
                float s0 = fsin[(size_t)r0 * HALF_DIM + (d >> 1)];
                float c1 = fcos[(size_t)(r0 + 8) * HALF_DIM + (d >> 1)];
                float s1 = fsin[(size_t)(r0 + 8) * HALF_DIM + (d >> 1)];
                float q00 = (v00 * c0 - v01 * s0) * scale;
                float q01 = (v00 * s0 + v01 * c0) * scale;
                float q10 = (v10 * c1 - v11 * s1) * scale;
                float q11 = (v10 * s1 + v11 * c1) * scale;
                size_t o0 = ((size_t)h * S_LEN + r0) * HEAD_DIM + d;
                if (mode == 0) {
                    uint32_t hh, ll;
                    split2h(q00, q01, hh, ll);
                    *(uint32_t*)(g_qhi + o0) = hh;
                    *(uint32_t*)(g_qlo + o0) = ll;
                    split2h(q10, q11, hh, ll);
                    *(uint32_t*)(g_qhi + o0 + 8 * HEAD_DIM) = hh;
                    *(uint32_t*)(g_qlo + o0 + 8 * HEAD_DIM) = ll;
                } else {
                    // K: single fp16 (attention drops K-lo term)
                    *(uint32_t*)(g_khi + o0) = pk_h2(q00, q01);
                    *(uint32_t*)(g_khi + o0 + 8 * HEAD_DIM) = pk_h2(q10, q11);
                }
            }
        }
    }
}

__global__ void __launch_bounds__(256, 2) gemm_o(
    const float* __restrict__ bias, float* __restrict__ oout)
{
    extern __shared__ __align__(16) char dsm[];
    uint32_t sb0 = smem_u32(dsm);

    int tid = threadIdx.x, wid = tid >> 5, lane = tid & 31;
    int m0 = (wid >> 2) * 64, n0 = (wid & 3) * 32;
    int bm = blockIdx.y * 128, bn = blockIdx.x * 128;

    int lrow = tid >> 1, lks = (tid & 1) * 16;
    uint32_t soff = (uint32_t)(lrow * LDT + lks) * 2u;
    const __half* pAh = g_ahi + (size_t)(bm + lrow) * D_MODEL + lks;
    const __half* pAl = g_alo + (size_t)(bm + lrow) * D_MODEL + lks;
    const __half* pBh = g_whi[3] + (size_t)(bn + lrow) * D_MODEL + lks;
    const __half* pBl = g_wlo[3] + (size_t)(bn + lrow) * D_MODEL + lks;

    float acc[4][4][4];
#pragma unroll
    for (int i = 0; i < 4; i++)
#pragma unroll
        for (int j = 0; j < 4; j++)
#pragma unroll
            for (int e = 0; e < 4; e++) acc[i][j][e] = 0.f;

    gemm_core<2>(sb0, soff, pAh, pAl, pBh, pBl, m0, n0, lane, acc);

    int rq = lane >> 2, cq = (lane & 3) * 2;
#pragma unroll
    for (int mt = 0; mt < 4; mt++) {
#pragma unroll
        for (int nt = 0; nt < 4; nt++) {
            int r0 = bm + m0 + mt * 16 + rq;
            int cg = bn + n0 + nt * 8 + cq;
            float b0 = bias[cg], b1 = bias[cg + 1];
            *(float2*)(oout + (size_t)r0 * D_MODEL + cg) =
                make_float2(acc[mt][nt][0] + b0, acc[mt][nt][1] + b1);
            *(float2*)(oout + (size_t)(r0 + 8) * D_MODEL + cg) =
                make_float2(acc[mt][nt][2] + b0, acc[mt][nt][3] + b1);
        }
    }
}

// ------ flash attention: paired tiles, Q split / K single / V single -------
// scores: Qh*Kh + Ql*Kh (2 MMAs); PV: P*Vh (1 MMA). smem 72.7 KB.
#define LDQK 72
#define LDV 136
#define QBUF (128 * LDQK * 2)
#define VBUF (64 * LDV * 2)
#define OFF_K (2 * QBUF)
#define OFF_V (3 * QBUF)
#define ATTN_SMEM (3 * QBUF + VBUF)   // 72704

__global__ void __launch_bounds__(128, 2) attn_k()
{
    extern __shared__ __align__(16) char smraw[];
    uint32_t sb = smem_u32(smraw);
    uint32_t aQhi = sb, aQlo = sb + QBUF;
    uint32_t aKhi = sb + OFF_K;
    uint32_t aVhi = sb + OFF_V;

    int pairi = blockIdx.x;               // 0..15
    int h = blockIdx.y;
    int tid = threadIdx.x, wid = tid >> 5, lane = tid & 31;
    int m0 = wid * 32;                    // warp's 32 query rows (2 m-tiles)
    int rq = lane >> 2, cq = (lane & 3) * 2;

    const __half* khg0 = g_khi + (size_t)h * S_LEN * HEAD_DIM;
    const __half* vhg0 = g_vhi + (size_t)h * HEAD_DIM * S_LEN;

    for (int ti = 0; ti < 2; ti++) {
        int qb = (ti == 0) ? (31 - pairi) : pairi;  // big tile first

        __syncthreads();  // prev tile's Q reads done before overwrite
        // load Q tile (cp.async, once per tile)
        {
            const __half* qhg = g_qhi + ((size_t)h * S_LEN + qb * 128) * HEAD_DIM;
            const __half* qlg = g_qlo + ((size_t)h * S_LEN + qb * 128) * HEAD_DIM;
#pragma unroll
            for (int it = 0; it < 8; it++) {
                int idx4 = tid + it * 128;
                int row = idx4 >> 3, col = (idx4 & 7) << 3;
                uint32_t off = (uint32_t)(row * LDQK + col) * 2u;
                cpa16(aQhi + off, qhg + (size_t)row * HEAD_DIM + col);
                cpa16(aQlo + off, qlg + (size_t)row * HEAD_DIM + col);
            }
            cpa_commit();
        }

        float m[2][2], l[2][2], o[2][8][4];
#pragma unroll
        for (int mt = 0; mt < 2; mt++) {
            m[mt][0] = m[mt][1] = -1e30f;
            l[mt][0] = l[mt][1] = 0.f;
#pragma unroll
            for (int dt = 0; dt < 8; dt++)
#pragma unroll
                for (int e = 0; e < 4; e++) o[mt][dt][e] = 0.f;
        }

        for (int kb = 0; kb <= qb; kb++) {
            __syncthreads();
            // ---- load K/V tile (hi only; single stage)
            {
                const __half* khg = khg0 + (size_t)(kb * 128) * HEAD_DIM;
                const __half* vhg = vhg0 + kb * 128;
#pragma unroll
                for (int it = 0; it < 8; it++) {
                    int idx4 = tid + it * 128;
                    int row = idx4 >> 3, col = (idx4 & 7) << 3;
                    uint32_t koff = (uint32_t)(row * LDQK + col) * 2u;
                    cpa16(aKhi + koff, khg + (size_t)row * HEAD_DIM + col);
                    int vrow = idx4 >> 4, vcol = (idx4 & 15) << 3;
                    uint32_t voff = (uint32_t)(vrow * LDV + vcol) * 2u;
                    cpa16(aVhi + voff, vhg + (size_t)vrow * S_LEN + vcol);
                }
                cpa_commit();
                cpa_wait<0>();
            }
            __syncthreads();

            // ---- two 64-column halves
#pragma unroll
            for (int half = 0; half < 2; half++) {
                int nb = half * 64;

                float sc[2][8][4];
#pragma unroll
                for (int mt = 0; mt < 2; mt++)
#pragma unroll
                    for (int nt = 0; nt < 8; nt++)
#pragma unroll
                        for (int e = 0; e < 4; e++) sc[mt][nt][e] = 0.f;

#pragma unroll
                for (int ks = 0; ks < 4; ks++) {
                    int k0 = ks * 16;
                    uint32_t ah[2][4], al[2][4];
                    ldsm_x4(ah[0], addrA(aQhi, m0, k0, lane, LDQK));
                    ldsm_x4(al[0], addrA(aQlo, m0, k0, lane, LDQK));
                    ldsm_x4(ah[1], addrA(aQhi, m0 + 16, k0, lane, LDQK));
                    ldsm_x4(al[1], addrA(aQlo, m0 + 16, k0, lane, LDQK));
#pragma unroll
                    for (int pg = 0; pg < 2; pg++) {
                        int p0 = nb + pg * 32;
                        uint32_t bh0[4], bh1[4];
                        ldsm_x4(bh0, addrB4(aKhi, p0, k0, lane, LDQK));
                        ldsm_x4(bh1, addrB4(aKhi, p0 + 16, k0, lane, LDQK));
#pragma unroll
                        for (int mt = 0; mt < 2; mt++) {
                            float* s0 = sc[mt][4 * pg + 0];
                            float* s1 = sc[mt][4 * pg + 1];
                            float* s2 = sc[mt][4 * pg + 2];
                            float* s3 = sc[mt][4 * pg + 3];
                            mma_f16(s0, ah[mt], bh0); mma_f16(s1, ah[mt], bh0 + 2);
                            mma_f16(s2, ah[mt], bh1); mma_f16(s3, ah[mt], bh1 + 2);
                            mma_f16(s0, al[mt], bh0); mma_f16(s1, al[mt], bh0 + 2);
                            mma_f16(s2, al[mt], bh1); mma_f16(s3, al[mt], bh1 + 2);
                        }
                    }
                }

                // ---- causal mask on diagonal tile
                if (kb == qb) {
#pragma unroll
                    for (int mt = 0; mt < 2; mt++)
#pragma unroll
                        for (int nt = 0; nt < 8; nt++)
#pragma unroll
                            for (int e = 0; e < 4; e++) {
                                int qi = m0 + mt * 16 + rq + ((e >> 1) << 3);
                                int kj = nb + nt * 8 + cq + (e & 1);
                                if (kj > qi) sc[mt][nt][e] = -1e30f;
                            }
                }

                // ---- online softmax (log2 domain, ex2)
#pragma unroll
                for (int mt = 0; mt < 2; mt++)
#pragma unroll
                    for (int r = 0; r < 2; r++) {
                        float mx = -1e30f;
#pragma unroll
                        for (int nt = 0; nt < 8; nt++)
                            mx = fmaxf(mx, fmaxf(sc[mt][nt][2 * r],
                                                 sc[mt][nt][2 * r + 1]));
                        mx = fmaxf(mx, __shfl_xor_sync(0xffffffffu, mx, 1));
                        mx = fmaxf(mx, __shfl_xor_sync(0xffffffffu, mx, 2));
                        float mn = fmaxf(m[mt][r], mx);
                        float corr = ex2f(m[mt][r] - mn);
                        m[mt][r] = mn;
                        float rs = 0.f;
#pragma unroll
                        for (int nt = 0; nt < 8; nt++) {
                            float p0 = ex2f(sc[mt][nt][2 * r] - mn);
                            float p1 = ex2f(sc[mt][nt][2 * r + 1] - mn);
                            sc[mt][nt][2 * r] = p0;
                            sc[mt][nt][2 * r + 1] = p1;
                            rs += p0 + p1;
                        }
                        l[mt][r] = l[mt][r] * corr + rs;
#pragma unroll
                        for (int dt = 0; dt < 8; dt++) {
                            o[mt][dt][2 * r] *= corr;
                            o[mt][dt][2 * r + 1] *= corr;
                        }
                    }

                // ---- PV: single-fp16 P x single-fp16 V
#pragma unroll
                for (int kp = 0; kp < 4; kp++) {
                    uint32_t pa[2][4];
#pragma unroll
                    for (int mt = 0; mt < 2; mt++) {
                        pa[mt][0] = pk_h2(sc[mt][2 * kp][0], sc[mt][2 * kp][1]);
                        pa[mt][1] = pk_h2(sc[mt][2 * kp][2], sc[mt][2 * kp][3]);
                        pa[mt][2] = pk_h2(sc[mt][2 * kp + 1][0], sc[mt][2 * kp + 1][1]);
                        pa[mt][3] = pk_h2(sc[mt][2 * kp + 1][2], sc[mt][2 * kp + 1][3]);
                    }
                    int k0 = nb + kp * 16;
#pragma unroll
                    for (int pg = 0; pg < 2; pg++) {
                        int p0 = pg * 32;
                        uint32_t vh0[4], vh1[4];
                        ldsm_x4(vh0, addrB4(aVhi, p0, k0, lane, LDV));
                        ldsm_x4(vh1, addrB4(aVhi, p0 + 16, k0, lane, LDV));
#pragma unroll
                        for (int mt = 0; mt < 2; mt++) {
                            mma_f16(o[mt][4 * pg + 0], pa[mt], vh0);
                            mma_f16(o[mt][4 * pg + 1], pa[mt], vh0 + 2);
                            mma_f16(o[mt][4 * pg + 2], pa[mt], vh1);
                            mma_f16(o[mt][4 * pg + 3], pa[mt], vh1 + 2);
                        }
                    }
                }
            }
        }

        // ---- finalize this q-tile
#pragma unroll
        for (int mt = 0; mt < 2; mt++) {
#pragma unroll
            for (int r = 0; r < 2; r++) {
                l[mt][r] += __shfl_xor_sync(0xffffffffu, l[mt][r], 1);
                l[mt][r] += __shfl_xor_sync(0xffffffffu, l[mt][r], 2);
            }
            float inv0 = 1.f / l[mt][0], inv1 = 1.f / l[mt][1];
            int r0 = qb * 128 + m0 + mt * 16 + rq;
            size_t ob = (size_t)r0 * D_MODEL + h * HEAD_DIM + cq;
#pragma unroll
            for (int dt = 0; dt < 8; dt++) {
                uint32_t hh, ll;
                split2h(o[mt][dt][0] * inv0, o[mt][dt][1] * inv0, hh, ll);
                *(uint32_t*)(g_ahi + ob + dt * 8) = hh;
                *(uint32_t*)(g_alo + ob + dt * 8) = ll;
                split2h(o[mt][dt][2] * inv1, o[mt][dt][3] * inv1, hh, ll);
                *(uint32_t*)(g_ahi + ob + 8 * D_MODEL + dt * 8) = hh;
                *(uint32_t*)(g_alo + ob + 8 * D_MODEL + dt * 8) = ll;
            }
        }
    }
}

extern "C" void kernel_launch(void* const* d_in, const int* in_sizes, int n_in,
                              void* d_out, int out_size)
{
    const float* x    = (const float*)d_in[0];
    const float* fcos = (const float*)d_in[2];
    const float* fsin = (const float*)d_in[3];
    const float* wq  = (const float*)d_in[5];
    const float* wqb = (const float*)d_in[6];
    const float* wk  = (const float*)d_in[7];
    const float* wkb = (const float*)d_in[8];
    const float* wv  = (const float*)d_in[9];
    const float* wvb = (const float*)d_in[10];
    const float* wo  = (const float*)d_in[11];
    const float* wob = (const float*)d_in[12];
    float* out = (float*)d_out;

    static bool attr_set = false;
    if (!attr_set) {
        cudaFuncSetAttribute(attn_k,
                             cudaFuncAttributeMaxDynamicSharedMemorySize,
                             ATTN_SMEM);
        cudaFuncSetAttribute(gemm_qkv,
                             cudaFuncAttributeMaxDynamicSharedMemorySize,
                             GEMM_SMEM);
        cudaFuncSetAttribute(gemm_o,
                             cudaFuncAttributeMaxDynamicSharedMemorySize,
                             GEMM_SMEM);
        attr_set = true;
    }

    conv_all<<<(NX + 4 * NW) / 256, 256>>>(x, wq, wk, wv, wo);
    gemm_qkv<<<dim3(D_MODEL / 128, S_LEN / 128, 3), 256, GEMM_SMEM>>>(
        wqb, wkb, wvb, fcos, fsin);
    attn_k<<<dim3(16, N_HEADS), 128, ATTN_SMEM>>>();
    gemm_o<<<dim3(D_MODEL / 128, S_LEN / 128), 256, GEMM_SMEM>>>(wob, out);
}

// round 15
// speedup vs baseline: 1.7686x; 1.0818x over previous
#include <cuda_runtime.h>
#include <cuda_fp16.h>
#include <cstdint>

#define S_LEN 4096
#define D_MODEL 1024
#define N_HEADS 16
#define HEAD_DIM 64
#define HALF_DIM 32

// ---------------- fp16-split scratch (device globals) ----------------------
__device__ __align__(16) __half g_xhi[S_LEN * D_MODEL];
__device__ __align__(16) __half g_xlo[S_LEN * D_MODEL];
__device__ __align__(16) __half g_whi[4][D_MODEL * D_MODEL];
__device__ __align__(16) __half g_wlo[4][D_MODEL * D_MODEL];
__device__ __align__(16) __half g_qhi[N_HEADS * S_LEN * HEAD_DIM]; // RoPE'd, *log2e/8, fp16
__device__ __align__(16) __half g_khi[N_HEADS * S_LEN * HEAD_DIM]; // RoPE'd, fp16
__device__ __align__(16) __half g_vhi[N_HEADS * HEAD_DIM * S_LEN]; // [h][d][s] fp16
__device__ __align__(16) __half g_ahi[S_LEN * D_MODEL];            // attn out
__device__ __align__(16) __half g_alo[S_LEN * D_MODEL];

// ---------------- helpers ---------------------------------------------------
__device__ __forceinline__ uint32_t smem_u32(const void* p) {
    uint32_t a;
    asm("{ .reg .u64 t; cvta.to.shared.u64 t, %1; cvt.u32.u64 %0, t; }"
        : "=r"(a) : "l"(p));
    return a;
}

__device__ __forceinline__ void cpa16(uint32_t dst, const void* src) {
    asm volatile("cp.async.cg.shared.global [%0], [%1], 16;"
                 :: "r"(dst), "l"(src));
}
__device__ __forceinline__ void cpa_commit() {
    asm volatile("cp.async.commit_group;");
}
template <int N>
__device__ __forceinline__ void cpa_wait() {
    asm volatile("cp.async.wait_group %0;" :: "n"(N));
}

__device__ __forceinline__ void ldsm_x4(uint32_t* r, uint32_t addr) {
    asm volatile("ldmatrix.sync.aligned.m8n8.x4.shared.b16 {%0,%1,%2,%3}, [%4];"
                 : "=r"(r[0]), "=r"(r[1]), "=r"(r[2]), "=r"(r[3]) : "r"(addr));
}

__device__ __forceinline__ void mma_f16(float* c, const uint32_t* a,
                                        const uint32_t* b) {
    asm volatile(
        "mma.sync.aligned.m16n8k16.row.col.f32.f16.f16.f32 "
        "{%0,%1,%2,%3}, {%4,%5,%6,%7}, {%8,%9}, {%0,%1,%2,%3};"
        : "+f"(c[0]), "+f"(c[1]), "+f"(c[2]), "+f"(c[3])
        : "r"(a[0]), "r"(a[1]), "r"(a[2]), "r"(a[3]), "r"(b[0]), "r"(b[1]));
}

__device__ __forceinline__ float ex2f(float x) {
    float y;
    asm("ex2.approx.f32 %0, %1;" : "=f"(y) : "f"(x));
    return y;
}

__device__ __forceinline__ uint32_t pk_h2(float a, float b) {
    __half2 t = __floats2half2_rn(a, b);
    return *reinterpret_cast<uint32_t*>(&t);
}

// fp16 hi/lo split of a float pair
__device__ __forceinline__ void split2h(float a, float b,
                                        uint32_t& hi, uint32_t& lo) {
    __half ha = __float2half_rn(a);
    __half hb = __float2half_rn(b);
    __half la = __float2half_rn(a - __half2float(ha));
    __half lb = __float2half_rn(b - __half2float(hb));
    __half2 th = __halves2half2(ha, hb);
    __half2 tl = __halves2half2(la, lb);
    hi = *reinterpret_cast<uint32_t*>(&th);
    lo = *reinterpret_cast<uint32_t*>(&tl);
}

__device__ __forceinline__ uint32_t addrA(uint32_t base, int m0, int k0,
                                          int lane, int ld) {
    int r = m0 + (lane & 15);
    int c = k0 + ((lane >> 4) << 3);
    return base + (uint32_t)(r * ld + c) * 2u;
}
__device__ __forceinline__ uint32_t addrB4(uint32_t base, int n0, int k0,
                                           int lane, int ld) {
    int g = lane >> 3;
    int r = n0 + ((g >> 1) << 3) + (lane & 7);
    int c = k0 + ((g & 1) << 3);
    return base + (uint32_t)(r * ld + c) * 2u;
}

// ---------------- pre-pass: f32 -> fp16 split (fused, one launch) -----------
#define NX (S_LEN * D_MODEL / 4)
#define NW (D_MODEL * D_MODEL / 4)

__global__ void __launch_bounds__(256) conv_all(
    const float* __restrict__ x, const float* __restrict__ wq,
    const float* __restrict__ wk, const float* __restrict__ wv,
    const float* __restrict__ wo)
{
    int idx = blockIdx.x * 256 + threadIdx.x;
    const float* src;
    __half *hi, *lo;
    int off;
    if (idx < NX) {
        src = x; hi = g_xhi; lo = g_xlo; off = idx;
    } else {
        int j = idx - NX;
        int t = j >> 18;
        off = j & (NW - 1);
        src = (t == 0) ? wq : (t == 1) ? wk : (t == 2) ? wv : wo;
        hi = g_whi[t]; lo = g_wlo[t];
    }
    float4 f = ((const float4*)src)[off];
    uint32_t h0, h1, l0, l1;
    split2h(f.x, f.y, h0, l0);
    split2h(f.z, f.w, h1, l1);
    ((uint2*)hi)[off] = make_uint2(h0, h1);
    ((uint2*)lo)[off] = make_uint2(l0, l1);
}

// ------------------- tensor-core GEMM (cp.async, double-buffered) ----------
// TERMS=3: Ah*Bh + Ah*Bl + Al*Bh (Q/K).  TERMS=2: Ah*Bh + Al*Bh (V/O).
#define LDT 40
#define GEMM_BUF (128 * LDT * 2)
#define GEMM_STAGE (4 * GEMM_BUF)
#define GEMM_SMEM (2 * GEMM_STAGE)   // 80 KB -> 2 CTAs/SM

template <int TERMS>
__device__ __forceinline__ void gemm_issue(
    uint32_t sb, uint32_t soff,
    const __half* pAh, const __half* pAl,
    const __half* pBh, const __half* pBl, int c)
{
    int go = c * 32;
    cpa16(sb + soff,                       pAh + go);
    cpa16(sb + soff + 16,                  pAh + go + 8);
    cpa16(sb + GEMM_BUF + soff,            pAl + go);
    cpa16(sb + GEMM_BUF + soff + 16,       pAl + go + 8);
    cpa16(sb + 2 * GEMM_BUF + soff,        pBh + go);
    cpa16(sb + 2 * GEMM_BUF + soff + 16,   pBh + go + 8);
    if (TERMS == 3) {
        cpa16(sb + 3 * GEMM_BUF + soff,      pBl + go);
        cpa16(sb + 3 * GEMM_BUF + soff + 16, pBl + go + 8);
    }
    cpa_commit();
}

template <int TERMS>
__device__ __forceinline__ void gemm_core(
    uint32_t sb0, uint32_t soff,
    const __half* pAh, const __half* pAl,
    const __half* pBh, const __half* pBl,
    int m0, int n0, int lane, float acc[4][4][4])
{
    gemm_issue<TERMS>(sb0, soff, pAh, pAl, pBh, pBl, 0);
    gemm_issue<TERMS>(sb0 + GEMM_STAGE, soff, pAh, pAl, pBh, pBl, 1);

    for (int c = 0; c < 32; c++) {
        if (c < 31) cpa_wait<1>(); else cpa_wait<0>();
        __syncthreads();
        uint32_t sb = sb0 + (c & 1) * GEMM_STAGE;
        uint32_t aAhi = sb, aAlo = sb + GEMM_BUF;
        uint32_t aBhi = sb + 2 * GEMM_BUF, aBlo = sb + 3 * GEMM_BUF;
#pragma unroll
        for (int ks = 0; ks < 2; ks++) {
            int k0 = ks * 16;
            uint32_t bh[2][4], bl[2][4];
#pragma unroll
            for (int p = 0; p < 2; p++) {
                ldsm_x4(bh[p], addrB4(aBhi, n0 + p * 16, k0, lane, LDT));
                if (TERMS == 3)
                    ldsm_x4(bl[p], addrB4(aBlo, n0 + p * 16, k0, lane, LDT));
            }
#pragma unroll
            for (int mt = 0; mt < 4; mt++) {
                uint32_t ah[4], al[4];
                ldsm_x4(ah, addrA(aAhi, m0 + mt * 16, k0, lane, LDT));
                ldsm_x4(al, addrA(aAlo, m0 + mt * 16, k0, lane, LDT));
#pragma unroll
                for (int nt = 0; nt < 4; nt++) {
                    const uint32_t* pbh = &bh[nt >> 1][(nt & 1) * 2];
                    mma_f16(acc[mt][nt], ah, pbh);
                    if (TERMS == 3) {
                        const uint32_t* pbl = &bl[nt >> 1][(nt & 1) * 2];
                        mma_f16(acc[mt][nt], ah, pbl);
                    }
                    mma_f16(acc[mt][nt], al, pbh);
                }
            }
        }
        __syncthreads();
        if (c + 2 < 32)
            gemm_issue<TERMS>(sb0 + (c & 1) * GEMM_STAGE, soff,
                              pAh, pAl, pBh, pBl, c + 2);
    }
}

// QKV fused: blockIdx.z = mode (0=Q,1=K,2=V)
__global__ void __launch_bounds__(256, 2) gemm_qkv(
    const float* __restrict__ bq, const float* __restrict__ bk,
    const float* __restrict__ bv, const float* __restrict__ fcos,
    const float* __restrict__ fsin)
{
    extern __shared__ __align__(16) char dsm[];
    uint32_t sb0 = smem_u32(dsm);

    int mode = blockIdx.z;
    const float* bias = (mode == 0) ? bq : (mode == 1) ? bk : bv;

    int tid = threadIdx.x, wid = tid >> 5, lane = tid & 31;
    int m0 = (wid >> 2) * 64, n0 = (wid & 3) * 32;
    int bm = blockIdx.y * 128, bn = blockIdx.x * 128;

    int lrow = tid >> 1, lks = (tid & 1) * 16;
    uint32_t soff = (uint32_t)(lrow * LDT + lks) * 2u;
    const __half* pAh = g_xhi + (size_t)(bm + lrow) * D_MODEL + lks;
    const __half* pAl = g_xlo + (size_t)(bm + lrow) * D_MODEL + lks;
    const __half* pBh = g_whi[mode] + (size_t)(bn + lrow) * D_MODEL + lks;
    const __half* pBl = g_wlo[mode] + (size_t)(bn + lrow) * D_MODEL + lks;

    float acc[4][4][4];
#pragma unroll
    for (int i = 0; i < 4; i++)
#pragma unroll
        for (int j = 0; j < 4; j++)
#pragma unroll
            for (int e = 0; e < 4; e++) acc[i][j][e] = 0.f;

    if (mode == 2)
        gemm_core<2>(sb0, soff, pAh, pAl, pBh, pBl, m0, n0, lane, acc);
    else
        gemm_core<3>(sb0, soff, pAh, pAl, pBh, pBl, m0, n0, lane, acc);

    int rq = lane >> 2, cq = (lane & 3) * 2;
    // Q pre-scale folds softmax 1/sqrt(64) AND log2(e) for ex2-based softmax
    float scale = (mode == 0) ? (0.125f * 1.4426950408889634f) : 1.f;
#pragma unroll
    for (int mt = 0; mt < 4; mt++) {
#pragma unroll
        for (int nt = 0; nt < 4; nt++) {
            int r0 = bm + m0 + mt * 16 + rq;
            int cg = bn + n0 + nt * 8 + cq;
            float b0 = bias[cg], b1 = bias[cg + 1];
            float v00 = acc[mt][nt][0] + b0, v01 = acc[mt][nt][1] + b1;
            float v10 = acc[mt][nt][2] + b0, v11 = acc[mt][nt][3] + b1;
            int h = cg >> 6, d = cg & 63;
            if (mode == 2) {
                // V: single fp16 [h][d][s]
                size_t o0 = ((size_t)h * HEAD_DIM + d) * S_LEN;
                g_vhi[o0 + r0]             = __float2half_rn(v00);
                g_vhi[o0 + r0 + 8]         = __float2half_rn(v10);
                g_vhi[o0 + S_LEN + r0]     = __float2half_rn(v01);
                g_vhi[o0 + S_LEN + r0 + 8] = __float2half_rn(v11);
            } else {
                float c0 = fcos[(size_t)r0 * HALF_DIM + (d >> 1)];
                float s0 = fsin[(size_t)r0 * HALF_DIM + (d >> 1)];
                float c1 = fcos[(size_t)(r0 + 8) * HALF_DIM + (d >> 1)];
                float s1 = fsin[(size_t)(r0 + 8) * HALF_DIM + (d >> 1)];
                float q00 = (v00 * c0 - v01 * s0) * scale;
                float q01 = (v00 * s0 + v01 * c0) * scale;
                float q10 = (v10 * c1 - v11 * s1) * scale;
                float q11 = (v10 * s1 + v11 * c1) * scale;
                size_t o0 = ((size_t)h * S_LEN + r0) * HEAD_DIM + d;
                // Q and K: single fp16 (attention uses 1-term score MMA)
                __half* dst = (mode == 0) ? g_qhi : g_khi;
                *(uint32_t*)(dst + o0) = pk_h2(q00, q01);
                *(uint32_t*)(dst + o0 + 8 * HEAD_DIM) = pk_h2(q10, q11);
            }
        }
    }
}

__global__ void __launch_bounds__(256, 2) gemm_o(
    const float* __restrict__ bias, float* __restrict__ oout)
{
    extern __shared__ __align__(16) char dsm[];
    uint32_t sb0 = smem_u32(dsm);

    int tid = threadIdx.x, wid = tid >> 5, lane = tid & 31;
    int m0 = (wid >> 2) * 64, n0 = (wid & 3) * 32;
    int bm = blockIdx.y * 128, bn = blockIdx.x * 128;

    int lrow = tid >> 1, lks = (tid & 1) * 16;
    uint32_t soff = (uint32_t)(lrow * LDT + lks) * 2u;
    const __half* pAh = g_ahi + (size_t)(bm + lrow) * D_MODEL + lks;
    const __half* pAl = g_alo + (size_t)(bm + lrow) * D_MODEL + lks;
    const __half* pBh = g_whi[3] + (size_t)(bn + lrow) * D_MODEL + lks;
    const __half* pBl = g_wlo[3] + (size_t)(bn + lrow) * D_MODEL + lks;

    float acc[4][4][4];
#pragma unroll
    for (int i = 0; i < 4; i++)
#pragma unroll
        for (int j = 0; j < 4; j++)
#pragma unroll
            for (int e = 0; e < 4; e++) acc[i][j][e] = 0.f;

    gemm_core<2>(sb0, soff, pAh, pAl, pBh, pBl, m0, n0, lane, acc);

    int rq = lane >> 2, cq = (lane & 3) * 2;
#pragma unroll
    for (int mt = 0; mt < 4; mt++) {
#pragma unroll
        for (int nt = 0; nt < 4; nt++) {
            int r0 = bm + m0 + mt * 16 + rq;
            int cg = bn + n0 + nt * 8 + cq;
            float b0 = bias[cg], b1 = bias[cg + 1];
            *(float2*)(oout + (size_t)r0 * D_MODEL + cg) =
                make_float2(acc[mt][nt][0] + b0, acc[mt][nt][1] + b1);
            *(float2*)(oout + (size_t)(r0 + 8) * D_MODEL + cg) =
                make_float2(acc[mt][nt][2] + b0, acc[mt][nt][3] + b1);
        }
    }
}

// ------ flash attention: paired tiles, Q/K/V all single fp16 ---------------
// scores: Qh*Kh (1 MMA); PV: P*Vh (1 MMA). smem 54.3 KB.
#define LDQK 72
#define LDV 136
#define QBUF (128 * LDQK * 2)
#define VBUF (64 * LDV * 2)
#define OFF_K (QBUF)
#define OFF_V (2 * QBUF)
#define ATTN_SMEM (2 * QBUF + VBUF)   // 54272

__global__ void __launch_bounds__(128, 2) attn_k()
{
    extern __shared__ __align__(16) char smraw[];
    uint32_t sb = smem_u32(smraw);
    uint32_t aQhi = sb;
    uint32_t aKhi = sb + OFF_K;
    uint32_t aVhi = sb + OFF_V;

    int pairi = blockIdx.x;               // 0..15
    int h = blockIdx.y;
    int tid = threadIdx.x, wid = tid >> 5, lane = tid & 31;
    int m0 = wid * 32;                    // warp's 32 query rows (2 m-tiles)
    int rq = lane >> 2, cq = (lane & 3) * 2;

    const __half* khg0 = g_khi + (size_t)h * S_LEN * HEAD_DIM;
    const __half* vhg0 = g_vhi + (size_t)h * HEAD_DIM * S_LEN;

    for (int ti = 0; ti < 2; ti++) {
        int qb = (ti == 0) ? (31 - pairi) : pairi;  // big tile first

        __syncthreads();  // prev tile's Q reads done before overwrite
        // load Q tile (cp.async, once per tile)
        {
            const __half* qhg = g_qhi + ((size_t)h * S_LEN + qb * 128) * HEAD_DIM;
#pragma unroll
            for (int it = 0; it < 8; it++) {
                int idx4 = tid + it * 128;
                int row = idx4 >> 3, col = (idx4 & 7) << 3;
                uint32_t off = (uint32_t)(row * LDQK + col) * 2u;
                cpa16(aQhi + off, qhg + (size_t)row * HEAD_DIM + col);
            }
            cpa_commit();
        }

        float m[2][2], l[2][2], o[2][8][4];
#pragma unroll
        for (int mt = 0; mt < 2; mt++) {
            m[mt][0] = m[mt][1] = -1e30f;
            l[mt][0] = l[mt][1] = 0.f;
#pragma unroll
            for (int dt = 0; dt < 8; dt++)
#pragma unroll
                for (int e = 0; e < 4; e++) o[mt][dt][e] = 0.f;
        }

        for (int kb = 0; kb <= qb; kb++) {
            __syncthreads();
            // ---- load K/V tile (single stage)
            {
                const __half* khg = khg0 + (size_t)(kb * 128) * HEAD_DIM;
                const __half* vhg = vhg0 + kb * 128;
#pragma unroll
                for (int it = 0; it < 8; it++) {
                    int idx4 = tid + it * 128;
                    int row = idx4 >> 3, col = (idx4 & 7) << 3;
                    uint32_t koff = (uint32_t)(row * LDQK + col) * 2u;
                    cpa16(aKhi + koff, khg + (size_t)row * HEAD_DIM + col);
                    int vrow = idx4 >> 4, vcol = (idx4 & 15) << 3;
                    uint32_t voff = (uint32_t)(vrow * LDV + vcol) * 2u;
                    cpa16(aVhi + voff, vhg + (size_t)vrow * S_LEN + vcol);
                }
                cpa_commit();
                cpa_wait<0>();
            }
            __syncthreads();

            // ---- two 64-column halves
#pragma unroll
            for (int half = 0; half < 2; half++) {
                int nb = half * 64;

                float sc[2][8][4];
#pragma unroll
                for (int mt = 0; mt < 2; mt++)
#pragma unroll
                    for (int nt = 0; nt < 8; nt++)
#pragma unroll
                        for (int e = 0; e < 4; e++) sc[mt][nt][e] = 0.f;

#pragma unroll
                for (int ks = 0; ks < 4; ks++) {
                    int k0 = ks * 16;
                    uint32_t ah[2][4];
                    ldsm_x4(ah[0], addrA(aQhi, m0, k0, lane, LDQK));
                    ldsm_x4(ah[1], addrA(aQhi, m0 + 16, k0, lane, LDQK));
#pragma unroll
                    for (int pg = 0; pg < 2; pg++) {
                        int p0 = nb + pg * 32;
                        uint32_t bh0[4], bh1[4];
                        ldsm_x4(bh0, addrB4(aKhi, p0, k0, lane, LDQK));
                        ldsm_x4(bh1, addrB4(aKhi, p0 + 16, k0, lane, LDQK));
#pragma unroll
                        for (int mt = 0; mt < 2; mt++) {
                            mma_f16(sc[mt][4 * pg + 0], ah[mt], bh0);
                            mma_f16(sc[mt][4 * pg + 1], ah[mt], bh0 + 2);
                            mma_f16(sc[mt][4 * pg + 2], ah[mt], bh1);
                            mma_f16(sc[mt][4 * pg + 3], ah[mt], bh1 + 2);
                        }
                    }
                }

                // ---- causal mask on diagonal tile
                if (kb == qb) {
#pragma unroll
                    for (int mt = 0; mt < 2; mt++)
#pragma unroll
                        for (int nt = 0; nt < 8; nt++)
#pragma unroll
                            for (int e = 0; e < 4; e++) {
                                int qi = m0 + mt * 16 + rq + ((e >> 1) << 3);
                                int kj = nb + nt * 8 + cq + (e & 1);
                                if (kj > qi) sc[mt][nt][e] = -1e30f;
                            }
                }

                // ---- online softmax (log2 domain, ex2)
#pragma unroll
                for (int mt = 0; mt < 2; mt++)
#pragma unroll
                    for (int r = 0; r < 2; r++) {
                        float mx = -1e30f;
#pragma unroll
                        for (int nt = 0; nt < 8; nt++)
                            mx = fmaxf(mx, fmaxf(sc[mt][nt][2 * r],
                                                 sc[mt][nt][2 * r + 1]));
                        mx = fmaxf(mx, __shfl_xor_sync(0xffffffffu, mx, 1));
                        mx = fmaxf(mx, __shfl_xor_sync(0xffffffffu, mx, 2));
                        float mn = fmaxf(m[mt][r], mx);
                        float corr = ex2f(m[mt][r] - mn);
                        m[mt][r] = mn;
                        float rs = 0.f;
#pragma unroll
                        for (int nt = 0; nt < 8; nt++) {
                            float p0 = ex2f(sc[mt][nt][2 * r] - mn);
                            float p1 = ex2f(sc[mt][nt][2 * r + 1] - mn);
                            sc[mt][nt][2 * r] = p0;
                            sc[mt][nt][2 * r + 1] = p1;
                            rs += p0 + p1;
                        }
                        l[mt][r] = l[mt][r] * corr + rs;
#pragma unroll
                        for (int dt = 0; dt < 8; dt++) {
                            o[mt][dt][2 * r] *= corr;
                            o[mt][dt][2 * r + 1] *= corr;
                        }
                    }

                // ---- PV: single-fp16 P x single-fp16 V
#pragma unroll
                for (int kp = 0; kp < 4; kp++) {
                    uint32_t pa[2][4];
#pragma unroll
                    for (int mt = 0; mt < 2; mt++) {
                        pa[mt][0] = pk_h2(sc[mt][2 * kp][0], sc[mt][2 * kp][1]);
                        pa[mt][1] = pk_h2(sc[mt][2 * kp][2], sc[mt][2 * kp][3]);
                        pa[mt][2] = pk_h2(sc[mt][2 * kp + 1][0], sc[mt][2 * kp + 1][1]);
                        pa[mt][3] = pk_h2(sc[mt][2 * kp + 1][2], sc[mt][2 * kp + 1][3]);
                    }
                    int k0 = nb + kp * 16;
#pragma unroll
                    for (int pg = 0; pg < 2; pg++) {
                        int p0 = pg * 32;
                        uint32_t vh0[4], vh1[4];
                        ldsm_x4(vh0, addrB4(aVhi, p0, k0, lane, LDV));
                        ldsm_x4(vh1, addrB4(aVhi, p0 + 16, k0, lane, LDV));
#pragma unroll
                        for (int mt = 0; mt < 2; mt++) {
                            mma_f16(o[mt][4 * pg + 0], pa[mt], vh0);
                            mma_f16(o[mt][4 * pg + 1], pa[mt], vh0 + 2);
                            mma_f16(o[mt][4 * pg + 2], pa[mt], vh1);
                            mma_f16(o[mt][4 * pg + 3], pa[mt], vh1 + 2);
                        }
                    }
                }
            }
        }

        // ---- finalize this q-tile
#pragma unroll
        for (int mt = 0; mt < 2; mt++) {
#pragma unroll
            for (int r = 0; r < 2; r++) {
                l[mt][r] += __shfl_xor_sync(0xffffffffu, l[mt][r], 1);
                l[mt][r] += __shfl_xor_sync(0xffffffffu, l[mt][r], 2);
            }
            float inv0 = 1.f / l[mt][0], inv1 = 1.f / l[mt][1];
            int r0 = qb * 128 + m0 + mt * 16 + rq;
            size_t ob = (size_t)r0 * D_MODEL + h * HEAD_DIM + cq;
#pragma unroll
            for (int dt = 0; dt < 8; dt++) {
                uint32_t hh, ll;
                split2h(o[mt][dt][0] * inv0, o[mt][dt][1] * inv0, hh, ll);
                *(uint32_t*)(g_ahi + ob + dt * 8) = hh;
                *(uint32_t*)(g_alo + ob + dt * 8) = ll;
                split2h(o[mt][dt][2] * inv1, o[mt][dt][3] * inv1, hh, ll);
                *(uint32_t*)(g_ahi + ob + 8 * D_MODEL + dt * 8) = hh;
                *(uint32_t*)(g_alo + ob + 8 * D_MODEL + dt * 8) = ll;
            }
        }
    }
}

extern "C" void kernel_launch(void* const* d_in, const int* in_sizes, int n_in,
                              void* d_out, int out_size)
{
    const float* x    = (const float*)d_in[0];
    const float* fcos = (const float*)d_in[2];
    const float* fsin = (const float*)d_in[3];
    const float* wq  = (const float*)d_in[5];
    const float* wqb = (const float*)d_in[6];
    const float* wk  = (const float*)d_in[7];
    const float* wkb = (const float*)d_in[8];
    const float* wv  = (const float*)d_in[9];
    const float* wvb = (const float*)d_in[10];
    const float* wo  = (const float*)d_in[11];
    const float* wob = (const float*)d_in[12];
    float* out = (float*)d_out;

    static bool attr_set = false;
    if (!attr_set) {
        cudaFuncSetAttribute(attn_k,
                             cudaFuncAttributeMaxDynamicSharedMemorySize,
                             ATTN_SMEM);
        cudaFuncSetAttribute(gemm_qkv,
                             cudaFuncAttributeMaxDynamicSharedMemorySize,
                             GEMM_SMEM);
        cudaFuncSetAttribute(gemm_o,
                             cudaFuncAttributeMaxDynamicSharedMemorySize,
                             GEMM_SMEM);
        attr_set = true;
    }

    conv_all<<<(NX + 4 * NW) / 256, 256>>>(x, wq, wk, wv, wo);
    gemm_qkv<<<dim3(D_MODEL / 128, S_LEN / 128, 3), 256, GEMM_SMEM>>>(
        wqb, wkb, wvb, fcos, fsin);
    attn_k<<<dim3(16, N_HEADS), 128, ATTN_SMEM>>>();
    gemm_o<<<dim3(D_MODEL / 128, S_LEN / 128), 256, GEMM_SMEM>>>(wob, out);
}

// round 16
// speedup vs baseline: 1.9159x; 1.0833x over previous
#include <cuda_runtime.h>
#include <cuda_fp16.h>
#include <cstdint>

#define S_LEN 4096
#define D_MODEL 1024
#define N_HEADS 16
#define HEAD_DIM 64
#define HALF_DIM 32

// ---------------- fp16-split scratch (device globals) ----------------------
__device__ __align__(16) __half g_xhi[S_LEN * D_MODEL];
__device__ __align__(16) __half g_xlo[S_LEN * D_MODEL];
__device__ __align__(16) __half g_whi[4][D_MODEL * D_MODEL];   // weights: hi only
__device__ __align__(16) __half g_qhi[N_HEADS * S_LEN * HEAD_DIM]; // RoPE'd, *log2e/8, fp16
__device__ __align__(16) __half g_khi[N_HEADS * S_LEN * HEAD_DIM]; // RoPE'd, fp16
__device__ __align__(16) __half g_vhi[N_HEADS * HEAD_DIM * S_LEN]; // [h][d][s] fp16
__device__ __align__(16) __half g_ahi[S_LEN * D_MODEL];            // attn out
__device__ __align__(16) __half g_alo[S_LEN * D_MODEL];

// ---------------- helpers ---------------------------------------------------
__device__ __forceinline__ uint32_t smem_u32(const void* p) {
    uint32_t a;
    asm("{ .reg .u64 t; cvta.to.shared.u64 t, %1; cvt.u32.u64 %0, t; }"
        : "=r"(a) : "l"(p));
    return a;
}

__device__ __forceinline__ void cpa16(uint32_t dst, const void* src) {
    asm volatile("cp.async.cg.shared.global [%0], [%1], 16;"
                 :: "r"(dst), "l"(src));
}
__device__ __forceinline__ void cpa_commit() {
    asm volatile("cp.async.commit_group;");
}
template <int N>
__device__ __forceinline__ void cpa_wait() {
    asm volatile("cp.async.wait_group %0;" :: "n"(N));
}

__device__ __forceinline__ void ldsm_x4(uint32_t* r, uint32_t addr) {
    asm volatile("ldmatrix.sync.aligned.m8n8.x4.shared.b16 {%0,%1,%2,%3}, [%4];"
                 : "=r"(r[0]), "=r"(r[1]), "=r"(r[2]), "=r"(r[3]) : "r"(addr));
}

__device__ __forceinline__ void mma_f16(float* c, const uint32_t* a,
                                        const uint32_t* b) {
    asm volatile(
        "mma.sync.aligned.m16n8k16.row.col.f32.f16.f16.f32 "
        "{%0,%1,%2,%3}, {%4,%5,%6,%7}, {%8,%9}, {%0,%1,%2,%3};"
        : "+f"(c[0]), "+f"(c[1]), "+f"(c[2]), "+f"(c[3])
        : "r"(a[0]), "r"(a[1]), "r"(a[2]), "r"(a[3]), "r"(b[0]), "r"(b[1]));
}

__device__ __forceinline__ float ex2f(float x) {
    float y;
    asm("ex2.approx.f32 %0, %1;" : "=f"(y) : "f"(x));
    return y;
}

__device__ __forceinline__ uint32_t pk_h2(float a, float b) {
    __half2 t = __floats2half2_rn(a, b);
    return *reinterpret_cast<uint32_t*>(&t);
}

// fp16 hi/lo split of a float pair
__device__ __forceinline__ void split2h(float a, float b,
                                        uint32_t& hi, uint32_t& lo) {
    __half ha = __float2half_rn(a);
    __half hb = __float2half_rn(b);
    __half la = __float2half_rn(a - __half2float(ha));
    __half lb = __float2half_rn(b - __half2float(hb));
    __half2 th = __halves2half2(ha, hb);
    __half2 tl = __halves2half2(la, lb);
    hi = *reinterpret_cast<uint32_t*>(&th);
    lo = *reinterpret_cast<uint32_t*>(&tl);
}

__device__ __forceinline__ uint32_t addrA(uint32_t base, int m0, int k0,
                                          int lane, int ld) {
    int r = m0 + (lane & 15);
    int c = k0 + ((lane >> 4) << 3);
    return base + (uint32_t)(r * ld + c) * 2u;
}
__device__ __forceinline__ uint32_t addrB4(uint32_t base, int n0, int k0,
                                           int lane, int ld) {
    int g = lane >> 3;
    int r = n0 + ((g >> 1) << 3) + (lane & 7);
    int c = k0 + ((g & 1) << 3);
    return base + (uint32_t)(r * ld + c) * 2u;
}

// ---------------- pre-pass: f32 -> fp16 (x: split, weights: hi only) -------
#define NX (S_LEN * D_MODEL / 4)
#define NW (D_MODEL * D_MODEL / 4)

__global__ void __launch_bounds__(256) conv_all(
    const float* __restrict__ x, const float* __restrict__ wq,
    const float* __restrict__ wk, const float* __restrict__ wv,
    const float* __restrict__ wo)
{
    int idx = blockIdx.x * 256 + threadIdx.x;
    if (idx < NX) {
        float4 f = ((const float4*)x)[idx];
        uint32_t h0, h1, l0, l1;
        split2h(f.x, f.y, h0, l0);
        split2h(f.z, f.w, h1, l1);
        ((uint2*)g_xhi)[idx] = make_uint2(h0, h1);
        ((uint2*)g_xlo)[idx] = make_uint2(l0, l1);
    } else {
        int j = idx - NX;
        int t = j >> 18;
        int off = j & (NW - 1);
        const float* src = (t == 0) ? wq : (t == 1) ? wk : (t == 2) ? wv : wo;
        float4 f = ((const float4*)src)[off];
        ((uint2*)g_whi[t])[off] =
            make_uint2(pk_h2(f.x, f.y), pk_h2(f.z, f.w));
    }
}

// ------------------- tensor-core GEMM (cp.async, double-buffered) ----------
// 2 terms: Ah*Bh + Al*Bh (A = activation split, B = weight hi).
#define LDT 40
#define GEMM_BUF (128 * LDT * 2)
#define GEMM_STAGE (3 * GEMM_BUF)
#define GEMM_SMEM (2 * GEMM_STAGE)   // 60 KB -> 2 CTAs/SM

__device__ __forceinline__ void gemm_issue(
    uint32_t sb, uint32_t soff,
    const __half* pAh, const __half* pAl, const __half* pBh, int c)
{
    int go = c * 32;
    cpa16(sb + soff,                       pAh + go);
    cpa16(sb + soff + 16,                  pAh + go + 8);
    cpa16(sb + GEMM_BUF + soff,            pAl + go);
    cpa16(sb + GEMM_BUF + soff + 16,       pAl + go + 8);
    cpa16(sb + 2 * GEMM_BUF + soff,        pBh + go);
    cpa16(sb + 2 * GEMM_BUF + soff + 16,   pBh + go + 8);
    cpa_commit();
}

__device__ __forceinline__ void gemm_core(
    uint32_t sb0, uint32_t soff,
    const __half* pAh, const __half* pAl, const __half* pBh,
    int m0, int n0, int lane, float acc[4][4][4])
{
    gemm_issue(sb0, soff, pAh, pAl, pBh, 0);
    gemm_issue(sb0 + GEMM_STAGE, soff, pAh, pAl, pBh, 1);

    for (int c = 0; c < 32; c++) {
        if (c < 31) cpa_wait<1>(); else cpa_wait<0>();
        __syncthreads();
        uint32_t sb = sb0 + (c & 1) * GEMM_STAGE;
        uint32_t aAhi = sb, aAlo = sb + GEMM_BUF;
        uint32_t aBhi = sb + 2 * GEMM_BUF;
#pragma unroll
        for (int ks = 0; ks < 2; ks++) {
            int k0 = ks * 16;
            uint32_t bh[2][4];
#pragma unroll
            for (int p = 0; p < 2; p++)
                ldsm_x4(bh[p], addrB4(aBhi, n0 + p * 16, k0, lane, LDT));
#pragma unroll
            for (int mt = 0; mt < 4; mt++) {
                uint32_t ah[4], al[4];
                ldsm_x4(ah, addrA(aAhi, m0 + mt * 16, k0, lane, LDT));
                ldsm_x4(al, addrA(aAlo, m0 + mt * 16, k0, lane, LDT));
#pragma unroll
                for (int nt = 0; nt < 4; nt++) {
                    const uint32_t* pbh = &bh[nt >> 1][(nt & 1) * 2];
                    mma_f16(acc[mt][nt], ah, pbh);
                    mma_f16(acc[mt][nt], al, pbh);
                }
            }
        }
        __syncthreads();
        if (c + 2 < 32)
            gemm_issue(sb0 + (c & 1) * GEMM_STAGE, soff, pAh, pAl, pBh, c + 2);
    }
}

// QKV fused: blockIdx.z = mode (0=Q,1=K,2=V)
__global__ void __launch_bounds__(256, 2) gemm_qkv(
    const float* __restrict__ bq, const float* __restrict__ bk,
    const float* __restrict__ bv, const float* __restrict__ fcos,
    const float* __restrict__ fsin)
{
    extern __shared__ __align__(16) char dsm[];
    uint32_t sb0 = smem_u32(dsm);

    int mode = blockIdx.z;
    const float* bias = (mode == 0) ? bq : (mode == 1) ? bk : bv;

    int tid = threadIdx.x, wid = tid >> 5, lane = tid & 31;
    int m0 = (wid >> 2) * 64, n0 = (wid & 3) * 32;
    int bm = blockIdx.y * 128, bn = blockIdx.x * 128;

    int lrow = tid >> 1, lks = (tid & 1) * 16;
    uint32_t soff = (uint32_t)(lrow * LDT + lks) * 2u;
    const __half* pAh = g_xhi + (size_t)(bm + lrow) * D_MODEL + lks;
    const __half* pAl = g_xlo + (size_t)(bm + lrow) * D_MODEL + lks;
    const __half* pBh = g_whi[mode] + (size_t)(bn + lrow) * D_MODEL + lks;

    float acc[4][4][4];
#pragma unroll
    for (int i = 0; i < 4; i++)
#pragma unroll
        for (int j = 0; j < 4; j++)
#pragma unroll
            for (int e = 0; e < 4; e++) acc[i][j][e] = 0.f;

    gemm_core(sb0, soff, pAh, pAl, pBh, m0, n0, lane, acc);

    int rq = lane >> 2, cq = (lane & 3) * 2;
    // Q pre-scale folds softmax 1/sqrt(64) AND log2(e) for ex2-based softmax
    float scale = (mode == 0) ? (0.125f * 1.4426950408889634f) : 1.f;
#pragma unroll
    for (int mt = 0; mt < 4; mt++) {
#pragma unroll
        for (int nt = 0; nt < 4; nt++) {
            int r0 = bm + m0 + mt * 16 + rq;
            int cg = bn + n0 + nt * 8 + cq;
            float b0 = bias[cg], b1 = bias[cg + 1];
            float v00 = acc[mt][nt][0] + b0, v01 = acc[mt][nt][1] + b1;
            float v10 = acc[mt][nt][2] + b0, v11 = acc[mt][nt][3] + b1;
            int h = cg >> 6, d = cg & 63;
            if (mode == 2) {
                // V: single fp16 [h][d][s]
                size_t o0 = ((size_t)h * HEAD_DIM + d) * S_LEN;
                g_vhi[o0 + r0]             = __float2half_rn(v00);
                g_vhi[o0 + r0 + 8]         = __float2half_rn(v10);
                g_vhi[o0 + S_LEN + r0]     = __float2half_rn(v01);
                g_vhi[o0 + S_LEN + r0 + 8] = __float2half_rn(v11);
            } else {
                float c0 = fcos[(size_t)r0 * HALF_DIM + (d >> 1)];
                float s0 = fsin[(size_t)r0 * HALF_DIM + (d >> 1)];
                float c1 = fcos[(size_t)(r0 + 8) * HALF_DIM + (d >> 1)];
                float s1 = fsin[(size_t)(r0 + 8) * HALF_DIM + (d >> 1)];
                float q00 = (v00 * c0 - v01 * s0) * scale;
                float q01 = (v00 * s0 + v01 * c0) * scale;
                float q10 = (v10 * c1 - v11 * s1) * scale;
                float q11 = (v10 * s1 + v11 * c1) * scale;
                size_t o0 = ((size_t)h * S_LEN + r0) * HEAD_DIM + d;
                __half* dst = (mode == 0) ? g_qhi : g_khi;
                *(uint32_t*)(dst + o0) = pk_h2(q00, q01);
                *(uint32_t*)(dst + o0 + 8 * HEAD_DIM) = pk_h2(q10, q11);
            }
        }
    }
}

__global__ void __launch_bounds__(256, 2) gemm_o(
    const float* __restrict__ bias, float* __restrict__ oout)
{
    extern __shared__ __align__(16) char dsm[];
    uint32_t sb0 = smem_u32(dsm);

    int tid = threadIdx.x, wid = tid >> 5, lane = tid & 31;
    int m0 = (wid >> 2) * 64, n0 = (wid & 3) * 32;
    int bm = blockIdx.y * 128, bn = blockIdx.x * 128;

    int lrow = tid >> 1, lks = (tid & 1) * 16;
    uint32_t soff = (uint32_t)(lrow * LDT + lks) * 2u;
    const __half* pAh = g_ahi + (size_t)(bm + lrow) * D_MODEL + lks;
    const __half* pAl = g_alo + (size_t)(bm + lrow) * D_MODEL + lks;
    const __half* pBh = g_whi[3] + (size_t)(bn + lrow) * D_MODEL + lks;

    float acc[4][4][4];
#pragma unroll
    for (int i = 0; i < 4; i++)
#pragma unroll
        for (int j = 0; j < 4; j++)
#pragma unroll
            for (int e = 0; e < 4; e++) acc[i][j][e] = 0.f;

    gemm_core(sb0, soff, pAh, pAl, pBh, m0, n0, lane, acc);

    int rq = lane >> 2, cq = (lane & 3) * 2;
#pragma unroll
    for (int mt = 0; mt < 4; mt++) {
#pragma unroll
        for (int nt = 0; nt < 4; nt++) {
            int r0 = bm + m0 + mt * 16 + rq;
            int cg = bn + n0 + nt * 8 + cq;
            float b0 = bias[cg], b1 = bias[cg + 1];
            *(float2*)(oout + (size_t)r0 * D_MODEL + cg) =
                make_float2(acc[mt][nt][0] + b0, acc[mt][nt][1] + b1);
            *(float2*)(oout + (size_t)(r0 + 8) * D_MODEL + cg) =
                make_float2(acc[mt][nt][2] + b0, acc[mt][nt][3] + b1);
        }
    }
}

// ------ flash attention: paired tiles, Q/K/V all single fp16 ---------------
// scores: Qh*Kh (1 MMA); PV: P*Vh (1 MMA). smem 54.3 KB.
#define LDQK 72
#define LDV 136
#define QBUF (128 * LDQK * 2)
#define VBUF (64 * LDV * 2)
#define OFF_K (QBUF)
#define OFF_V (2 * QBUF)
#define ATTN_SMEM (2 * QBUF + VBUF)   // 54272

__global__ void __launch_bounds__(128, 2) attn_k()
{
    extern __shared__ __align__(16) char smraw[];
    uint32_t sb = smem_u32(smraw);
    uint32_t aQhi = sb;
    uint32_t aKhi = sb + OFF_K;
    uint32_t aVhi = sb + OFF_V;

    int pairi = blockIdx.x;               // 0..15
    int h = blockIdx.y;
    int tid = threadIdx.x, wid = tid >> 5, lane = tid & 31;
    int m0 = wid * 32;                    // warp's 32 query rows (2 m-tiles)
    int rq = lane >> 2, cq = (lane & 3) * 2;

    const __half* khg0 = g_khi + (size_t)h * S_LEN * HEAD_DIM;
    const __half* vhg0 = g_vhi + (size_t)h * HEAD_DIM * S_LEN;

    for (int ti = 0; ti < 2; ti++) {
        int qb = (ti == 0) ? (31 - pairi) : pairi;  // big tile first

        __syncthreads();  // prev tile's Q reads done before overwrite
        // load Q tile (cp.async, once per tile)
        {
            const __half* qhg = g_qhi + ((size_t)h * S_LEN + qb * 128) * HEAD_DIM;
#pragma unroll
            for (int it = 0; it < 8; it++) {
                int idx4 = tid + it * 128;
                int row = idx4 >> 3, col = (idx4 & 7) << 3;
                uint32_t off = (uint32_t)(row * LDQK + col) * 2u;
                cpa16(aQhi + off, qhg + (size_t)row * HEAD_DIM + col);
            }
            cpa_commit();
        }

        float m[2][2], l[2][2], o[2][8][4];
#pragma unroll
        for (int mt = 0; mt < 2; mt++) {
            m[mt][0] = m[mt][1] = -1e30f;
            l[mt][0] = l[mt][1] = 0.f;
#pragma unroll
            for (int dt = 0; dt < 8; dt++)
#pragma unroll
                for (int e = 0; e < 4; e++) o[mt][dt][e] = 0.f;
        }

        for (int kb = 0; kb <= qb; kb++) {
            __syncthreads();
            // ---- load K/V tile (single stage)
            {
                const __half* khg = khg0 + (size_t)(kb * 128) * HEAD_DIM;
                const __half* vhg = vhg0 + kb * 128;
#pragma unroll
                for (int it = 0; it < 8; it++) {
                    int idx4 = tid + it * 128;
                    int row = idx4 >> 3, col = (idx4 & 7) << 3;
                    uint32_t koff = (uint32_t)(row * LDQK + col) * 2u;
                    cpa16(aKhi + koff, khg + (size_t)row * HEAD_DIM + col);
                    int vrow = idx4 >> 4, vcol = (idx4 & 15) << 3;
                    uint32_t voff = (uint32_t)(vrow * LDV + vcol) * 2u;
                    cpa16(aVhi + voff, vhg + (size_t)vrow * S_LEN + vcol);
                }
                cpa_commit();
                cpa_wait<0>();
            }
            __syncthreads();

            // ---- two 64-column halves
#pragma unroll
            for (int half = 0; half < 2; half++) {
                int nb = half * 64;

                float sc[2][8][4];
#pragma unroll
                for (int mt = 0; mt < 2; mt++)
#pragma unroll
                    for (int nt = 0; nt < 8; nt++)
#pragma unroll
                        for (int e = 0; e < 4; e++) sc[mt][nt][e] = 0.f;

#pragma unroll
                for (int ks = 0; ks < 4; ks++) {
                    int k0 = ks * 16;
                    uint32_t ah[2][4];
                    ldsm_x4(ah[0], addrA(aQhi, m0, k0, lane, LDQK));
                    ldsm_x4(ah[1], addrA(aQhi, m0 + 16, k0, lane, LDQK));
#pragma unroll
                    for (int pg = 0; pg < 2; pg++) {
                        int p0 = nb + pg * 32;
                        uint32_t bh0[4], bh1[4];
                        ldsm_x4(bh0, addrB4(aKhi, p0, k0, lane, LDQK));
                        ldsm_x4(bh1, addrB4(aKhi, p0 + 16, k0, lane, LDQK));
#pragma unroll
                        for (int mt = 0; mt < 2; mt++) {
                            mma_f16(sc[mt][4 * pg + 0], ah[mt], bh0);
                            mma_f16(sc[mt][4 * pg + 1], ah[mt], bh0 + 2);
                            mma_f16(sc[mt][4 * pg + 2], ah[mt], bh1);
                            mma_f16(sc[mt][4 * pg + 3], ah[mt], bh1 + 2);
                        }
                    }
                }

                // ---- causal mask on diagonal tile
                if (kb == qb) {
#pragma unroll
                    for (int mt = 0; mt < 2; mt++)
#pragma unroll
                        for (int nt = 0; nt < 8; nt++)
#pragma unroll
                            for (int e = 0; e < 4; e++) {
                                int qi = m0 + mt * 16 + rq + ((e >> 1) << 3);
                                int kj = nb + nt * 8 + cq + (e & 1);
                                if (kj > qi) sc[mt][nt][e] = -1e30f;
                            }
                }

                // ---- online softmax (log2 domain, ex2)
#pragma unroll
                for (int mt = 0; mt < 2; mt++)
#pragma unroll
                    for (int r = 0; r < 2; r++) {
                        float mx = -1e30f;
#pragma unroll
                        for (int nt = 0; nt < 8; nt++)
                            mx = fmaxf(mx, fmaxf(sc[mt][nt][2 * r],
                                                 sc[mt][nt][2 * r + 1]));
                        mx = fmaxf(mx, __shfl_xor_sync(0xffffffffu, mx, 1));
                        mx = fmaxf(mx, __shfl_xor_sync(0xffffffffu, mx, 2));
                        float mn = fmaxf(m[mt][r], mx);
                        float corr = ex2f(m[mt][r] - mn);
                        m[mt][r] = mn;
                        float rs = 0.f;
#pragma unroll
                        for (int nt = 0; nt < 8; nt++) {
                            float p0 = ex2f(sc[mt][nt][2 * r] - mn);
                            float p1 = ex2f(sc[mt][nt][2 * r + 1] - mn);
                            sc[mt][nt][2 * r] = p0;
                            sc[mt][nt][2 * r + 1] = p1;
                            rs += p0 + p1;
                        }
                        l[mt][r] = l[mt][r] * corr + rs;
#pragma unroll
                        for (int dt = 0; dt < 8; dt++) {
                            o[mt][dt][2 * r] *= corr;
                            o[mt][dt][2 * r + 1] *= corr;
                        }
                    }

                // ---- PV: single-fp16 P x single-fp16 V
#pragma unroll
                for (int kp = 0; kp < 4; kp++) {
                    uint32_t pa[2][4];
#pragma unroll
                    for (int mt = 0; mt < 2; mt++) {
                        pa[mt][0] = pk_h2(sc[mt][2 * kp][0], sc[mt][2 * kp][1]);
                        pa[mt][1] = pk_h2(sc[mt][2 * kp][2], sc[mt][2 * kp][3]);
                        pa[mt][2] = pk_h2(sc[mt][2 * kp + 1][0], sc[mt][2 * kp + 1][1]);
                        pa[mt][3] = pk_h2(sc[mt][2 * kp + 1][2], sc[mt][2 * kp + 1][3]);
                    }
                    int k0 = nb + kp * 16;
#pragma unroll
                    for (int pg = 0; pg < 2; pg++) {
                        int p0 = pg * 32;
                        uint32_t vh0[4], vh1[4];
                        ldsm_x4(vh0, addrB4(aVhi, p0, k0, lane, LDV));
                        ldsm_x4(vh1, addrB4(aVhi, p0 + 16, k0, lane, LDV));
#pragma unroll
                        for (int mt = 0; mt < 2; mt++) {
                            mma_f16(o[mt][4 * pg + 0], pa[mt], vh0);
                            mma_f16(o[mt][4 * pg + 1], pa[mt], vh0 + 2);
                            mma_f16(o[mt][4 * pg + 2], pa[mt], vh1);
                            mma_f16(o[mt][4 * pg + 3], pa[mt], vh1 + 2);
                        }
                    }
                }
            }
        }

        // ---- finalize this q-tile
#pragma unroll
        for (int mt = 0; mt < 2; mt++) {
#pragma unroll
            for (int r = 0; r < 2; r++) {
                l[mt][r] += __shfl_xor_sync(0xffffffffu, l[mt][r], 1);
                l[mt][r] += __shfl_xor_sync(0xffffffffu, l[mt][r], 2);
            }
            float inv0 = 1.f / l[mt][0], inv1 = 1.f / l[mt][1];
            int r0 = qb * 128 + m0 + mt * 16 + rq;
            size_t ob = (size_t)r0 * D_MODEL + h * HEAD_DIM + cq;
#pragma unroll
            for (int dt = 0; dt < 8; dt++) {
                uint32_t hh, ll;
                split2h(o[mt][dt][0] * inv0, o[mt][dt][1] * inv0, hh, ll);
                *(uint32_t*)(g_ahi + ob + dt * 8) = hh;
                *(uint32_t*)(g_alo + ob + dt * 8) = ll;
                split2h(o[mt][dt][2] * inv1, o[mt][dt][3] * inv1, hh, ll);
                *(uint32_t*)(g_ahi + ob + 8 * D_MODEL + dt * 8) = hh;
                *(uint32_t*)(g_alo + ob + 8 * D_MODEL + dt * 8) = ll;
            }
        }
    }
}

extern "C" void kernel_launch(void* const* d_in, const int* in_sizes, int n_in,
                              void* d_out, int out_size)
{
    const float* x    = (const float*)d_in[0];
    const float* fcos = (const float*)d_in[2];
    const float* fsin = (const float*)d_in[3];
    const float* wq  = (const float*)d_in[5];
    const float* wqb = (const float*)d_in[6];
    const float* wk  = (const float*)d_in[7];
    const float* wkb = (const float*)d_in[8];
    const float* wv  = (const float*)d_in[9];
    const float* wvb = (const float*)d_in[10];
    const float* wo  = (const float*)d_in[11];
    const float* wob = (const float*)d_in[12];
    float* out = (float*)d_out;

    static bool attr_set = false;
    if (!attr_set) {
        cudaFuncSetAttribute(attn_k,
                             cudaFuncAttributeMaxDynamicSharedMemorySize,
                             ATTN_SMEM);
        cudaFuncSetAttribute(gemm_qkv,
                             cudaFuncAttributeMaxDynamicSharedMemorySize,
                             GEMM_SMEM);
        cudaFuncSetAttribute(gemm_o,
                             cudaFuncAttributeMaxDynamicSharedMemorySize,
                             GEMM_SMEM);
        attr_set = true;
    }

    conv_all<<<(NX + 4 * NW) / 256, 256>>>(x, wq, wk, wv, wo);
    gemm_qkv<<<dim3(D_MODEL / 128, S_LEN / 128, 3), 256, GEMM_SMEM>>>(
        wqb, wkb, wvb, fcos, fsin);
    attn_k<<<dim3(16, N_HEADS), 128, ATTN_SMEM>>>();
    gemm_o<<<dim3(D_MODEL / 128, S_LEN / 128), 256, GEMM_SMEM>>>(wob, out);
}

// round 17
// speedup vs baseline: 2.5398x; 1.3257x over previous
#include <cuda_runtime.h>
#include <cuda_fp16.h>
#include <cstdint>

#define S_LEN 4096
#define D_MODEL 1024
#define N_HEADS 16
#define HEAD_DIM 64
#define HALF_DIM 32

// ---------------- fp16 scratch (device globals) ----------------------------
__device__ __align__(16) __half g_xhi[S_LEN * D_MODEL];
__device__ __align__(16) __half g_whi[4][D_MODEL * D_MODEL];
__device__ __align__(16) __half g_qhi[N_HEADS * S_LEN * HEAD_DIM]; // RoPE'd, *log2e/8
__device__ __align__(16) __half g_khi[N_HEADS * S_LEN * HEAD_DIM]; // RoPE'd
__device__ __align__(16) __half g_vhi[N_HEADS * HEAD_DIM * S_LEN]; // [h][d][s]
__device__ __align__(16) __half g_ahi[S_LEN * D_MODEL];            // attn out

// ---------------- helpers ---------------------------------------------------
__device__ __forceinline__ uint32_t smem_u32(const void* p) {
    uint32_t a;
    asm("{ .reg .u64 t; cvta.to.shared.u64 t, %1; cvt.u32.u64 %0, t; }"
        : "=r"(a) : "l"(p));
    return a;
}

__device__ __forceinline__ void cpa16(uint32_t dst, const void* src) {
    asm volatile("cp.async.cg.shared.global [%0], [%1], 16;"
                 :: "r"(dst), "l"(src));
}
__device__ __forceinline__ void cpa_commit() {
    asm volatile("cp.async.commit_group;");
}
template <int N>
__device__ __forceinline__ void cpa_wait() {
    asm volatile("cp.async.wait_group %0;" :: "n"(N));
}

__device__ __forceinline__ void ldsm_x4(uint32_t* r, uint32_t addr) {
    asm volatile("ldmatrix.sync.aligned.m8n8.x4.shared.b16 {%0,%1,%2,%3}, [%4];"
                 : "=r"(r[0]), "=r"(r[1]), "=r"(r[2]), "=r"(r[3]) : "r"(addr));
}

__device__ __forceinline__ void mma_f16(float* c, const uint32_t* a,
                                        const uint32_t* b) {
    asm volatile(
        "mma.sync.aligned.m16n8k16.row.col.f32.f16.f16.f32 "
        "{%0,%1,%2,%3}, {%4,%5,%6,%7}, {%8,%9}, {%0,%1,%2,%3};"
        : "+f"(c[0]), "+f"(c[1]), "+f"(c[2]), "+f"(c[3])
        : "r"(a[0]), "r"(a[1]), "r"(a[2]), "r"(a[3]), "r"(b[0]), "r"(b[1]));
}

__device__ __forceinline__ float ex2f(float x) {
    float y;
    asm("ex2.approx.f32 %0, %1;" : "=f"(y) : "f"(x));
    return y;
}

__device__ __forceinline__ uint32_t pk_h2(float a, float b) {
    __half2 t = __floats2half2_rn(a, b);
    return *reinterpret_cast<uint32_t*>(&t);
}

__device__ __forceinline__ uint32_t addrA(uint32_t base, int m0, int k0,
                                          int lane, int ld) {
    int r = m0 + (lane & 15);
    int c = k0 + ((lane >> 4) << 3);
    return base + (uint32_t)(r * ld + c) * 2u;
}
__device__ __forceinline__ uint32_t addrB4(uint32_t base, int n0, int k0,
                                           int lane, int ld) {
    int g = lane >> 3;
    int r = n0 + ((g >> 1) << 3) + (lane & 7);
    int c = k0 + ((g & 1) << 3);
    return base + (uint32_t)(r * ld + c) * 2u;
}

// ---------------- pre-pass: f32 -> fp16 (hi only, fused) --------------------
#define NX (S_LEN * D_MODEL / 4)
#define NW (D_MODEL * D_MODEL / 4)

__global__ void __launch_bounds__(256) conv_all(
    const float* __restrict__ x, const float* __restrict__ wq,
    const float* __restrict__ wk, const float* __restrict__ wv,
    const float* __restrict__ wo)
{
    int idx = blockIdx.x * 256 + threadIdx.x;
    const float* src;
    __half* dst;
    int off;
    if (idx < NX) {
        src = x; dst = g_xhi; off = idx;
    } else {
        int j = idx - NX;
        int t = j >> 18;
        off = j & (NW - 1);
        src = (t == 0) ? wq : (t == 1) ? wk : (t == 2) ? wv : wo;
        dst = g_whi[t];
    }
    float4 f = ((const float4*)src)[off];
    ((uint2*)dst)[off] = make_uint2(pk_h2(f.x, f.y), pk_h2(f.z, f.w));
}

// ------------------- tensor-core GEMM (pure fp16, 1 term) ------------------
#define LDT 40
#define GEMM_BUF (128 * LDT * 2)
#define GEMM_STAGE (2 * GEMM_BUF)
#define GEMM_SMEM (2 * GEMM_STAGE)   // 40 KB -> 2 CTAs/SM

__device__ __forceinline__ void gemm_issue(
    uint32_t sb, uint32_t soff, const __half* pA, const __half* pB, int c)
{
    int go = c * 32;
    cpa16(sb + soff,                     pA + go);
    cpa16(sb + soff + 16,                pA + go + 8);
    cpa16(sb + GEMM_BUF + soff,          pB + go);
    cpa16(sb + GEMM_BUF + soff + 16,     pB + go + 8);
    cpa_commit();
}

__device__ __forceinline__ void gemm_core(
    uint32_t sb0, uint32_t soff,
    const __half* pA, const __half* pB,
    int m0, int n0, int lane, float acc[4][4][4])
{
    gemm_issue(sb0, soff, pA, pB, 0);
    gemm_issue(sb0 + GEMM_STAGE, soff, pA, pB, 1);

    for (int c = 0; c < 32; c++) {
        if (c < 31) cpa_wait<1>(); else cpa_wait<0>();
        __syncthreads();
        uint32_t sb = sb0 + (c & 1) * GEMM_STAGE;
        uint32_t aA = sb, aB = sb + GEMM_BUF;
#pragma unroll
        for (int ks = 0; ks < 2; ks++) {
            int k0 = ks * 16;
            uint32_t bh[2][4];
#pragma unroll
            for (int p = 0; p < 2; p++)
                ldsm_x4(bh[p], addrB4(aB, n0 + p * 16, k0, lane, LDT));
#pragma unroll
            for (int mt = 0; mt < 4; mt++) {
                uint32_t ah[4];
                ldsm_x4(ah, addrA(aA, m0 + mt * 16, k0, lane, LDT));
#pragma unroll
                for (int nt = 0; nt < 4; nt++)
                    mma_f16(acc[mt][nt], ah, &bh[nt >> 1][(nt & 1) * 2]);
            }
        }
        __syncthreads();
        if (c + 2 < 32)
            gemm_issue(sb0 + (c & 1) * GEMM_STAGE, soff, pA, pB, c + 2);
    }
}

// QKV fused: blockIdx.z = mode (0=Q,1=K,2=V)
__global__ void __launch_bounds__(256, 2) gemm_qkv(
    const float* __restrict__ bq, const float* __restrict__ bk,
    const float* __restrict__ bv, const float* __restrict__ fcos,
    const float* __restrict__ fsin)
{
    extern __shared__ __align__(16) char dsm[];
    uint32_t sb0 = smem_u32(dsm);

    int mode = blockIdx.z;
    const float* bias = (mode == 0) ? bq : (mode == 1) ? bk : bv;

    int tid = threadIdx.x, wid = tid >> 5, lane = tid & 31;
    int m0 = (wid >> 2) * 64, n0 = (wid & 3) * 32;
    int bm = blockIdx.y * 128, bn = blockIdx.x * 128;

    int lrow = tid >> 1, lks = (tid & 1) * 16;
    uint32_t soff = (uint32_t)(lrow * LDT + lks) * 2u;
    const __half* pA = g_xhi + (size_t)(bm + lrow) * D_MODEL + lks;
    const __half* pB = g_whi[mode] + (size_t)(bn + lrow) * D_MODEL + lks;

    float acc[4][4][4];
#pragma unroll
    for (int i = 0; i < 4; i++)
#pragma unroll
        for (int j = 0; j < 4; j++)
#pragma unroll
            for (int e = 0; e < 4; e++) acc[i][j][e] = 0.f;

    gemm_core(sb0, soff, pA, pB, m0, n0, lane, acc);

    int rq = lane >> 2, cq = (lane & 3) * 2;
    // Q pre-scale folds softmax 1/sqrt(64) AND log2(e) for ex2-based softmax
    float scale = (mode == 0) ? (0.125f * 1.4426950408889634f) : 1.f;
#pragma unroll
    for (int mt = 0; mt < 4; mt++) {
#pragma unroll
        for (int nt = 0; nt < 4; nt++) {
            int r0 = bm + m0 + mt * 16 + rq;
            int cg = bn + n0 + nt * 8 + cq;
            float b0 = bias[cg], b1 = bias[cg + 1];
            float v00 = acc[mt][nt][0] + b0, v01 = acc[mt][nt][1] + b1;
            float v10 = acc[mt][nt][2] + b0, v11 = acc[mt][nt][3] + b1;
            int h = cg >> 6, d = cg & 63;
            if (mode == 2) {
                // V: [h][d][s]
                size_t o0 = ((size_t)h * HEAD_DIM + d) * S_LEN;
                g_vhi[o0 + r0]             = __float2half_rn(v00);
                g_vhi[o0 + r0 + 8]         = __float2half_rn(v10);
                g_vhi[o0 + S_LEN + r0]     = __float2half_rn(v01);
                g_vhi[o0 + S_LEN + r0 + 8] = __float2half_rn(v11);
            } else {
                float c0 = fcos[(size_t)r0 * HALF_DIM + (d >> 1)];
                float s0 = fsin[(size_t)r0 * HALF_DIM + (d >> 1)];
                float c1 = fcos[(size_t)(r0 + 8) * HALF_DIM + (d >> 1)];
                float s1 = fsin[(size_t)(r0 + 8) * HALF_DIM + (d >> 1)];
                float q00 = (v00 * c0 - v01 * s0) * scale;
                float q01 = (v00 * s0 + v01 * c0) * scale;
                float q10 = (v10 * c1 - v11 * s1) * scale;
                float q11 = (v10 * s1 + v11 * c1) * scale;
                size_t o0 = ((size_t)h * S_LEN + r0) * HEAD_DIM + d;
                __half* dst = (mode == 0) ? g_qhi : g_khi;
                *(uint32_t*)(dst + o0) = pk_h2(q00, q01);
                *(uint32_t*)(dst + o0 + 8 * HEAD_DIM) = pk_h2(q10, q11);
            }
        }
    }
}

__global__ void __launch_bounds__(256, 2) gemm_o(
    const float* __restrict__ bias, float* __restrict__ oout)
{
    extern __shared__ __align__(16) char dsm[];
    uint32_t sb0 = smem_u32(dsm);

    int tid = threadIdx.x, wid = tid >> 5, lane = tid & 31;
    int m0 = (wid >> 2) * 64, n0 = (wid & 3) * 32;
    int bm = blockIdx.y * 128, bn = blockIdx.x * 128;

    int lrow = tid >> 1, lks = (tid & 1) * 16;
    uint32_t soff = (uint32_t)(lrow * LDT + lks) * 2u;
    const __half* pA = g_ahi + (size_t)(bm + lrow) * D_MODEL + lks;
    const __half* pB = g_whi[3] + (size_t)(bn + lrow) * D_MODEL + lks;

    float acc[4][4][4];
#pragma unroll
    for (int i = 0; i < 4; i++)
#pragma unroll
        for (int j = 0; j < 4; j++)
#pragma unroll
            for (int e = 0; e < 4; e++) acc[i][j][e] = 0.f;

    gemm_core(sb0, soff, pA, pB, m0, n0, lane, acc);

    int rq = lane >> 2, cq = (lane & 3) * 2;
#pragma unroll
    for (int mt = 0; mt < 4; mt++) {
#pragma unroll
        for (int nt = 0; nt < 4; nt++) {
            int r0 = bm + m0 + mt * 16 + rq;
            int cg = bn + n0 + nt * 8 + cq;
            float b0 = bias[cg], b1 = bias[cg + 1];
            *(float2*)(oout + (size_t)r0 * D_MODEL + cg) =
                make_float2(acc[mt][nt][0] + b0, acc[mt][nt][1] + b1);
            *(float2*)(oout + (size_t)(r0 + 8) * D_MODEL + cg) =
                make_float2(acc[mt][nt][2] + b0, acc[mt][nt][3] + b1);
        }
    }
}

// ------ flash attention: paired tiles, Q/K/V all single fp16 ---------------
#define LDQK 72
#define LDV 136
#define QBUF (128 * LDQK * 2)
#define VBUF (64 * LDV * 2)
#define OFF_K (QBUF)
#define OFF_V (2 * QBUF)
#define ATTN_SMEM (2 * QBUF + VBUF)   // 54272

__global__ void __launch_bounds__(128, 2) attn_k()
{
    extern __shared__ __align__(16) char smraw[];
    uint32_t sb = smem_u32(smraw);
    uint32_t aQhi = sb;
    uint32_t aKhi = sb + OFF_K;
    uint32_t aVhi = sb + OFF_V;

    int pairi = blockIdx.x;               // 0..15
    int h = blockIdx.y;
    int tid = threadIdx.x, wid = tid >> 5, lane = tid & 31;
    int m0 = wid * 32;                    // warp's 32 query rows (2 m-tiles)
    int rq = lane >> 2, cq = (lane & 3) * 2;

    const __half* khg0 = g_khi + (size_t)h * S_LEN * HEAD_DIM;
    const __half* vhg0 = g_vhi + (size_t)h * HEAD_DIM * S_LEN;

    for (int ti = 0; ti < 2; ti++) {
        int qb = (ti == 0) ? (31 - pairi) : pairi;  // big tile first

        __syncthreads();
        // load Q tile (cp.async, once per tile)
        {
            const __half* qhg = g_qhi + ((size_t)h * S_LEN + qb * 128) * HEAD_DIM;
#pragma unroll
            for (int it = 0; it < 8; it++) {
                int idx4 = tid + it * 128;
                int row = idx4 >> 3, col = (idx4 & 7) << 3;
                uint32_t off = (uint32_t)(row * LDQK + col) * 2u;
                cpa16(aQhi + off, qhg + (size_t)row * HEAD_DIM + col);
            }
            cpa_commit();
        }

        float m[2][2], l[2][2], o[2][8][4];
#pragma unroll
        for (int mt = 0; mt < 2; mt++) {
            m[mt][0] = m[mt][1] = -1e30f;
            l[mt][0] = l[mt][1] = 0.f;
#pragma unroll
            for (int dt = 0; dt < 8; dt++)
#pragma unroll
                for (int e = 0; e < 4; e++) o[mt][dt][e] = 0.f;
        }

        for (int kb = 0; kb <= qb; kb++) {
            __syncthreads();
            // ---- load K/V tile (single stage)
            {
                const __half* khg = khg0 + (size_t)(kb * 128) * HEAD_DIM;
                const __half* vhg = vhg0 + kb * 128;
#pragma unroll
                for (int it = 0; it < 8; it++) {
                    int idx4 = tid + it * 128;
                    int row = idx4 >> 3, col = (idx4 & 7) << 3;
                    uint32_t koff = (uint32_t)(row * LDQK + col) * 2u;
                    cpa16(aKhi + koff, khg + (size_t)row * HEAD_DIM + col);
                    int vrow = idx4 >> 4, vcol = (idx4 & 15) << 3;
                    uint32_t voff = (uint32_t)(vrow * LDV + vcol) * 2u;
                    cpa16(aVhi + voff, vhg + (size_t)vrow * S_LEN + vcol);
                }
                cpa_commit();
                cpa_wait<0>();
            }
            __syncthreads();

            // ---- two 64-column halves
#pragma unroll
            for (int half = 0; half < 2; half++) {
                int nb = half * 64;

                float sc[2][8][4];
#pragma unroll
                for (int mt = 0; mt < 2; mt++)
#pragma unroll
                    for (int nt = 0; nt < 8; nt++)
#pragma unroll
                        for (int e = 0; e < 4; e++) sc[mt][nt][e] = 0.f;

#pragma unroll
                for (int ks = 0; ks < 4; ks++) {
                    int k0 = ks * 16;
                    uint32_t ah[2][4];
                    ldsm_x4(ah[0], addrA(aQhi, m0, k0, lane, LDQK));
                    ldsm_x4(ah[1], addrA(aQhi, m0 + 16, k0, lane, LDQK));
#pragma unroll
                    for (int pg = 0; pg < 2; pg++) {
                        int p0 = nb + pg * 32;
                        uint32_t bh0[4], bh1[4];
                        ldsm_x4(bh0, addrB4(aKhi, p0, k0, lane, LDQK));
                        ldsm_x4(bh1, addrB4(aKhi, p0 + 16, k0, lane, LDQK));
#pragma unroll
                        for (int mt = 0; mt < 2; mt++) {
                            mma_f16(sc[mt][4 * pg + 0], ah[mt], bh0);
                            mma_f16(sc[mt][4 * pg + 1], ah[mt], bh0 + 2);
                            mma_f16(sc[mt][4 * pg + 2], ah[mt], bh1);
                            mma_f16(sc[mt][4 * pg + 3], ah[mt], bh1 + 2);
                        }
                    }
                }

                // ---- causal mask on diagonal tile
                if (kb == qb) {
#pragma unroll
                    for (int mt = 0; mt < 2; mt++)
#pragma unroll
                        for (int nt = 0; nt < 8; nt++)
#pragma unroll
                            for (int e = 0; e < 4; e++) {
                                int qi = m0 + mt * 16 + rq + ((e >> 1) << 3);
                                int kj = nb + nt * 8 + cq + (e & 1);
                                if (kj > qi) sc[mt][nt][e] = -1e30f;
                            }
                }

                // ---- online softmax (log2 domain, ex2)
#pragma unroll
                for (int mt = 0; mt < 2; mt++)
#pragma unroll
                    for (int r = 0; r < 2; r++) {
                        float mx = -1e30f;
#pragma unroll
                        for (int nt = 0; nt < 8; nt++)
                            mx = fmaxf(mx, fmaxf(sc[mt][nt][2 * r],
                                                 sc[mt][nt][2 * r + 1]));
                        mx = fmaxf(mx, __shfl_xor_sync(0xffffffffu, mx, 1));
                        mx = fmaxf(mx, __shfl_xor_sync(0xffffffffu, mx, 2));
                        float mn = fmaxf(m[mt][r], mx);
                        float corr = ex2f(m[mt][r] - mn);
                        m[mt][r] = mn;
                        float rs = 0.f;
#pragma unroll
                        for (int nt = 0; nt < 8; nt++) {
                            float p0 = ex2f(sc[mt][nt][2 * r] - mn);
                            float p1 = ex2f(sc[mt][nt][2 * r + 1] - mn);
                            sc[mt][nt][2 * r] = p0;
                            sc[mt][nt][2 * r + 1] = p1;
                            rs += p0 + p1;
                        }
                        l[mt][r] = l[mt][r] * corr + rs;
#pragma unroll
                        for (int dt = 0; dt < 8; dt++) {
                            o[mt][dt][2 * r] *= corr;
                            o[mt][dt][2 * r + 1] *= corr;
                        }
                    }

                // ---- PV: single-fp16 P x single-fp16 V
#pragma unroll
                for (int kp = 0; kp < 4; kp++) {
                    uint32_t pa[2][4];
#pragma unroll
                    for (int mt = 0; mt < 2; mt++) {
                        pa[mt][0] = pk_h2(sc[mt][2 * kp][0], sc[mt][2 * kp][1]);
                        pa[mt][1] = pk_h2(sc[mt][2 * kp][2], sc[mt][2 * kp][3]);
                        pa[mt][2] = pk_h2(sc[mt][2 * kp + 1][0], sc[mt][2 * kp + 1][1]);
                        pa[mt][3] = pk_h2(sc[mt][2 * kp + 1][2], sc[mt][2 * kp + 1][3]);
                    }
                    int k0 = nb + kp * 16;
#pragma unroll
                    for (int pg = 0; pg < 2; pg++) {
                        int p0 = pg * 32;
                        uint32_t vh0[4], vh1[4];
                        ldsm_x4(vh0, addrB4(aVhi, p0, k0, lane, LDV));
                        ldsm_x4(vh1, addrB4(aVhi, p0 + 16, k0, lane, LDV));
#pragma unroll
                        for (int mt = 0; mt < 2; mt++) {
                            mma_f16(o[mt][4 * pg + 0], pa[mt], vh0);
                            mma_f16(o[mt][4 * pg + 1], pa[mt], vh0 + 2);
                            mma_f16(o[mt][4 * pg + 2], pa[mt], vh1);
                            mma_f16(o[mt][4 * pg + 3], pa[mt], vh1 + 2);
                        }
                    }
                }
            }
        }

        // ---- finalize this q-tile (single fp16 out)
#pragma unroll
        for (int mt = 0; mt < 2; mt++) {
#pragma unroll
            for (int r = 0; r < 2; r++) {
                l[mt][r] += __shfl_xor_sync(0xffffffffu, l[mt][r], 1);
                l[mt][r] += __shfl_xor_sync(0xffffffffu, l[mt][r], 2);
            }
            float inv0 = 1.f / l[mt][0], inv1 = 1.f / l[mt][1];
            int r0 = qb * 128 + m0 + mt * 16 + rq;
            size_t ob = (size_t)r0 * D_MODEL + h * HEAD_DIM + cq;
#pragma unroll
            for (int dt = 0; dt < 8; dt++) {
                *(uint32_t*)(g_ahi + ob + dt * 8) =
                    pk_h2(o[mt][dt][0] * inv0, o[mt][dt][1] * inv0);
                *(uint32_t*)(g_ahi + ob + 8 * D_MODEL + dt * 8) =
                    pk_h2(o[mt][dt][2] * inv1, o[mt][dt][3] * inv1);
            }
        }
    }
}

extern "C" void kernel_launch(void* const* d_in, const int* in_sizes, int n_in,
                              void* d_out, int out_size)
{
    const float* x    = (const float*)d_in[0];
    const float* fcos = (const float*)d_in[2];
    const float* fsin = (const float*)d_in[3];
    const float* wq  = (const float*)d_in[5];
    const float* wqb = (const float*)d_in[6];
    const float* wk  = (const float*)d_in[7];
    const float* wkb = (const float*)d_in[8];
    const float* wv  = (const float*)d_in[9];
    const float* wvb = (const float*)d_in[10];
    const float* wo  = (const float*)d_in[11];
    const float* wob = (const float*)d_in[12];
    float* out = (float*)d_out;

    static bool attr_set = false;
    if (!attr_set) {
        cudaFuncSetAttribute(attn_k,
                             cudaFuncAttributeMaxDynamicSharedMemorySize,
                             ATTN_SMEM);
        cudaFuncSetAttribute(gemm_qkv,
                             cudaFuncAttributeMaxDynamicSharedMemorySize,
                             GEMM_SMEM);
        cudaFuncSetAttribute(gemm_o,
                             cudaFuncAttributeMaxDynamicSharedMemorySize,
                             GEMM_SMEM);
        attr_set = true;
    }

    conv_all<<<(NX + 4 * NW) / 256, 256>>>(x, wq, wk, wv, wo);
    gemm_qkv<<<dim3(D_MODEL / 128, S_LEN / 128, 3), 256, GEMM_SMEM>>>(
        wqb, wkb, wvb, fcos, fsin);
    attn_k<<<dim3(16, N_HEADS), 128, ATTN_SMEM>>>();
    gemm_o<<<dim3(D_MODEL / 128, S_LEN / 128), 256, GEMM_SMEM>>>(wob, out);
}